// round 6
// baseline (speedup 1.0000x reference)
#include <cuda_runtime.h>
#include <cuda_fp16.h>
#include <math.h>
#include <stdint.h>

// Problem constants
#define Bq 4
#define Tq 2048
#define Cq 2048
#define Hq 32
#define HSq 64
#define Mq (Bq*Tq)            // 8192 tokens
#define DW 128
#define DA 128
#define DG 224
#define DV 64
#define EPS_GN 0.00064f

// ---------------------------------------------------------------------------
// Scratch (static device globals; zero-initialized at module load)
// ---------------------------------------------------------------------------
#define BTC ((size_t)Mq*Cq)
__device__ __half h_xr[BTC];
__device__ __half h_xw[BTC];
__device__ __half h_xk[BTC];
__device__ __half h_xv[BTC];
__device__ __half h_xa[BTC];
__device__ __half h_xg[BTC];
__device__ __half h_z [BTC];
__device__ __half h_Wr[(size_t)Cq*Cq];
__device__ __half h_Wk[(size_t)Cq*Cq];
__device__ __half h_Wv[(size_t)Cq*Cq];
__device__ __half h_Wo[(size_t)Cq*Cq];
__device__ __half h_w1[(size_t)128*Cq];   // [DW pad128][C]
__device__ __half h_w2[(size_t)Cq*DW];    // [C][DW]
__device__ __half h_a1[(size_t)128*Cq];
__device__ __half h_a2[(size_t)Cq*DA];
__device__ __half h_v1[(size_t)128*Cq];   // [DV pad128][C]
__device__ __half h_v2[(size_t)Cq*DV];
__device__ __half h_g1[(size_t)256*Cq];   // [DG pad256][C]
__device__ __half h_g2[(size_t)Cq*DG];
__device__ __half h_tw[(size_t)Mq*DW];
__device__ __half h_ta[(size_t)Mq*DA];
__device__ __half h_tv[(size_t)Mq*DV];
__device__ __half h_tg[(size_t)Mq*DG];
// fp32 intermediates
__device__ float g_r [BTC];
__device__ float g_k [BTC];
__device__ float g_v [BTC];
__device__ float g_dec[BTC];
__device__ float g_a [BTC];
__device__ float g_g [BTC];
__device__ float g_kk[BTC];
__device__ float g_y [BTC];

__device__ __forceinline__ float sigmoidf_(float x){ return 1.0f/(1.0f+expf(-x)); }

__device__ __forceinline__ void cpa16(uint32_t s, const void* g){
    asm volatile("cp.async.cg.shared.global [%0], [%1], 16;\n" :: "r"(s), "l"(g));
}
__device__ __forceinline__ void ldsm_x4(uint32_t* r, uint32_t addr){
    asm volatile("ldmatrix.sync.aligned.m8n8.x4.shared.b16 {%0,%1,%2,%3}, [%4];"
        : "=r"(r[0]),"=r"(r[1]),"=r"(r[2]),"=r"(r[3]) : "r"(addr));
}
__device__ __forceinline__ void mma16(float* c, const uint32_t* a, const uint32_t* b){
    asm volatile("mma.sync.aligned.m16n8k16.row.col.f32.f16.f16.f32 "
        "{%0,%1,%2,%3},{%4,%5,%6,%7},{%8,%9},{%0,%1,%2,%3};\n"
        : "+f"(c[0]),"+f"(c[1]),"+f"(c[2]),"+f"(c[3])
        : "r"(a[0]),"r"(a[1]),"r"(a[2]),"r"(a[3]),"r"(b[0]),"r"(b[1]));
}

// ---------------------------------------------------------------------------
// Prep: f32 -> f16 copy; transpose f32[R][C] -> f16[C][R]
// ---------------------------------------------------------------------------
__global__ void f2h_kernel(const float* __restrict__ in, __half* __restrict__ out, size_t n4)
{
    size_t i = (size_t)blockIdx.x*blockDim.x + threadIdx.x;
    if (i >= n4) return;
    float4 v = ((const float4*)in)[i];
    ((__half2*)out)[i*2  ] = __floats2half2_rn(v.x, v.y);
    ((__half2*)out)[i*2+1] = __floats2half2_rn(v.z, v.w);
}

__global__ void transpose_h(const float* __restrict__ in, __half* __restrict__ out, int R, int C)
{
    __shared__ float tile[32][33];
    int cb = blockIdx.x*32, rb = blockIdx.y*32;
    int c = cb + threadIdx.x;
    #pragma unroll
    for (int i=threadIdx.y; i<32; i+=8){
        int r = rb + i;
        if (r<R && c<C) tile[i][threadIdx.x] = in[(size_t)r*C + c];
    }
    __syncthreads();
    int r2 = rb + threadIdx.x;
    #pragma unroll
    for (int i=threadIdx.y; i<32; i+=8){
        int c2 = cb + i;
        if (r2<R && c2<C) out[(size_t)c2*R + r2] = __float2half_rn(tile[threadIdx.x][i]);
    }
}

// ---------------------------------------------------------------------------
// Token-shift mix -> fp16 outputs
// ---------------------------------------------------------------------------
__global__ void mix_kernel(const float* __restrict__ x,
                           const float* __restrict__ cr, const float* __restrict__ cw,
                           const float* __restrict__ ck, const float* __restrict__ cv,
                           const float* __restrict__ ca, const float* __restrict__ cg,
                           __half* __restrict__ xr, __half* __restrict__ xw,
                           __half* __restrict__ xk, __half* __restrict__ xv,
                           __half* __restrict__ xa, __half* __restrict__ xg)
{
    size_t i4 = (size_t)blockIdx.x*blockDim.x + threadIdx.x;
    size_t n4 = BTC/4;
    if (i4 >= n4) return;
    size_t flat = i4*4;
    int tok = (int)(flat / Cq);
    int t   = tok % Tq;
    const float4* x4 = (const float4*)x;
    float4 xc = x4[i4];
    float4 xp = (t==0) ? make_float4(0,0,0,0) : x4[i4 - Cq/4];
    float4 dx = make_float4(xp.x-xc.x, xp.y-xc.y, xp.z-xc.z, xp.w-xc.w);
    size_t c4 = i4 % (Cq/4);
    #define MIX1(COEF, OUT) { \
        float4 cf = ((const float4*)COEF)[c4]; \
        ((__half2*)OUT)[i4*2  ] = __floats2half2_rn(xc.x + dx.x*cf.x, xc.y + dx.y*cf.y); \
        ((__half2*)OUT)[i4*2+1] = __floats2half2_rn(xc.z + dx.z*cf.z, xc.w + dx.w*cf.w); }
    MIX1(cr, xr) MIX1(cw, xw) MIX1(ck, xk) MIX1(cv, xv) MIX1(ca, xa) MIX1(cg, xg)
    #undef MIX1
}

// ---------------------------------------------------------------------------
// Epilogue transform: 0 none, 1 tanh, 2 sigmoid, 3 w->decay, 4 a-sigm, 5 v-mix
// ---------------------------------------------------------------------------
template<int EPI>
__device__ __forceinline__ float epi_val(float val, int m, int n, int Nd,
                                         const float* __restrict__ bias,
                                         const float* __restrict__ vold,
                                         const float* __restrict__ vfirst)
{
    if (EPI==1) { val = tanhf(val); }
    else if (EPI==2) { val = sigmoidf_(val); }
    else if (EPI==3) {
        float w = bias[n] + val;
        float mneg = -w;
        float sp = fmaxf(mneg,0.f) + log1pf(expf(-fabsf(mneg)));
        float wl = -sp - 0.5f;
        val = expf(-expf(wl));
    }
    else if (EPI==4) { val = sigmoidf_(bias[n] + val); }
    else if (EPI==5) {
        float s  = sigmoidf_(bias[n] + val);
        size_t idx = (size_t)m*Nd + n;
        float vo = vold[idx];
        val = vo + (vfirst[idx] - vo)*s;
    }
    return val;
}

// ---------------------------------------------------------------------------
// fp16 tensor-core GEMM body: C[m,n] = sum_k A[m,k] * B[n,k]
// CTA 128x128, BK=32, 4-stage cp.async, 8 warps (2Mx4N), warp 64x32.
// ---------------------------------------------------------------------------
#define GSTAGES 4
#define STAGE_HB 10240           // bytes: 128 rows * 40 halves * 2B
#define STAGE_BYTES (2*STAGE_HB)

template<int EPI,int RND>
__device__ __forceinline__
void gemm_body(const __half* __restrict__ A, const __half* __restrict__ Bw,
               void* __restrict__ Cm, int Nd, int Kd,
               const float* __restrict__ bias,
               const float* __restrict__ vold, const float* __restrict__ vfirst)
{
    extern __shared__ __align__(128) char smc[];
    const int tid = threadIdx.x;
    const int lane = tid&31, warp = tid>>5;
    const int bm = blockIdx.y*128, bn = blockIdx.x*128;
    const int wm = (warp&1)*64, wn = (warp>>1)*32;
    const int g = lane>>2, tig = lane&3;
    const uint32_t sbase = (uint32_t)__cvta_generic_to_shared(smc);

    const int arow = wm + (lane&7) + ((lane>>3)&1)*8;   // + mt*16
    const int akof = (lane>>4)*8;
    const int brow = wn + (lane&7) + (lane>>4)*8;       // + p*16
    const int bkof = ((lane>>3)&1)*8;

    float acc[4][4][4];
    #pragma unroll
    for (int i=0;i<4;i++)
        #pragma unroll
        for (int j=0;j<4;j++)
            #pragma unroll
            for (int q=0;q<4;q++) acc[i][j][q]=0.f;

    const int NS = Kd >> 5;

    auto loadSlab = [&](int s, int st){
        const uint32_t sb = sbase + st*STAGE_BYTES;
        const int k0 = s*32;
        #pragma unroll
        for (int i=0;i<2;i++){
            int id  = tid + i*256;
            int row = id>>2, c16 = id&3;
            cpa16(sb + row*80 + c16*16,
                  &A[(size_t)(bm+row)*Kd + k0 + c16*8]);
            cpa16(sb + STAGE_HB + row*80 + c16*16,
                  &Bw[(size_t)(bn+row)*Kd + k0 + c16*8]);
        }
    };
    auto compute = [&](int st){
        const uint32_t sb = sbase + st*STAGE_BYTES;
        #pragma unroll
        for (int ks=0; ks<2; ks++){
            uint32_t af[4][4], bf[2][4];
            #pragma unroll
            for (int mt=0;mt<4;mt++)
                ldsm_x4(af[mt], sb + ((arow+mt*16)*40 + akof + ks*16)*2);
            #pragma unroll
            for (int p=0;p<2;p++)
                ldsm_x4(bf[p], sb + STAGE_HB + ((brow+p*16)*40 + bkof + ks*16)*2);
            #pragma unroll
            for (int mt=0;mt<4;mt++)
                #pragma unroll
                for (int nt=0;nt<4;nt++)
                    mma16(acc[mt][nt], af[mt], &bf[nt>>1][(nt&1)*2]);
        }
    };

    #pragma unroll
    for (int i=0;i<GSTAGES-1;i++){
        if (i<NS) loadSlab(i,i);
        asm volatile("cp.async.commit_group;\n");
    }
    for (int s=0;s<NS;s++){
        int ld = s + GSTAGES-1;
        if (ld < NS) loadSlab(ld, ld&3);
        asm volatile("cp.async.commit_group;\n");
        asm volatile("cp.async.wait_group %0;\n" :: "n"(GSTAGES-1));
        __syncthreads();
        compute(s&3);
        __syncthreads();
    }

    #pragma unroll
    for (int mt=0;mt<4;mt++){
        int r0 = bm + wm + mt*16 + g;
        #pragma unroll
        for (int nt=0;nt<4;nt++){
            int n0 = bn + wn + nt*8 + tig*2;
            if (n0 < Nd){
                float* c = acc[mt][nt];
                float v00 = epi_val<EPI>(c[0], r0,   n0,   Nd, bias, vold, vfirst);
                float v01 = epi_val<EPI>(c[1], r0,   n0+1, Nd, bias, vold, vfirst);
                float v10 = epi_val<EPI>(c[2], r0+8, n0,   Nd, bias, vold, vfirst);
                float v11 = epi_val<EPI>(c[3], r0+8, n0+1, Nd, bias, vold, vfirst);
                if (RND){
                    __half* O = (__half*)Cm;
                    *(__half2*)&O[(size_t)r0*Nd + n0]     = __floats2half2_rn(v00, v01);
                    *(__half2*)&O[(size_t)(r0+8)*Nd + n0] = __floats2half2_rn(v10, v11);
                } else {
                    float* O = (float*)Cm;
                    *(float2*)&O[(size_t)r0*Nd + n0]     = make_float2(v00, v01);
                    *(float2*)&O[(size_t)(r0+8)*Nd + n0] = make_float2(v10, v11);
                }
            }
        }
    }
}

template<int EPI,int RND>
__global__ __launch_bounds__(256,2)
void gemm_h(const __half* __restrict__ A, const __half* __restrict__ Bw,
            void* __restrict__ Cm, int Nd, int Kd,
            const float* __restrict__ bias,
            const float* __restrict__ vold, const float* __restrict__ vfirst)
{
    gemm_body<EPI,RND>(A, Bw, Cm, Nd, Kd, bias, vold, vfirst);
}

// merged r/k/v projections: blockIdx.z selects which
__global__ __launch_bounds__(256,2)
void gemm_h3(const __half* __restrict__ A0, const __half* __restrict__ B0, float* __restrict__ C0,
             const __half* __restrict__ A1, const __half* __restrict__ B1, float* __restrict__ C1,
             const __half* __restrict__ A2, const __half* __restrict__ B2, float* __restrict__ C2)
{
    const __half* A = (blockIdx.z==0) ? A0 : (blockIdx.z==1) ? A1 : A2;
    const __half* B = (blockIdx.z==0) ? B0 : (blockIdx.z==1) ? B1 : B2;
    float*        C = (blockIdx.z==0) ? C0 : (blockIdx.z==1) ? C1 : C2;
    gemm_body<0,0>(A, B, (void*)C, Cq, Cq, nullptr, nullptr, nullptr);
}

// ---------------------------------------------------------------------------
// kk normalize + k transform
// ---------------------------------------------------------------------------
__global__ void kk_kernel(float* __restrict__ k, const float* __restrict__ a,
                          const float* __restrict__ k_k, const float* __restrict__ k_a,
                          float* __restrict__ kk)
{
    int gw   = blockIdx.x*8 + (threadIdx.x>>5);
    int lane = threadIdx.x & 31;
    int m = gw >> 5;
    int h = gw & 31;
    size_t base = (size_t)m*Cq + h*HSq;
    int c0 = h*HSq + lane, c1 = c0 + 32;
    float k0 = k[base+lane], k1 = k[base+lane+32];
    float kk0 = k0*k_k[c0], kk1 = k1*k_k[c1];
    float s = kk0*kk0 + kk1*kk1;
    #pragma unroll
    for (int off=16; off; off>>=1) s += __shfl_xor_sync(0xffffffffu, s, off);
    float inv = 1.0f / fmaxf(sqrtf(s), 1e-12f);
    kk[base+lane]    = kk0*inv;
    kk[base+lane+32] = kk1*inv;
    float a0 = a[base+lane], a1 = a[base+lane+32];
    k[base+lane]    = k0*(1.0f + (a0-1.0f)*k_a[c0]);
    k[base+lane+32] = k1*(1.0f + (a1-1.0f)*k_a[c1]);
}

// ---------------------------------------------------------------------------
// WKV7 scan: 256 threads per (b,h). Thread (i,p): row i (0..63), quarter p
// (16 state cols). All 4 SMSPs busy; shfl reductions over the 4-lane group;
// double-buffered shared staging -> ONE barrier per step.
// ---------------------------------------------------------------------------
__global__ __launch_bounds__(256)
void wkv_kernel(const float* __restrict__ r, const float* __restrict__ wd,
                const float* __restrict__ k, const float* __restrict__ v,
                const float* __restrict__ kkp, const float* __restrict__ ap,
                float* __restrict__ y)
{
    const int bh = blockIdx.x;
    const int b = bh >> 5;
    const int h = bh & 31;
    const int tid = threadIdx.x;
    const int i = tid >> 2;     // state row
    const int p = tid & 3;      // quarter (cols p*16 .. p*16+15)
    const int role = tid >> 6;  // loader role 0..3
    const int lc   = tid & 63;  // loader column

    // [buf][array][64]; arrays: 0=r 1=w 2=k 3=a(-kk) 4=b(kk*a) 5=v
    __shared__ __align__(16) float sbuf[2][6][64];

    float st[16];
    #pragma unroll
    for (int j=0;j<16;j++) st[j]=0.f;

    const size_t base = ((size_t)b*Tq)*Cq + (size_t)h*HSq;

    // preload step 0 into buffer 0
    {
        if (role==0){ sbuf[0][0][lc] = r[base+lc]; sbuf[0][5][lc] = v[base+lc]; }
        else if (role==1){ sbuf[0][1][lc] = wd[base+lc]; }
        else if (role==2){ sbuf[0][2][lc] = k[base+lc]; }
        else { float kkv = kkp[base+lc]; sbuf[0][3][lc] = -kkv; sbuf[0][4][lc] = kkv*ap[base+lc]; }
    }
    __syncthreads();

    size_t o = base;
    for (int t=0; t<Tq; t++){
        const int cur = t&1, nxt = cur^1;

        // loaders stage step t+1 into the other buffer (overlaps compute)
        if (t+1 < Tq){
            size_t on = o + Cq;
            if (role==0){ sbuf[nxt][0][lc] = r[on+lc]; sbuf[nxt][5][lc] = v[on+lc]; }
            else if (role==1){ sbuf[nxt][1][lc] = wd[on+lc]; }
            else if (role==2){ sbuf[nxt][2][lc] = k[on+lc]; }
            else { float kkv = kkp[on+lc]; sbuf[nxt][3][lc] = -kkv; sbuf[nxt][4][lc] = kkv*ap[on+lc]; }
        }

        // ---- compute on cur ----
        const float4* A4 = (const float4*)&sbuf[cur][3][p*16];
        float s0=0,s1=0,s2=0,s3=0;
        #pragma unroll
        for (int j=0;j<4;j++){
            float4 a4 = A4[j];
            s0 += st[4*j+0]*a4.x; s1 += st[4*j+1]*a4.y;
            s2 += st[4*j+2]*a4.z; s3 += st[4*j+3]*a4.w;
        }
        float sa = (s0+s1)+(s2+s3);
        sa += __shfl_xor_sync(0xffffffffu, sa, 1);
        sa += __shfl_xor_sync(0xffffffffu, sa, 2);

        const float vv = sbuf[cur][5][i];
        const float4* W4=(const float4*)&sbuf[cur][1][p*16];
        const float4* K4=(const float4*)&sbuf[cur][2][p*16];
        const float4* B4=(const float4*)&sbuf[cur][4][p*16];
        const float4* R4=(const float4*)&sbuf[cur][0][p*16];
        float o0=0,o1=0,o2=0,o3=0;
        #pragma unroll
        for (int j=0;j<4;j++){
            float4 w4=W4[j], k4=K4[j], b4=B4[j], r4=R4[j];
            float t0 = st[4*j+0]*w4.x + vv*k4.x + sa*b4.x;
            float t1 = st[4*j+1]*w4.y + vv*k4.y + sa*b4.y;
            float t2 = st[4*j+2]*w4.z + vv*k4.z + sa*b4.z;
            float t3 = st[4*j+3]*w4.w + vv*k4.w + sa*b4.w;
            st[4*j+0]=t0; st[4*j+1]=t1; st[4*j+2]=t2; st[4*j+3]=t3;
            o0 += t0*r4.x; o1 += t1*r4.y; o2 += t2*r4.z; o3 += t3*r4.w;
        }
        float op = (o0+o1)+(o2+o3);
        op += __shfl_xor_sync(0xffffffffu, op, 1);
        op += __shfl_xor_sync(0xffffffffu, op, 2);
        if (p==0) y[o+i] = op;

        o += Cq;
        __syncthreads();   // next buffer staged AND everyone done reading cur
    }
}

// ---------------------------------------------------------------------------
// GroupNorm + bonus + gate -> z (fp16 for Wo gemm)
// ---------------------------------------------------------------------------
__global__ void gn_kernel(const float* __restrict__ y, const float* __restrict__ r,
                          const float* __restrict__ k, const float* __restrict__ v,
                          const float* __restrict__ g,
                          const float* __restrict__ lnw, const float* __restrict__ lnb,
                          const float* __restrict__ r_k, __half* __restrict__ z)
{
    int gw   = blockIdx.x*8 + (threadIdx.x>>5);
    int lane = threadIdx.x & 31;
    int m = gw >> 5;
    int h = gw & 31;
    size_t base = (size_t)m*Cq + h*HSq;
    int c0 = h*HSq + lane, c1 = c0 + 32;
    float y0=y[base+lane], y1=y[base+lane+32];
    float r0=r[base+lane], r1=r[base+lane+32];
    float k0=k[base+lane], k1=k[base+lane+32];
    float sum = y0+y1;
    float sq  = y0*y0 + y1*y1;
    float dot = r0*k0*r_k[c0] + r1*k1*r_k[c1];
    #pragma unroll
    for (int off=16; off; off>>=1) {
        sum += __shfl_xor_sync(0xffffffffu, sum, off);
        sq  += __shfl_xor_sync(0xffffffffu, sq , off);
        dot += __shfl_xor_sync(0xffffffffu, dot, off);
    }
    float mean = sum * (1.0f/64.0f);
    float var  = sq * (1.0f/64.0f) - mean*mean;
    float inv  = rsqrtf(var + EPS_GN);
    float v0=v[base+lane], v1=v[base+lane+32];
    float g0=g[base+lane], g1=g[base+lane+32];
    float z0 = ((y0-mean)*inv*lnw[c0] + lnb[c0] + dot*v0) * g0;
    float z1 = ((y1-mean)*inv*lnw[c1] + lnb[c1] + dot*v1) * g1;
    z[base+lane]    = __float2half_rn(z0);
    z[base+lane+32] = __float2half_rn(z1);
}

// ---------------------------------------------------------------------------
// Host helpers
// ---------------------------------------------------------------------------
template<int EPI,int RND>
static void rg(const __half* A, const __half* Bw, void* C, int Nd, int Kd,
               const float* bias, const float* vold, const float* vfirst)
{
    cudaFuncSetAttribute(gemm_h<EPI,RND>, cudaFuncAttributeMaxDynamicSharedMemorySize,
                         GSTAGES*STAGE_BYTES);
    dim3 grid((Nd+127)/128, Mq/128);
    gemm_h<EPI,RND><<<grid, 256, GSTAGES*STAGE_BYTES>>>(A, Bw, C, Nd, Kd, bias, vold, vfirst);
}

// ---------------------------------------------------------------------------
// Launch
// ---------------------------------------------------------------------------
extern "C" void kernel_launch(void* const* d_in, const int* in_sizes, int n_in,
                              void* d_out, int out_size)
{
    const float* x       = (const float*)d_in[0];
    const float* v_first = (const float*)d_in[1];
    const float* x_r = (const float*)d_in[2];
    const float* x_w = (const float*)d_in[3];
    const float* x_k = (const float*)d_in[4];
    const float* x_v = (const float*)d_in[5];
    const float* x_a = (const float*)d_in[6];
    const float* x_g = (const float*)d_in[7];
    const float* w0  = (const float*)d_in[8];
    const float* w1  = (const float*)d_in[9];
    const float* w2  = (const float*)d_in[10];
    const float* a0  = (const float*)d_in[11];
    const float* a1  = (const float*)d_in[12];
    const float* a2  = (const float*)d_in[13];
    const float* v0  = (const float*)d_in[14];
    const float* v1  = (const float*)d_in[15];
    const float* v2  = (const float*)d_in[16];
    const float* g1  = (const float*)d_in[17];
    const float* g2  = (const float*)d_in[18];
    const float* k_k = (const float*)d_in[19];
    const float* k_a = (const float*)d_in[20];
    const float* r_k = (const float*)d_in[21];
    const float* Wr  = (const float*)d_in[22];
    const float* Wk  = (const float*)d_in[23];
    const float* Wv  = (const float*)d_in[24];
    const float* Wo  = (const float*)d_in[25];
    const float* lnw = (const float*)d_in[26];
    const float* lnb = (const float*)d_in[27];
    float* out = (float*)d_out;

    __half *xr,*xw,*xk,*xv,*xa,*xg,*zh,*Wrh,*Wkh,*Wvh,*Woh;
    __half *w1h,*w2h,*a1h,*a2h,*v1h,*v2h,*g1h,*g2h,*twh,*tah,*tvh,*tgh;
    float *rB,*kB,*vB,*dec,*aB,*gB,*kkB,*yB;
    cudaGetSymbolAddress((void**)&xr , h_xr);
    cudaGetSymbolAddress((void**)&xw , h_xw);
    cudaGetSymbolAddress((void**)&xk , h_xk);
    cudaGetSymbolAddress((void**)&xv , h_xv);
    cudaGetSymbolAddress((void**)&xa , h_xa);
    cudaGetSymbolAddress((void**)&xg , h_xg);
    cudaGetSymbolAddress((void**)&zh , h_z);
    cudaGetSymbolAddress((void**)&Wrh, h_Wr);
    cudaGetSymbolAddress((void**)&Wkh, h_Wk);
    cudaGetSymbolAddress((void**)&Wvh, h_Wv);
    cudaGetSymbolAddress((void**)&Woh, h_Wo);
    cudaGetSymbolAddress((void**)&w1h, h_w1);
    cudaGetSymbolAddress((void**)&w2h, h_w2);
    cudaGetSymbolAddress((void**)&a1h, h_a1);
    cudaGetSymbolAddress((void**)&a2h, h_a2);
    cudaGetSymbolAddress((void**)&v1h, h_v1);
    cudaGetSymbolAddress((void**)&v2h, h_v2);
    cudaGetSymbolAddress((void**)&g1h, h_g1);
    cudaGetSymbolAddress((void**)&g2h, h_g2);
    cudaGetSymbolAddress((void**)&twh, h_tw);
    cudaGetSymbolAddress((void**)&tah, h_ta);
    cudaGetSymbolAddress((void**)&tvh, h_tv);
    cudaGetSymbolAddress((void**)&tgh, h_tg);
    cudaGetSymbolAddress((void**)&rB , g_r);
    cudaGetSymbolAddress((void**)&kB , g_k);
    cudaGetSymbolAddress((void**)&vB , g_v);
    cudaGetSymbolAddress((void**)&dec, g_dec);
    cudaGetSymbolAddress((void**)&aB , g_a);
    cudaGetSymbolAddress((void**)&gB , g_g);
    cudaGetSymbolAddress((void**)&kkB, g_kk);
    cudaGetSymbolAddress((void**)&yB , g_y);

    // launches 1-4: big weights f32->f16
    #define F2H_(IN,OUT,N) f2h_kernel<<<(unsigned)(((N)/4 + 255)/256), 256>>>(IN, OUT, (size_t)(N)/4);
    F2H_(Wr, Wrh, (size_t)Cq*Cq) F2H_(Wk, Wkh, (size_t)Cq*Cq)
    F2H_(Wv, Wvh, (size_t)Cq*Cq) F2H_(Wo, Woh, (size_t)Cq*Cq)
    #undef F2H_

    // launch 5: token-shift mixes -> fp16
    mix_kernel<<<(unsigned)((BTC/4 + 255)/256), 256>>>(x, x_r,x_w,x_k,x_v,x_a,x_g,
                                                       xr,xw,xk,xv,xa,xg);

    // launch 6 (ncu-profiled): merged big projections r/k/v
    cudaFuncSetAttribute(gemm_h3, cudaFuncAttributeMaxDynamicSharedMemorySize,
                         GSTAGES*STAGE_BYTES);
    gemm_h3<<<dim3(Cq/128, Mq/128, 3), 256, GSTAGES*STAGE_BYTES>>>(
        xr, Wrh, rB, xk, Wkh, kB, xv, Wvh, vB);

    // launches 7-14: lora weight transposes (K-major)
    dim3 tb(32,8);
    transpose_h<<<dim3((DW+31)/32,(Cq+31)/32), tb>>>(w1, w1h, Cq, DW);
    transpose_h<<<dim3((Cq+31)/32,(DW+31)/32), tb>>>(w2, w2h, DW, Cq);
    transpose_h<<<dim3((DA+31)/32,(Cq+31)/32), tb>>>(a1, a1h, Cq, DA);
    transpose_h<<<dim3((Cq+31)/32,(DA+31)/32), tb>>>(a2, a2h, DA, Cq);
    transpose_h<<<dim3((DV+31)/32,(Cq+31)/32), tb>>>(v1, v1h, Cq, DV);
    transpose_h<<<dim3((Cq+31)/32,(DV+31)/32), tb>>>(v2, v2h, DV, Cq);
    transpose_h<<<dim3((DG+31)/32,(Cq+31)/32), tb>>>(g1, g1h, Cq, DG);
    transpose_h<<<dim3((Cq+31)/32,(DG+31)/32), tb>>>(g2, g2h, DG, Cq);

    // loras (up -> fp16 intermediate, down -> fp32 + epilogue)
    rg<1,1>(xw, w1h, twh, DW, Cq, nullptr,nullptr,nullptr);
    rg<3,0>(twh, w2h, dec, Cq, DW, w0, nullptr,nullptr);
    rg<0,1>(xa, a1h, tah, DA, Cq, nullptr,nullptr,nullptr);
    rg<4,0>(tah, a2h, aB, Cq, DA, a0, nullptr,nullptr);
    rg<0,1>(xv, v1h, tvh, DV, Cq, nullptr,nullptr,nullptr);
    rg<5,0>(tvh, v2h, vB, Cq, DV, v0, vB, v_first);
    rg<2,1>(xg, g1h, tgh, DG, Cq, nullptr,nullptr,nullptr);
    rg<0,0>(tgh, g2h, gB, Cq, DG, nullptr,nullptr,nullptr);

    // kk normalize + k transform
    kk_kernel<<<Mq*Hq/8, 256>>>(kB, aB, k_k, k_a, kkB);

    // WKV7 scan (256 threads/block)
    wkv_kernel<<<Bq*Hq, 256>>>(rB, dec, kB, vB, kkB, aB, yB);

    // GroupNorm + bonus + gate -> fp16 z
    gn_kernel<<<Mq*Hq/8, 256>>>(yB, rB, kB, vB, gB, lnw, lnb, r_k, zh);

    // output projection
    rg<0,0>(zh, Woh, out, Cq, Cq, nullptr,nullptr,nullptr);
}

// round 7
// speedup vs baseline: 1.2017x; 1.2017x over previous
#include <cuda_runtime.h>
#include <cuda_fp16.h>
#include <math.h>
#include <stdint.h>

// Problem constants
#define Bq 4
#define Tq 2048
#define Cq 2048
#define Hq 32
#define HSq 64
#define Mq (Bq*Tq)            // 8192 tokens
#define DW 128
#define DA 128
#define DG 224
#define DV 64
#define EPS_GN 0.00064f

// ---------------------------------------------------------------------------
// Scratch (static device globals; zero-initialized at module load)
// ---------------------------------------------------------------------------
#define BTC ((size_t)Mq*Cq)
__device__ __half h_xr[BTC];
__device__ __half h_xw[BTC];
__device__ __half h_xk[BTC];
__device__ __half h_xv[BTC];
__device__ __half h_xa[BTC];
__device__ __half h_xg[BTC];
__device__ __half h_z [BTC];
__device__ __half h_Wr[(size_t)Cq*Cq];
__device__ __half h_Wk[(size_t)Cq*Cq];
__device__ __half h_Wv[(size_t)Cq*Cq];
__device__ __half h_Wo[(size_t)Cq*Cq];
__device__ __half h_w1[(size_t)128*Cq];   // [DW pad128][C]
__device__ __half h_w2[(size_t)Cq*DW];    // [C][DW]
__device__ __half h_a1[(size_t)128*Cq];
__device__ __half h_a2[(size_t)Cq*DA];
__device__ __half h_v1[(size_t)128*Cq];   // [DV pad128][C]
__device__ __half h_v2[(size_t)Cq*DV];
__device__ __half h_g1[(size_t)256*Cq];   // [DG pad256][C]
__device__ __half h_g2[(size_t)Cq*DG];
__device__ __half h_tw[(size_t)Mq*DW];
__device__ __half h_ta[(size_t)Mq*DA];
__device__ __half h_tv[(size_t)Mq*DV];
__device__ __half h_tg[(size_t)Mq*DG];
// fp32 intermediates
__device__ float g_r [BTC];
__device__ float g_k [BTC];
__device__ float g_v [BTC];
__device__ float g_dec[BTC];
__device__ float g_a [BTC];
__device__ float g_g [BTC];
__device__ float g_kk[BTC];
__device__ float g_y [BTC];

__device__ __forceinline__ float sigmoidf_(float x){ return 1.0f/(1.0f+expf(-x)); }

__device__ __forceinline__ void cpa16(uint32_t s, const void* g){
    asm volatile("cp.async.cg.shared.global [%0], [%1], 16;\n" :: "r"(s), "l"(g));
}
__device__ __forceinline__ void ldsm_x4(uint32_t* r, uint32_t addr){
    asm volatile("ldmatrix.sync.aligned.m8n8.x4.shared.b16 {%0,%1,%2,%3}, [%4];"
        : "=r"(r[0]),"=r"(r[1]),"=r"(r[2]),"=r"(r[3]) : "r"(addr));
}
__device__ __forceinline__ void mma16(float* c, const uint32_t* a, const uint32_t* b){
    asm volatile("mma.sync.aligned.m16n8k16.row.col.f32.f16.f16.f32 "
        "{%0,%1,%2,%3},{%4,%5,%6,%7},{%8,%9},{%0,%1,%2,%3};\n"
        : "+f"(c[0]),"+f"(c[1]),"+f"(c[2]),"+f"(c[3])
        : "r"(a[0]),"r"(a[1]),"r"(a[2]),"r"(a[3]),"r"(b[0]),"r"(b[1]));
}

// ---------------------------------------------------------------------------
// Prep: f32 -> f16 copy; transpose f32[R][C] -> f16[C][R]
// ---------------------------------------------------------------------------
__global__ void f2h_kernel(const float* __restrict__ in, __half* __restrict__ out, size_t n4)
{
    size_t i = (size_t)blockIdx.x*blockDim.x + threadIdx.x;
    if (i >= n4) return;
    float4 v = ((const float4*)in)[i];
    ((__half2*)out)[i*2  ] = __floats2half2_rn(v.x, v.y);
    ((__half2*)out)[i*2+1] = __floats2half2_rn(v.z, v.w);
}

__global__ void transpose_h(const float* __restrict__ in, __half* __restrict__ out, int R, int C)
{
    __shared__ float tile[32][33];
    int cb = blockIdx.x*32, rb = blockIdx.y*32;
    int c = cb + threadIdx.x;
    #pragma unroll
    for (int i=threadIdx.y; i<32; i+=8){
        int r = rb + i;
        if (r<R && c<C) tile[i][threadIdx.x] = in[(size_t)r*C + c];
    }
    __syncthreads();
    int r2 = rb + threadIdx.x;
    #pragma unroll
    for (int i=threadIdx.y; i<32; i+=8){
        int c2 = cb + i;
        if (r2<R && c2<C) out[(size_t)c2*R + r2] = __float2half_rn(tile[threadIdx.x][i]);
    }
}

// ---------------------------------------------------------------------------
// Token-shift mix -> fp16 outputs
// ---------------------------------------------------------------------------
__global__ void mix_kernel(const float* __restrict__ x,
                           const float* __restrict__ cr, const float* __restrict__ cw,
                           const float* __restrict__ ck, const float* __restrict__ cv,
                           const float* __restrict__ ca, const float* __restrict__ cg,
                           __half* __restrict__ xr, __half* __restrict__ xw,
                           __half* __restrict__ xk, __half* __restrict__ xv,
                           __half* __restrict__ xa, __half* __restrict__ xg)
{
    size_t i4 = (size_t)blockIdx.x*blockDim.x + threadIdx.x;
    size_t n4 = BTC/4;
    if (i4 >= n4) return;
    size_t flat = i4*4;
    int tok = (int)(flat / Cq);
    int t   = tok % Tq;
    const float4* x4 = (const float4*)x;
    float4 xc = x4[i4];
    float4 xp = (t==0) ? make_float4(0,0,0,0) : x4[i4 - Cq/4];
    float4 dx = make_float4(xp.x-xc.x, xp.y-xc.y, xp.z-xc.z, xp.w-xc.w);
    size_t c4 = i4 % (Cq/4);
    #define MIX1(COEF, OUT) { \
        float4 cf = ((const float4*)COEF)[c4]; \
        ((__half2*)OUT)[i4*2  ] = __floats2half2_rn(xc.x + dx.x*cf.x, xc.y + dx.y*cf.y); \
        ((__half2*)OUT)[i4*2+1] = __floats2half2_rn(xc.z + dx.z*cf.z, xc.w + dx.w*cf.w); }
    MIX1(cr, xr) MIX1(cw, xw) MIX1(ck, xk) MIX1(cv, xv) MIX1(ca, xa) MIX1(cg, xg)
    #undef MIX1
}

// ---------------------------------------------------------------------------
// Epilogue transform: 0 none, 1 tanh, 2 sigmoid, 3 w->decay, 4 a-sigm, 5 v-mix
// ---------------------------------------------------------------------------
template<int EPI>
__device__ __forceinline__ float epi_val(float val, int m, int n, int Nd,
                                         const float* __restrict__ bias,
                                         const float* __restrict__ vold,
                                         const float* __restrict__ vfirst)
{
    if (EPI==1) { val = tanhf(val); }
    else if (EPI==2) { val = sigmoidf_(val); }
    else if (EPI==3) {
        float w = bias[n] + val;
        float mneg = -w;
        float sp = fmaxf(mneg,0.f) + log1pf(expf(-fabsf(mneg)));
        float wl = -sp - 0.5f;
        val = expf(-expf(wl));
    }
    else if (EPI==4) { val = sigmoidf_(bias[n] + val); }
    else if (EPI==5) {
        float s  = sigmoidf_(bias[n] + val);
        size_t idx = (size_t)m*Nd + n;
        float vo = vold[idx];
        val = vo + (vfirst[idx] - vo)*s;
    }
    return val;
}

// ---------------------------------------------------------------------------
// fp16 tensor-core GEMM body: C[m,n] = sum_k A[m,k] * B[n,k]
// CTA 128x128, BK=32, 4-stage cp.async, 8 warps (2Mx4N), warp 64x32.
// ---------------------------------------------------------------------------
#define GSTAGES 4
#define STAGE_HB 10240           // bytes: 128 rows * 40 halves * 2B
#define STAGE_BYTES (2*STAGE_HB)

template<int EPI,int RND>
__device__ __forceinline__
void gemm_body(const __half* __restrict__ A, const __half* __restrict__ Bw,
               void* __restrict__ Cm, int Nd, int Kd,
               const float* __restrict__ bias,
               const float* __restrict__ vold, const float* __restrict__ vfirst)
{
    extern __shared__ __align__(128) char smc[];
    const int tid = threadIdx.x;
    const int lane = tid&31, warp = tid>>5;
    const int bm = blockIdx.y*128, bn = blockIdx.x*128;
    const int wm = (warp&1)*64, wn = (warp>>1)*32;
    const int g = lane>>2, tig = lane&3;
    const uint32_t sbase = (uint32_t)__cvta_generic_to_shared(smc);

    const int arow = wm + (lane&7) + ((lane>>3)&1)*8;   // + mt*16
    const int akof = (lane>>4)*8;
    const int brow = wn + (lane&7) + (lane>>4)*8;       // + p*16
    const int bkof = ((lane>>3)&1)*8;

    float acc[4][4][4];
    #pragma unroll
    for (int i=0;i<4;i++)
        #pragma unroll
        for (int j=0;j<4;j++)
            #pragma unroll
            for (int q=0;q<4;q++) acc[i][j][q]=0.f;

    const int NS = Kd >> 5;

    auto loadSlab = [&](int s, int st){
        const uint32_t sb = sbase + st*STAGE_BYTES;
        const int k0 = s*32;
        #pragma unroll
        for (int i=0;i<2;i++){
            int id  = tid + i*256;
            int row = id>>2, c16 = id&3;
            cpa16(sb + row*80 + c16*16,
                  &A[(size_t)(bm+row)*Kd + k0 + c16*8]);
            cpa16(sb + STAGE_HB + row*80 + c16*16,
                  &Bw[(size_t)(bn+row)*Kd + k0 + c16*8]);
        }
    };
    auto compute = [&](int st){
        const uint32_t sb = sbase + st*STAGE_BYTES;
        #pragma unroll
        for (int ks=0; ks<2; ks++){
            uint32_t af[4][4], bf[2][4];
            #pragma unroll
            for (int mt=0;mt<4;mt++)
                ldsm_x4(af[mt], sb + ((arow+mt*16)*40 + akof + ks*16)*2);
            #pragma unroll
            for (int p=0;p<2;p++)
                ldsm_x4(bf[p], sb + STAGE_HB + ((brow+p*16)*40 + bkof + ks*16)*2);
            #pragma unroll
            for (int mt=0;mt<4;mt++)
                #pragma unroll
                for (int nt=0;nt<4;nt++)
                    mma16(acc[mt][nt], af[mt], &bf[nt>>1][(nt&1)*2]);
        }
    };

    #pragma unroll
    for (int i=0;i<GSTAGES-1;i++){
        if (i<NS) loadSlab(i,i);
        asm volatile("cp.async.commit_group;\n");
    }
    for (int s=0;s<NS;s++){
        int ld = s + GSTAGES-1;
        if (ld < NS) loadSlab(ld, ld&3);
        asm volatile("cp.async.commit_group;\n");
        asm volatile("cp.async.wait_group %0;\n" :: "n"(GSTAGES-1));
        __syncthreads();
        compute(s&3);
        __syncthreads();
    }

    #pragma unroll
    for (int mt=0;mt<4;mt++){
        int r0 = bm + wm + mt*16 + g;
        #pragma unroll
        for (int nt=0;nt<4;nt++){
            int n0 = bn + wn + nt*8 + tig*2;
            if (n0 < Nd){
                float* c = acc[mt][nt];
                float v00 = epi_val<EPI>(c[0], r0,   n0,   Nd, bias, vold, vfirst);
                float v01 = epi_val<EPI>(c[1], r0,   n0+1, Nd, bias, vold, vfirst);
                float v10 = epi_val<EPI>(c[2], r0+8, n0,   Nd, bias, vold, vfirst);
                float v11 = epi_val<EPI>(c[3], r0+8, n0+1, Nd, bias, vold, vfirst);
                if (RND){
                    __half* O = (__half*)Cm;
                    *(__half2*)&O[(size_t)r0*Nd + n0]     = __floats2half2_rn(v00, v01);
                    *(__half2*)&O[(size_t)(r0+8)*Nd + n0] = __floats2half2_rn(v10, v11);
                } else {
                    float* O = (float*)Cm;
                    *(float2*)&O[(size_t)r0*Nd + n0]     = make_float2(v00, v01);
                    *(float2*)&O[(size_t)(r0+8)*Nd + n0] = make_float2(v10, v11);
                }
            }
        }
    }
}

template<int EPI,int RND>
__global__ __launch_bounds__(256,2)
void gemm_h(const __half* __restrict__ A, const __half* __restrict__ Bw,
            void* __restrict__ Cm, int Nd, int Kd,
            const float* __restrict__ bias,
            const float* __restrict__ vold, const float* __restrict__ vfirst)
{
    gemm_body<EPI,RND>(A, Bw, Cm, Nd, Kd, bias, vold, vfirst);
}

// merged r/k/v projections: blockIdx.z selects which
__global__ __launch_bounds__(256,2)
void gemm_h3(const __half* __restrict__ A0, const __half* __restrict__ B0, float* __restrict__ C0,
             const __half* __restrict__ A1, const __half* __restrict__ B1, float* __restrict__ C1,
             const __half* __restrict__ A2, const __half* __restrict__ B2, float* __restrict__ C2)
{
    const __half* A = (blockIdx.z==0) ? A0 : (blockIdx.z==1) ? A1 : A2;
    const __half* B = (blockIdx.z==0) ? B0 : (blockIdx.z==1) ? B1 : B2;
    float*        C = (blockIdx.z==0) ? C0 : (blockIdx.z==1) ? C1 : C2;
    gemm_body<0,0>(A, B, (void*)C, Cq, Cq, nullptr, nullptr, nullptr);
}

// ---------------------------------------------------------------------------
// kk normalize + k transform
// ---------------------------------------------------------------------------
__global__ void kk_kernel(float* __restrict__ k, const float* __restrict__ a,
                          const float* __restrict__ k_k, const float* __restrict__ k_a,
                          float* __restrict__ kk)
{
    int gw   = blockIdx.x*8 + (threadIdx.x>>5);
    int lane = threadIdx.x & 31;
    int m = gw >> 5;
    int h = gw & 31;
    size_t base = (size_t)m*Cq + h*HSq;
    int c0 = h*HSq + lane, c1 = c0 + 32;
    float k0 = k[base+lane], k1 = k[base+lane+32];
    float kk0 = k0*k_k[c0], kk1 = k1*k_k[c1];
    float s = kk0*kk0 + kk1*kk1;
    #pragma unroll
    for (int off=16; off; off>>=1) s += __shfl_xor_sync(0xffffffffu, s, off);
    float inv = 1.0f / fmaxf(sqrtf(s), 1e-12f);
    kk[base+lane]    = kk0*inv;
    kk[base+lane+32] = kk1*inv;
    float a0 = a[base+lane], a1 = a[base+lane+32];
    k[base+lane]    = k0*(1.0f + (a0-1.0f)*k_a[c0]);
    k[base+lane+32] = k1*(1.0f + (a1-1.0f)*k_a[c1]);
}

// ---------------------------------------------------------------------------
// WKV7 scan: 256 threads per (b,h); thread (i,p) owns row i, quarter p.
// REGISTER-staged prefetch (gmem latency hidden) + double-buffered smem,
// ONE __syncthreads per step.
// ---------------------------------------------------------------------------
__global__ __launch_bounds__(256)
void wkv_kernel(const float* __restrict__ r, const float* __restrict__ wd,
                const float* __restrict__ k, const float* __restrict__ v,
                const float* __restrict__ kkp, const float* __restrict__ ap,
                float* __restrict__ y)
{
    const int bh = blockIdx.x;
    const int b = bh >> 5;
    const int h = bh & 31;
    const int tid = threadIdx.x;
    const int i = tid >> 2;     // state row
    const int p = tid & 3;      // quarter (cols p*16 .. p*16+15)
    const int role = tid >> 6;  // loader role 0..3
    const int lc   = tid & 63;  // loader column

    // [buf][array][64]; arrays: 0=r 1=w 2=k 3=a(-kk) 4=b(kk*a) 5=v
    __shared__ __align__(16) float sbuf[2][6][64];

    float st[16];
    #pragma unroll
    for (int j=0;j<16;j++) st[j]=0.f;

    const size_t base = ((size_t)b*Tq)*Cq + (size_t)h*HSq;

    // register-stage step 0
    float ld0=0.f, ld1=0.f;
    if (role==0){ ld0 = r[base+lc];  ld1 = v[base+lc]; }
    else if (role==1){ ld0 = wd[base+lc]; }
    else if (role==2){ ld0 = k[base+lc]; }
    else { ld0 = kkp[base+lc]; ld1 = ap[base+lc]; }

    size_t o = base;
    for (int t=0; t<Tq; t++){
        const int cur = t&1;

        // publish step t (from registers)
        if (role==0){ sbuf[cur][0][lc] = ld0; sbuf[cur][5][lc] = ld1; }
        else if (role==1){ sbuf[cur][1][lc] = ld0; }
        else if (role==2){ sbuf[cur][2][lc] = ld0; }
        else { sbuf[cur][3][lc] = -ld0; sbuf[cur][4][lc] = ld0*ld1; }
        __syncthreads();

        // issue prefetch of step t+1 into registers (overlaps compute below)
        if (t+1 < Tq){
            size_t on = o + Cq;
            if (role==0){ ld0 = r[on+lc];  ld1 = v[on+lc]; }
            else if (role==1){ ld0 = wd[on+lc]; }
            else if (role==2){ ld0 = k[on+lc]; }
            else { ld0 = kkp[on+lc]; ld1 = ap[on+lc]; }
        }

        // ---- compute on cur ----
        const float4* A4 = (const float4*)&sbuf[cur][3][p*16];
        float s0=0,s1=0,s2=0,s3=0;
        #pragma unroll
        for (int j=0;j<4;j++){
            float4 a4 = A4[j];
            s0 += st[4*j+0]*a4.x; s1 += st[4*j+1]*a4.y;
            s2 += st[4*j+2]*a4.z; s3 += st[4*j+3]*a4.w;
        }
        float sa = (s0+s1)+(s2+s3);
        sa += __shfl_xor_sync(0xffffffffu, sa, 1);
        sa += __shfl_xor_sync(0xffffffffu, sa, 2);

        const float vv = sbuf[cur][5][i];
        const float4* W4=(const float4*)&sbuf[cur][1][p*16];
        const float4* K4=(const float4*)&sbuf[cur][2][p*16];
        const float4* B4=(const float4*)&sbuf[cur][4][p*16];
        const float4* R4=(const float4*)&sbuf[cur][0][p*16];
        float o0=0,o1=0,o2=0,o3=0;
        #pragma unroll
        for (int j=0;j<4;j++){
            float4 w4=W4[j], k4=K4[j], b4=B4[j], r4=R4[j];
            float t0 = st[4*j+0]*w4.x + vv*k4.x + sa*b4.x;
            float t1 = st[4*j+1]*w4.y + vv*k4.y + sa*b4.y;
            float t2 = st[4*j+2]*w4.z + vv*k4.z + sa*b4.z;
            float t3 = st[4*j+3]*w4.w + vv*k4.w + sa*b4.w;
            st[4*j+0]=t0; st[4*j+1]=t1; st[4*j+2]=t2; st[4*j+3]=t3;
            o0 += t0*r4.x; o1 += t1*r4.y; o2 += t2*r4.z; o3 += t3*r4.w;
        }
        float op = (o0+o1)+(o2+o3);
        op += __shfl_xor_sync(0xffffffffu, op, 1);
        op += __shfl_xor_sync(0xffffffffu, op, 2);
        if (p==0) y[o+i] = op;

        o += Cq;
        // no trailing barrier: next iter writes the OTHER buffer; writes to
        // this buffer at t+2 are ordered behind t's reads by t+1's barrier.
    }
}

// ---------------------------------------------------------------------------
// GroupNorm + bonus + gate -> z (fp16 for Wo gemm)
// ---------------------------------------------------------------------------
__global__ void gn_kernel(const float* __restrict__ y, const float* __restrict__ r,
                          const float* __restrict__ k, const float* __restrict__ v,
                          const float* __restrict__ g,
                          const float* __restrict__ lnw, const float* __restrict__ lnb,
                          const float* __restrict__ r_k, __half* __restrict__ z)
{
    int gw   = blockIdx.x*8 + (threadIdx.x>>5);
    int lane = threadIdx.x & 31;
    int m = gw >> 5;
    int h = gw & 31;
    size_t base = (size_t)m*Cq + h*HSq;
    int c0 = h*HSq + lane, c1 = c0 + 32;
    float y0=y[base+lane], y1=y[base+lane+32];
    float r0=r[base+lane], r1=r[base+lane+32];
    float k0=k[base+lane], k1=k[base+lane+32];
    float sum = y0+y1;
    float sq  = y0*y0 + y1*y1;
    float dot = r0*k0*r_k[c0] + r1*k1*r_k[c1];
    #pragma unroll
    for (int off=16; off; off>>=1) {
        sum += __shfl_xor_sync(0xffffffffu, sum, off);
        sq  += __shfl_xor_sync(0xffffffffu, sq , off);
        dot += __shfl_xor_sync(0xffffffffu, dot, off);
    }
    float mean = sum * (1.0f/64.0f);
    float var  = sq * (1.0f/64.0f) - mean*mean;
    float inv  = rsqrtf(var + EPS_GN);
    float v0=v[base+lane], v1=v[base+lane+32];
    float g0=g[base+lane], g1=g[base+lane+32];
    float z0 = ((y0-mean)*inv*lnw[c0] + lnb[c0] + dot*v0) * g0;
    float z1 = ((y1-mean)*inv*lnw[c1] + lnb[c1] + dot*v1) * g1;
    z[base+lane]    = __float2half_rn(z0);
    z[base+lane+32] = __float2half_rn(z1);
}

// ---------------------------------------------------------------------------
// Host helpers
// ---------------------------------------------------------------------------
template<int EPI,int RND>
static void rg(const __half* A, const __half* Bw, void* C, int Nd, int Kd,
               const float* bias, const float* vold, const float* vfirst)
{
    cudaFuncSetAttribute(gemm_h<EPI,RND>, cudaFuncAttributeMaxDynamicSharedMemorySize,
                         GSTAGES*STAGE_BYTES);
    dim3 grid((Nd+127)/128, Mq/128);
    gemm_h<EPI,RND><<<grid, 256, GSTAGES*STAGE_BYTES>>>(A, Bw, C, Nd, Kd, bias, vold, vfirst);
}

// ---------------------------------------------------------------------------
// Launch
// ---------------------------------------------------------------------------
extern "C" void kernel_launch(void* const* d_in, const int* in_sizes, int n_in,
                              void* d_out, int out_size)
{
    const float* x       = (const float*)d_in[0];
    const float* v_first = (const float*)d_in[1];
    const float* x_r = (const float*)d_in[2];
    const float* x_w = (const float*)d_in[3];
    const float* x_k = (const float*)d_in[4];
    const float* x_v = (const float*)d_in[5];
    const float* x_a = (const float*)d_in[6];
    const float* x_g = (const float*)d_in[7];
    const float* w0  = (const float*)d_in[8];
    const float* w1  = (const float*)d_in[9];
    const float* w2  = (const float*)d_in[10];
    const float* a0  = (const float*)d_in[11];
    const float* a1  = (const float*)d_in[12];
    const float* a2  = (const float*)d_in[13];
    const float* v0  = (const float*)d_in[14];
    const float* v1  = (const float*)d_in[15];
    const float* v2  = (const float*)d_in[16];
    const float* g1  = (const float*)d_in[17];
    const float* g2  = (const float*)d_in[18];
    const float* k_k = (const float*)d_in[19];
    const float* k_a = (const float*)d_in[20];
    const float* r_k = (const float*)d_in[21];
    const float* Wr  = (const float*)d_in[22];
    const float* Wk  = (const float*)d_in[23];
    const float* Wv  = (const float*)d_in[24];
    const float* Wo  = (const float*)d_in[25];
    const float* lnw = (const float*)d_in[26];
    const float* lnb = (const float*)d_in[27];
    float* out = (float*)d_out;

    __half *xr,*xw,*xk,*xv,*xa,*xg,*zh,*Wrh,*Wkh,*Wvh,*Woh;
    __half *w1h,*w2h,*a1h,*a2h,*v1h,*v2h,*g1h,*g2h,*twh,*tah,*tvh,*tgh;
    float *rB,*kB,*vB,*dec,*aB,*gB,*kkB,*yB;
    cudaGetSymbolAddress((void**)&xr , h_xr);
    cudaGetSymbolAddress((void**)&xw , h_xw);
    cudaGetSymbolAddress((void**)&xk , h_xk);
    cudaGetSymbolAddress((void**)&xv , h_xv);
    cudaGetSymbolAddress((void**)&xa , h_xa);
    cudaGetSymbolAddress((void**)&xg , h_xg);
    cudaGetSymbolAddress((void**)&zh , h_z);
    cudaGetSymbolAddress((void**)&Wrh, h_Wr);
    cudaGetSymbolAddress((void**)&Wkh, h_Wk);
    cudaGetSymbolAddress((void**)&Wvh, h_Wv);
    cudaGetSymbolAddress((void**)&Woh, h_Wo);
    cudaGetSymbolAddress((void**)&w1h, h_w1);
    cudaGetSymbolAddress((void**)&w2h, h_w2);
    cudaGetSymbolAddress((void**)&a1h, h_a1);
    cudaGetSymbolAddress((void**)&a2h, h_a2);
    cudaGetSymbolAddress((void**)&v1h, h_v1);
    cudaGetSymbolAddress((void**)&v2h, h_v2);
    cudaGetSymbolAddress((void**)&g1h, h_g1);
    cudaGetSymbolAddress((void**)&g2h, h_g2);
    cudaGetSymbolAddress((void**)&twh, h_tw);
    cudaGetSymbolAddress((void**)&tah, h_ta);
    cudaGetSymbolAddress((void**)&tvh, h_tv);
    cudaGetSymbolAddress((void**)&tgh, h_tg);
    cudaGetSymbolAddress((void**)&rB , g_r);
    cudaGetSymbolAddress((void**)&kB , g_k);
    cudaGetSymbolAddress((void**)&vB , g_v);
    cudaGetSymbolAddress((void**)&dec, g_dec);
    cudaGetSymbolAddress((void**)&aB , g_a);
    cudaGetSymbolAddress((void**)&gB , g_g);
    cudaGetSymbolAddress((void**)&kkB, g_kk);
    cudaGetSymbolAddress((void**)&yB , g_y);

    // big weights f32->f16
    #define F2H_(IN,OUT,N) f2h_kernel<<<(unsigned)(((N)/4 + 255)/256), 256>>>(IN, OUT, (size_t)(N)/4);
    F2H_(Wr, Wrh, (size_t)Cq*Cq) F2H_(Wk, Wkh, (size_t)Cq*Cq)
    F2H_(Wv, Wvh, (size_t)Cq*Cq) F2H_(Wo, Woh, (size_t)Cq*Cq)
    #undef F2H_

    // token-shift mixes -> fp16
    mix_kernel<<<(unsigned)((BTC/4 + 255)/256), 256>>>(x, x_r,x_w,x_k,x_v,x_a,x_g,
                                                       xr,xw,xk,xv,xa,xg);

    // merged big projections r/k/v
    cudaFuncSetAttribute(gemm_h3, cudaFuncAttributeMaxDynamicSharedMemorySize,
                         GSTAGES*STAGE_BYTES);
    gemm_h3<<<dim3(Cq/128, Mq/128, 3), 256, GSTAGES*STAGE_BYTES>>>(
        xr, Wrh, rB, xk, Wkh, kB, xv, Wvh, vB);

    // lora weight transposes (K-major)
    dim3 tb(32,8);
    transpose_h<<<dim3((DW+31)/32,(Cq+31)/32), tb>>>(w1, w1h, Cq, DW);
    transpose_h<<<dim3((Cq+31)/32,(DW+31)/32), tb>>>(w2, w2h, DW, Cq);
    transpose_h<<<dim3((DA+31)/32,(Cq+31)/32), tb>>>(a1, a1h, Cq, DA);
    transpose_h<<<dim3((Cq+31)/32,(DA+31)/32), tb>>>(a2, a2h, DA, Cq);
    transpose_h<<<dim3((DV+31)/32,(Cq+31)/32), tb>>>(v1, v1h, Cq, DV);
    transpose_h<<<dim3((Cq+31)/32,(DV+31)/32), tb>>>(v2, v2h, DV, Cq);
    transpose_h<<<dim3((DG+31)/32,(Cq+31)/32), tb>>>(g1, g1h, Cq, DG);
    transpose_h<<<dim3((Cq+31)/32,(DG+31)/32), tb>>>(g2, g2h, DG, Cq);

    // loras (up -> fp16 intermediate, down -> fp32 + epilogue)
    rg<1,1>(xw, w1h, twh, DW, Cq, nullptr,nullptr,nullptr);
    rg<3,0>(twh, w2h, dec, Cq, DW, w0, nullptr,nullptr);
    rg<0,1>(xa, a1h, tah, DA, Cq, nullptr,nullptr,nullptr);
    rg<4,0>(tah, a2h, aB, Cq, DA, a0, nullptr,nullptr);
    rg<0,1>(xv, v1h, tvh, DV, Cq, nullptr,nullptr,nullptr);
    rg<5,0>(tvh, v2h, vB, Cq, DV, v0, vB, v_first);
    rg<2,1>(xg, g1h, tgh, DG, Cq, nullptr,nullptr,nullptr);
    rg<0,0>(tgh, g2h, gB, Cq, DG, nullptr,nullptr,nullptr);

    // kk normalize + k transform
    kk_kernel<<<Mq*Hq/8, 256>>>(kB, aB, k_k, k_a, kkB);

    // WKV7 scan (256 threads/block, register-prefetched)
    wkv_kernel<<<Bq*Hq, 256>>>(rB, dec, kB, vB, kkB, aB, yB);

    // GroupNorm + bonus + gate -> fp16 z
    gn_kernel<<<Mq*Hq/8, 256>>>(yB, rB, kB, vB, gB, lnw, lnb, r_k, zh);

    // output projection
    rg<0,0>(zh, Woh, out, Cq, Cq, nullptr,nullptr,nullptr);
}

// round 8
// speedup vs baseline: 1.2902x; 1.0737x over previous
#include <cuda_runtime.h>
#include <cuda_fp16.h>
#include <math.h>
#include <stdint.h>

// Problem constants
#define Bq 4
#define Tq 2048
#define Cq 2048
#define Hq 32
#define HSq 64
#define Mq (Bq*Tq)            // 8192 tokens
#define DW 128
#define DA 128
#define DG 224
#define DV 64
#define EPS_GN 0.00064f

// ---------------------------------------------------------------------------
// Scratch (static device globals; zero-initialized at module load)
// ---------------------------------------------------------------------------
#define BTC ((size_t)Mq*Cq)
__device__ __half h_xr[BTC];
__device__ __half h_xw[BTC];
__device__ __half h_xk[BTC];
__device__ __half h_xv[BTC];
__device__ __half h_xa[BTC];
__device__ __half h_xg[BTC];
__device__ __half h_z [BTC];
__device__ __half h_Wr[(size_t)Cq*Cq];
__device__ __half h_Wk[(size_t)Cq*Cq];
__device__ __half h_Wv[(size_t)Cq*Cq];
__device__ __half h_Wo[(size_t)Cq*Cq];
__device__ __half h_w1[(size_t)128*Cq];   // [DW pad128][C]
__device__ __half h_w2[(size_t)Cq*DW];    // [C][DW]
__device__ __half h_a1[(size_t)128*Cq];
__device__ __half h_a2[(size_t)Cq*DA];
__device__ __half h_v1[(size_t)128*Cq];   // [DV pad128][C]
__device__ __half h_v2[(size_t)Cq*DV];
__device__ __half h_g1[(size_t)256*Cq];   // [DG pad256][C]
__device__ __half h_g2[(size_t)Cq*DG];
__device__ __half h_tw[(size_t)Mq*DW];
__device__ __half h_ta[(size_t)Mq*DA];
__device__ __half h_tv[(size_t)Mq*DV];
__device__ __half h_tg[(size_t)Mq*DG];
// fp32 intermediates
__device__ float g_r [BTC];
__device__ float g_k [BTC];
__device__ float g_v [BTC];
__device__ float g_dec[BTC];
__device__ float g_a [BTC];
__device__ float g_g [BTC];
__device__ float g_kk[BTC];
__device__ float g_y [BTC];

__device__ __forceinline__ float sigmoidf_(float x){ return 1.0f/(1.0f+expf(-x)); }

__device__ __forceinline__ void cpa16(uint32_t s, const void* g){
    asm volatile("cp.async.cg.shared.global [%0], [%1], 16;\n" :: "r"(s), "l"(g));
}
__device__ __forceinline__ void ldsm_x4(uint32_t* r, uint32_t addr){
    asm volatile("ldmatrix.sync.aligned.m8n8.x4.shared.b16 {%0,%1,%2,%3}, [%4];"
        : "=r"(r[0]),"=r"(r[1]),"=r"(r[2]),"=r"(r[3]) : "r"(addr));
}
__device__ __forceinline__ void mma16(float* c, const uint32_t* a, const uint32_t* b){
    asm volatile("mma.sync.aligned.m16n8k16.row.col.f32.f16.f16.f32 "
        "{%0,%1,%2,%3},{%4,%5,%6,%7},{%8,%9},{%0,%1,%2,%3};\n"
        : "+f"(c[0]),"+f"(c[1]),"+f"(c[2]),"+f"(c[3])
        : "r"(a[0]),"r"(a[1]),"r"(a[2]),"r"(a[3]),"r"(b[0]),"r"(b[1]));
}

// ---------------------------------------------------------------------------
// Prep: 4x f32->f16 weight copies in ONE launch (blockIdx.y selects)
// ---------------------------------------------------------------------------
__global__ void f2h4_kernel(const float* __restrict__ i0, __half* __restrict__ o0,
                            const float* __restrict__ i1, __half* __restrict__ o1,
                            const float* __restrict__ i2, __half* __restrict__ o2,
                            const float* __restrict__ i3, __half* __restrict__ o3,
                            size_t n4)
{
    size_t i = (size_t)blockIdx.x*blockDim.x + threadIdx.x;
    if (i >= n4) return;
    const float* in = (blockIdx.y==0)?i0:(blockIdx.y==1)?i1:(blockIdx.y==2)?i2:i3;
    __half* out     = (blockIdx.y==0)?o0:(blockIdx.y==1)?o1:(blockIdx.y==2)?o2:o3;
    float4 v = ((const float4*)in)[i];
    ((__half2*)out)[i*2  ] = __floats2half2_rn(v.x, v.y);
    ((__half2*)out)[i*2+1] = __floats2half2_rn(v.z, v.w);
}

// ---------------------------------------------------------------------------
// 8 lora-weight transposes (f32[R][C] -> f16[C][R]) in ONE launch (blockIdx.z)
// ---------------------------------------------------------------------------
__device__ __forceinline__
void transpose_body(const float* __restrict__ in, __half* __restrict__ out, int R, int C)
{
    __shared__ float tile[32][33];
    int cb = blockIdx.x*32, rb = blockIdx.y*32;
    if (cb >= C || rb >= R) return;
    int c = cb + threadIdx.x;
    #pragma unroll
    for (int i=threadIdx.y; i<32; i+=8){
        int r = rb + i;
        if (r<R && c<C) tile[i][threadIdx.x] = in[(size_t)r*C + c];
    }
    __syncthreads();
    int r2 = rb + threadIdx.x;
    #pragma unroll
    for (int i=threadIdx.y; i<32; i+=8){
        int c2 = cb + i;
        if (r2<R && c2<C) out[(size_t)c2*R + r2] = __float2half_rn(tile[threadIdx.x][i]);
    }
}

__global__ void transpose8(const float* w1, __half* w1h, const float* w2, __half* w2h,
                           const float* a1, __half* a1h, const float* a2, __half* a2h,
                           const float* v1, __half* v1h, const float* v2, __half* v2h,
                           const float* g1, __half* g1h, const float* g2, __half* g2h)
{
    switch(blockIdx.z){
        case 0: transpose_body(w1, w1h, Cq, DW); break;
        case 1: transpose_body(w2, w2h, DW, Cq); break;
        case 2: transpose_body(a1, a1h, Cq, DA); break;
        case 3: transpose_body(a2, a2h, DA, Cq); break;
        case 4: transpose_body(v1, v1h, Cq, DV); break;
        case 5: transpose_body(v2, v2h, DV, Cq); break;
        case 6: transpose_body(g1, g1h, Cq, DG); break;
        default: transpose_body(g2, g2h, DG, Cq); break;
    }
}

// ---------------------------------------------------------------------------
// Token-shift mix -> fp16 outputs
// ---------------------------------------------------------------------------
__global__ void mix_kernel(const float* __restrict__ x,
                           const float* __restrict__ cr, const float* __restrict__ cw,
                           const float* __restrict__ ck, const float* __restrict__ cv,
                           const float* __restrict__ ca, const float* __restrict__ cg,
                           __half* __restrict__ xr, __half* __restrict__ xw,
                           __half* __restrict__ xk, __half* __restrict__ xv,
                           __half* __restrict__ xa, __half* __restrict__ xg)
{
    size_t i4 = (size_t)blockIdx.x*blockDim.x + threadIdx.x;
    size_t n4 = BTC/4;
    if (i4 >= n4) return;
    size_t flat = i4*4;
    int tok = (int)(flat / Cq);
    int t   = tok % Tq;
    const float4* x4 = (const float4*)x;
    float4 xc = x4[i4];
    float4 xp = (t==0) ? make_float4(0,0,0,0) : x4[i4 - Cq/4];
    float4 dx = make_float4(xp.x-xc.x, xp.y-xc.y, xp.z-xc.z, xp.w-xc.w);
    size_t c4 = i4 % (Cq/4);
    #define MIX1(COEF, OUT) { \
        float4 cf = ((const float4*)COEF)[c4]; \
        ((__half2*)OUT)[i4*2  ] = __floats2half2_rn(xc.x + dx.x*cf.x, xc.y + dx.y*cf.y); \
        ((__half2*)OUT)[i4*2+1] = __floats2half2_rn(xc.z + dx.z*cf.z, xc.w + dx.w*cf.w); }
    MIX1(cr, xr) MIX1(cw, xw) MIX1(ck, xk) MIX1(cv, xv) MIX1(ca, xa) MIX1(cg, xg)
    #undef MIX1
}

// ---------------------------------------------------------------------------
// Epilogue transform: 0 none, 1 tanh, 2 sigmoid, 3 w->decay, 4 a-sigm, 5 v-mix
// ---------------------------------------------------------------------------
template<int EPI>
__device__ __forceinline__ float epi_val(float val, int m, int n, int Nd,
                                         const float* __restrict__ bias,
                                         const float* __restrict__ vold,
                                         const float* __restrict__ vfirst)
{
    if (EPI==1) { val = tanhf(val); }
    else if (EPI==2) { val = sigmoidf_(val); }
    else if (EPI==3) {
        float w = bias[n] + val;
        float mneg = -w;
        float sp = fmaxf(mneg,0.f) + log1pf(expf(-fabsf(mneg)));
        float wl = -sp - 0.5f;
        val = expf(-expf(wl));
    }
    else if (EPI==4) { val = sigmoidf_(bias[n] + val); }
    else if (EPI==5) {
        float s  = sigmoidf_(bias[n] + val);
        size_t idx = (size_t)m*Nd + n;
        float vo = vold[idx];
        val = vo + (vfirst[idx] - vo)*s;
    }
    return val;
}

// ---------------------------------------------------------------------------
// fp16 tensor-core GEMM body: C[m,n] = sum_k A[m,k] * B[n,k]
// CTA 128x128, BK=32, 4-stage cp.async, 8 warps (2Mx4N), warp 64x32.
// ---------------------------------------------------------------------------
#define GSTAGES 4
#define STAGE_HB 10240           // bytes: 128 rows * 40 halves * 2B
#define STAGE_BYTES (2*STAGE_HB)

template<int EPI,int RND>
__device__ __forceinline__
void gemm_body(const __half* __restrict__ A, const __half* __restrict__ Bw,
               void* __restrict__ Cm, int Nd, int Kd,
               const float* __restrict__ bias,
               const float* __restrict__ vold, const float* __restrict__ vfirst)
{
    extern __shared__ __align__(128) char smc[];
    const int tid = threadIdx.x;
    const int lane = tid&31, warp = tid>>5;
    const int bm = blockIdx.y*128, bn = blockIdx.x*128;
    const int wm = (warp&1)*64, wn = (warp>>1)*32;
    const int g = lane>>2, tig = lane&3;
    const uint32_t sbase = (uint32_t)__cvta_generic_to_shared(smc);

    const int arow = wm + (lane&7) + ((lane>>3)&1)*8;   // + mt*16
    const int akof = (lane>>4)*8;
    const int brow = wn + (lane&7) + (lane>>4)*8;       // + p*16
    const int bkof = ((lane>>3)&1)*8;

    float acc[4][4][4];
    #pragma unroll
    for (int i=0;i<4;i++)
        #pragma unroll
        for (int j=0;j<4;j++)
            #pragma unroll
            for (int q=0;q<4;q++) acc[i][j][q]=0.f;

    const int NS = Kd >> 5;

    auto loadSlab = [&](int s, int st){
        const uint32_t sb = sbase + st*STAGE_BYTES;
        const int k0 = s*32;
        #pragma unroll
        for (int i=0;i<2;i++){
            int id  = tid + i*256;
            int row = id>>2, c16 = id&3;
            cpa16(sb + row*80 + c16*16,
                  &A[(size_t)(bm+row)*Kd + k0 + c16*8]);
            cpa16(sb + STAGE_HB + row*80 + c16*16,
                  &Bw[(size_t)(bn+row)*Kd + k0 + c16*8]);
        }
    };
    auto compute = [&](int st){
        const uint32_t sb = sbase + st*STAGE_BYTES;
        #pragma unroll
        for (int ks=0; ks<2; ks++){
            uint32_t af[4][4], bf[2][4];
            #pragma unroll
            for (int mt=0;mt<4;mt++)
                ldsm_x4(af[mt], sb + ((arow+mt*16)*40 + akof + ks*16)*2);
            #pragma unroll
            for (int p=0;p<2;p++)
                ldsm_x4(bf[p], sb + STAGE_HB + ((brow+p*16)*40 + bkof + ks*16)*2);
            #pragma unroll
            for (int mt=0;mt<4;mt++)
                #pragma unroll
                for (int nt=0;nt<4;nt++)
                    mma16(acc[mt][nt], af[mt], &bf[nt>>1][(nt&1)*2]);
        }
    };

    #pragma unroll
    for (int i=0;i<GSTAGES-1;i++){
        if (i<NS) loadSlab(i,i);
        asm volatile("cp.async.commit_group;\n");
    }
    for (int s=0;s<NS;s++){
        int ld = s + GSTAGES-1;
        if (ld < NS) loadSlab(ld, ld&3);
        asm volatile("cp.async.commit_group;\n");
        asm volatile("cp.async.wait_group %0;\n" :: "n"(GSTAGES-1));
        __syncthreads();
        compute(s&3);
        __syncthreads();
    }

    #pragma unroll
    for (int mt=0;mt<4;mt++){
        int r0 = bm + wm + mt*16 + g;
        #pragma unroll
        for (int nt=0;nt<4;nt++){
            int n0 = bn + wn + nt*8 + tig*2;
            if (n0 < Nd){
                float* c = acc[mt][nt];
                float v00 = epi_val<EPI>(c[0], r0,   n0,   Nd, bias, vold, vfirst);
                float v01 = epi_val<EPI>(c[1], r0,   n0+1, Nd, bias, vold, vfirst);
                float v10 = epi_val<EPI>(c[2], r0+8, n0,   Nd, bias, vold, vfirst);
                float v11 = epi_val<EPI>(c[3], r0+8, n0+1, Nd, bias, vold, vfirst);
                if (RND){
                    __half* O = (__half*)Cm;
                    *(__half2*)&O[(size_t)r0*Nd + n0]     = __floats2half2_rn(v00, v01);
                    *(__half2*)&O[(size_t)(r0+8)*Nd + n0] = __floats2half2_rn(v10, v11);
                } else {
                    float* O = (float*)Cm;
                    *(float2*)&O[(size_t)r0*Nd + n0]     = make_float2(v00, v01);
                    *(float2*)&O[(size_t)(r0+8)*Nd + n0] = make_float2(v10, v11);
                }
            }
        }
    }
}

template<int EPI,int RND>
__global__ __launch_bounds__(256,2)
void gemm_h(const __half* __restrict__ A, const __half* __restrict__ Bw,
            void* __restrict__ Cm, int Nd, int Kd,
            const float* __restrict__ bias,
            const float* __restrict__ vold, const float* __restrict__ vfirst)
{
    gemm_body<EPI,RND>(A, Bw, Cm, Nd, Kd, bias, vold, vfirst);
}

// 4 lora up-projections in ONE launch (blockIdx.z selects; uniform per block)
__global__ __launch_bounds__(256,2)
void gemm_lora4(const __half* __restrict__ xw, const __half* __restrict__ w1h, __half* __restrict__ tw,
                const __half* __restrict__ xa, const __half* __restrict__ a1h, __half* __restrict__ ta,
                const __half* __restrict__ xv, const __half* __restrict__ v1h, __half* __restrict__ tv,
                const __half* __restrict__ xg, const __half* __restrict__ g1h, __half* __restrict__ tg)
{
    const int bn = blockIdx.x*128;
    switch(blockIdx.z){
        case 0: if (bn >= DW) return; gemm_body<1,1>(xw, w1h, (void*)tw, DW, Cq, nullptr,nullptr,nullptr); break;
        case 1: if (bn >= DA) return; gemm_body<0,1>(xa, a1h, (void*)ta, DA, Cq, nullptr,nullptr,nullptr); break;
        case 2: if (bn >= DV) return; gemm_body<0,1>(xv, v1h, (void*)tv, DV, Cq, nullptr,nullptr,nullptr); break;
        default:                      gemm_body<2,1>(xg, g1h, (void*)tg, DG, Cq, nullptr,nullptr,nullptr); break;
    }
}

// ---------------------------------------------------------------------------
// kk normalize + k transform
// ---------------------------------------------------------------------------
__global__ void kk_kernel(float* __restrict__ k, const float* __restrict__ a,
                          const float* __restrict__ k_k, const float* __restrict__ k_a,
                          float* __restrict__ kk)
{
    int gw   = blockIdx.x*8 + (threadIdx.x>>5);
    int lane = threadIdx.x & 31;
    int m = gw >> 5;
    int h = gw & 31;
    size_t base = (size_t)m*Cq + h*HSq;
    int c0 = h*HSq + lane, c1 = c0 + 32;
    float k0 = k[base+lane], k1 = k[base+lane+32];
    float kk0 = k0*k_k[c0], kk1 = k1*k_k[c1];
    float s = kk0*kk0 + kk1*kk1;
    #pragma unroll
    for (int off=16; off; off>>=1) s += __shfl_xor_sync(0xffffffffu, s, off);
    float inv = 1.0f / fmaxf(sqrtf(s), 1e-12f);
    kk[base+lane]    = kk0*inv;
    kk[base+lane+32] = kk1*inv;
    float a0 = a[base+lane], a1 = a[base+lane+32];
    k[base+lane]    = k0*(1.0f + (a0-1.0f)*k_a[c0]);
    k[base+lane+32] = k1*(1.0f + (a1-1.0f)*k_a[c1]);
}

// ---------------------------------------------------------------------------
// WKV7 scan (one block per (b,h), 64 threads, register-prefetched) — R5 exact
// ---------------------------------------------------------------------------
__global__ __launch_bounds__(64)
void wkv_kernel(const float* __restrict__ r, const float* __restrict__ wd,
                const float* __restrict__ k, const float* __restrict__ v,
                const float* __restrict__ kkp, const float* __restrict__ ap,
                float* __restrict__ y)
{
    int bh = blockIdx.x;
    int b = bh >> 5;
    int h = bh & 31;
    int i = threadIdx.x;
    __shared__ __align__(16) float sr[64], sw[64], sk[64], sa[64], sb[64];
    float st[64];
    #pragma unroll
    for (int j=0;j<64;j++) st[j]=0.f;
    size_t base = ((size_t)b*Tq)*Cq + (size_t)h*HSq;

    size_t o = base;
    float rv=r[o+i], wv=wd[o+i], kv=k[o+i], kkv=kkp[o+i], av=ap[o+i], vv=v[o+i];

    for (int t=0; t<Tq; t++) {
        sr[i]=rv; sw[i]=wv; sk[i]=kv; sa[i]=-kkv; sb[i]=kkv*av;
        float vcur = vv;
        __syncthreads();

        size_t on = o + Cq;
        if (t+1 < Tq){
            rv=r[on+i]; wv=wd[on+i]; kv=k[on+i]; kkv=kkp[on+i]; av=ap[on+i]; vv=v[on+i];
        }

        float s0=0,s1=0,s2=0,s3=0;
        const float4* A4 = (const float4*)sa;
        #pragma unroll
        for (int j=0;j<16;j++) {
            float4 a4 = A4[j];
            s0 += st[4*j+0]*a4.x; s1 += st[4*j+1]*a4.y;
            s2 += st[4*j+2]*a4.z; s3 += st[4*j+3]*a4.w;
        }
        float sav = (s0+s1)+(s2+s3);

        const float4* W4=(const float4*)sw; const float4* K4=(const float4*)sk;
        const float4* B4=(const float4*)sb; const float4* R4=(const float4*)sr;
        float o0=0,o1=0,o2=0,o3=0;
        #pragma unroll
        for (int j=0;j<16;j++) {
            float4 w4=W4[j], k4=K4[j], b4=B4[j], r4=R4[j];
            float t0 = st[4*j+0]*w4.x + vcur*k4.x + sav*b4.x;
            float t1 = st[4*j+1]*w4.y + vcur*k4.y + sav*b4.y;
            float t2 = st[4*j+2]*w4.z + vcur*k4.z + sav*b4.z;
            float t3 = st[4*j+3]*w4.w + vcur*k4.w + sav*b4.w;
            st[4*j+0]=t0; st[4*j+1]=t1; st[4*j+2]=t2; st[4*j+3]=t3;
            o0 += t0*r4.x; o1 += t1*r4.y; o2 += t2*r4.z; o3 += t3*r4.w;
        }
        y[o+i] = (o0+o1)+(o2+o3);
        o = on;
        __syncthreads();
    }
}

// ---------------------------------------------------------------------------
// GroupNorm + bonus + gate -> z (fp16 for Wo gemm)
// ---------------------------------------------------------------------------
__global__ void gn_kernel(const float* __restrict__ y, const float* __restrict__ r,
                          const float* __restrict__ k, const float* __restrict__ v,
                          const float* __restrict__ g,
                          const float* __restrict__ lnw, const float* __restrict__ lnb,
                          const float* __restrict__ r_k, __half* __restrict__ z)
{
    int gw   = blockIdx.x*8 + (threadIdx.x>>5);
    int lane = threadIdx.x & 31;
    int m = gw >> 5;
    int h = gw & 31;
    size_t base = (size_t)m*Cq + h*HSq;
    int c0 = h*HSq + lane, c1 = c0 + 32;
    float y0=y[base+lane], y1=y[base+lane+32];
    float r0=r[base+lane], r1=r[base+lane+32];
    float k0=k[base+lane], k1=k[base+lane+32];
    float sum = y0+y1;
    float sq  = y0*y0 + y1*y1;
    float dot = r0*k0*r_k[c0] + r1*k1*r_k[c1];
    #pragma unroll
    for (int off=16; off; off>>=1) {
        sum += __shfl_xor_sync(0xffffffffu, sum, off);
        sq  += __shfl_xor_sync(0xffffffffu, sq , off);
        dot += __shfl_xor_sync(0xffffffffu, dot, off);
    }
    float mean = sum * (1.0f/64.0f);
    float var  = sq * (1.0f/64.0f) - mean*mean;
    float inv  = rsqrtf(var + EPS_GN);
    float v0=v[base+lane], v1=v[base+lane+32];
    float g0=g[base+lane], g1=g[base+lane+32];
    float z0 = ((y0-mean)*inv*lnw[c0] + lnb[c0] + dot*v0) * g0;
    float z1 = ((y1-mean)*inv*lnw[c1] + lnb[c1] + dot*v1) * g1;
    z[base+lane]    = __float2half_rn(z0);
    z[base+lane+32] = __float2half_rn(z1);
}

// ---------------------------------------------------------------------------
// Host helpers
// ---------------------------------------------------------------------------
template<int EPI,int RND>
static void rg(const __half* A, const __half* Bw, void* C, int Nd, int Kd,
               const float* bias, const float* vold, const float* vfirst)
{
    cudaFuncSetAttribute(gemm_h<EPI,RND>, cudaFuncAttributeMaxDynamicSharedMemorySize,
                         GSTAGES*STAGE_BYTES);
    dim3 grid((Nd+127)/128, Mq/128);
    gemm_h<EPI,RND><<<grid, 256, GSTAGES*STAGE_BYTES>>>(A, Bw, C, Nd, Kd, bias, vold, vfirst);
}

// ---------------------------------------------------------------------------
// Launch
// ---------------------------------------------------------------------------
extern "C" void kernel_launch(void* const* d_in, const int* in_sizes, int n_in,
                              void* d_out, int out_size)
{
    const float* x       = (const float*)d_in[0];
    const float* v_first = (const float*)d_in[1];
    const float* x_r = (const float*)d_in[2];
    const float* x_w = (const float*)d_in[3];
    const float* x_k = (const float*)d_in[4];
    const float* x_v = (const float*)d_in[5];
    const float* x_a = (const float*)d_in[6];
    const float* x_g = (const float*)d_in[7];
    const float* w0  = (const float*)d_in[8];
    const float* w1  = (const float*)d_in[9];
    const float* w2  = (const float*)d_in[10];
    const float* a0  = (const float*)d_in[11];
    const float* a1  = (const float*)d_in[12];
    const float* a2  = (const float*)d_in[13];
    const float* v0  = (const float*)d_in[14];
    const float* v1  = (const float*)d_in[15];
    const float* v2  = (const float*)d_in[16];
    const float* g1  = (const float*)d_in[17];
    const float* g2  = (const float*)d_in[18];
    const float* k_k = (const float*)d_in[19];
    const float* k_a = (const float*)d_in[20];
    const float* r_k = (const float*)d_in[21];
    const float* Wr  = (const float*)d_in[22];
    const float* Wk  = (const float*)d_in[23];
    const float* Wv  = (const float*)d_in[24];
    const float* Wo  = (const float*)d_in[25];
    const float* lnw = (const float*)d_in[26];
    const float* lnb = (const float*)d_in[27];
    float* out = (float*)d_out;

    __half *xr,*xw,*xk,*xv,*xa,*xg,*zh,*Wrh,*Wkh,*Wvh,*Woh;
    __half *w1h,*w2h,*a1h,*a2h,*v1h,*v2h,*g1h,*g2h,*twh,*tah,*tvh,*tgh;
    float *rB,*kB,*vB,*dec,*aB,*gB,*kkB,*yB;
    cudaGetSymbolAddress((void**)&xr , h_xr);
    cudaGetSymbolAddress((void**)&xw , h_xw);
    cudaGetSymbolAddress((void**)&xk , h_xk);
    cudaGetSymbolAddress((void**)&xv , h_xv);
    cudaGetSymbolAddress((void**)&xa , h_xa);
    cudaGetSymbolAddress((void**)&xg , h_xg);
    cudaGetSymbolAddress((void**)&zh , h_z);
    cudaGetSymbolAddress((void**)&Wrh, h_Wr);
    cudaGetSymbolAddress((void**)&Wkh, h_Wk);
    cudaGetSymbolAddress((void**)&Wvh, h_Wv);
    cudaGetSymbolAddress((void**)&Woh, h_Wo);
    cudaGetSymbolAddress((void**)&w1h, h_w1);
    cudaGetSymbolAddress((void**)&w2h, h_w2);
    cudaGetSymbolAddress((void**)&a1h, h_a1);
    cudaGetSymbolAddress((void**)&a2h, h_a2);
    cudaGetSymbolAddress((void**)&v1h, h_v1);
    cudaGetSymbolAddress((void**)&v2h, h_v2);
    cudaGetSymbolAddress((void**)&g1h, h_g1);
    cudaGetSymbolAddress((void**)&g2h, h_g2);
    cudaGetSymbolAddress((void**)&twh, h_tw);
    cudaGetSymbolAddress((void**)&tah, h_ta);
    cudaGetSymbolAddress((void**)&tvh, h_tv);
    cudaGetSymbolAddress((void**)&tgh, h_tg);
    cudaGetSymbolAddress((void**)&rB , g_r);
    cudaGetSymbolAddress((void**)&kB , g_k);
    cudaGetSymbolAddress((void**)&vB , g_v);
    cudaGetSymbolAddress((void**)&dec, g_dec);
    cudaGetSymbolAddress((void**)&aB , g_a);
    cudaGetSymbolAddress((void**)&gB , g_g);
    cudaGetSymbolAddress((void**)&kkB, g_kk);
    cudaGetSymbolAddress((void**)&yB , g_y);

    // big weights f32->f16 (one launch)
    f2h4_kernel<<<dim3((unsigned)(((size_t)Cq*Cq/4 + 255)/256), 4), 256>>>(
        Wr, Wrh, Wk, Wkh, Wv, Wvh, Wo, Woh, (size_t)Cq*Cq/4);

    // lora weight transposes (one launch)
    transpose8<<<dim3(64, 64, 8), dim3(32,8)>>>(w1, w1h, w2, w2h, a1, a1h, a2, a2h,
                                                v1, v1h, v2, v2h, g1, g1h, g2, g2h);

    // token-shift mixes -> fp16
    mix_kernel<<<(unsigned)((BTC/4 + 255)/256), 256>>>(x, x_r,x_w,x_k,x_v,x_a,x_g,
                                                       xr,xw,xk,xv,xa,xg);

    // big projections r/k/v (separate, as in R5)
    rg<0,0>(xr, Wrh, rB, Cq, Cq, nullptr,nullptr,nullptr);
    rg<0,0>(xk, Wkh, kB, Cq, Cq, nullptr,nullptr,nullptr);
    rg<0,0>(xv, Wvh, vB, Cq, Cq, nullptr,nullptr,nullptr);

    // lora up-projections (one launch, 256 CTAs)
    cudaFuncSetAttribute(gemm_lora4, cudaFuncAttributeMaxDynamicSharedMemorySize,
                         GSTAGES*STAGE_BYTES);
    gemm_lora4<<<dim3(2, Mq/128, 4), 256, GSTAGES*STAGE_BYTES>>>(
        xw, w1h, twh, xa, a1h, tah, xv, v1h, tvh, xg, g1h, tgh);

    // lora down-projections (fp32 + epilogue)
    rg<3,0>(twh, w2h, dec, Cq, DW, w0, nullptr,nullptr);
    rg<4,0>(tah, a2h, aB, Cq, DA, a0, nullptr,nullptr);
    rg<5,0>(tvh, v2h, vB, Cq, DV, v0, vB, v_first);
    rg<0,0>(tgh, g2h, gB, Cq, DG, nullptr,nullptr,nullptr);

    // kk normalize + k transform
    kk_kernel<<<Mq*Hq/8, 256>>>(kB, aB, k_k, k_a, kkB);

    // WKV7 scan (64 threads/block, R5 exact)
    wkv_kernel<<<Bq*Hq, 64>>>(rB, dec, kB, vB, kkB, aB, yB);

    // GroupNorm + bonus + gate -> fp16 z
    gn_kernel<<<Mq*Hq/8, 256>>>(yB, rB, kB, vB, gB, lnw, lnb, r_k, zh);

    // output projection
    rg<0,0>(zh, Woh, out, Cq, Cq, nullptr,nullptr,nullptr);
}

// round 9
// speedup vs baseline: 1.3264x; 1.0280x over previous
#include <cuda_runtime.h>
#include <cuda_fp16.h>
#include <math.h>
#include <stdint.h>

// Problem constants
#define Bq 4
#define Tq 2048
#define Cq 2048
#define Hq 32
#define HSq 64
#define Mq (Bq*Tq)            // 8192 tokens
#define DW 128
#define DA 128
#define DG 224
#define DV 64
#define EPS_GN 0.00064f

// ---------------------------------------------------------------------------
// Scratch (static device globals; zero-initialized at module load)
// ---------------------------------------------------------------------------
#define BTC ((size_t)Mq*Cq)
__device__ __half h_xr[BTC];
__device__ __half h_xw[BTC];
__device__ __half h_xk[BTC];
__device__ __half h_xv[BTC];
__device__ __half h_xa[BTC];
__device__ __half h_xg[BTC];
__device__ __half h_z [BTC];
__device__ __half h_Wr[(size_t)Cq*Cq];
__device__ __half h_Wk[(size_t)Cq*Cq];
__device__ __half h_Wv[(size_t)Cq*Cq];
__device__ __half h_Wo[(size_t)Cq*Cq];
__device__ __half h_w1[(size_t)128*Cq];   // [DW pad128][C]
__device__ __half h_w2[(size_t)Cq*DW];    // [C][DW]
__device__ __half h_a1[(size_t)128*Cq];
__device__ __half h_a2[(size_t)Cq*DA];
__device__ __half h_v1[(size_t)128*Cq];   // [DV pad128][C]
__device__ __half h_v2[(size_t)Cq*DV];
__device__ __half h_g1[(size_t)256*Cq];   // [DG pad256][C]
__device__ __half h_g2[(size_t)Cq*DG];
__device__ __half h_tw[(size_t)Mq*DW];
__device__ __half h_ta[(size_t)Mq*DA];
__device__ __half h_tv[(size_t)Mq*DV];
__device__ __half h_tg[(size_t)Mq*DG];
// fp32 intermediates
__device__ float g_r [BTC];
__device__ float g_k [BTC];
__device__ float g_v [BTC];
__device__ float g_dec[BTC];
__device__ float g_a [BTC];
__device__ float g_g [BTC];
__device__ float g_kk[BTC];
__device__ float g_y [BTC];

__device__ __forceinline__ float sigmoidf_(float x){ return 1.0f/(1.0f+expf(-x)); }

__device__ __forceinline__ void cpa16(uint32_t s, const void* g){
    asm volatile("cp.async.cg.shared.global [%0], [%1], 16;\n" :: "r"(s), "l"(g));
}
__device__ __forceinline__ void ldsm_x4(uint32_t* r, uint32_t addr){
    asm volatile("ldmatrix.sync.aligned.m8n8.x4.shared.b16 {%0,%1,%2,%3}, [%4];"
        : "=r"(r[0]),"=r"(r[1]),"=r"(r[2]),"=r"(r[3]) : "r"(addr));
}
__device__ __forceinline__ void mma16(float* c, const uint32_t* a, const uint32_t* b){
    asm volatile("mma.sync.aligned.m16n8k16.row.col.f32.f16.f16.f32 "
        "{%0,%1,%2,%3},{%4,%5,%6,%7},{%8,%9},{%0,%1,%2,%3};\n"
        : "+f"(c[0]),"+f"(c[1]),"+f"(c[2]),"+f"(c[3])
        : "r"(a[0]),"r"(a[1]),"r"(a[2]),"r"(a[3]),"r"(b[0]),"r"(b[1]));
}

// ---------------------------------------------------------------------------
// Prep: 4x f32->f16 weight copies in ONE launch (blockIdx.y selects)
// ---------------------------------------------------------------------------
__global__ void f2h4_kernel(const float* __restrict__ i0, __half* __restrict__ o0,
                            const float* __restrict__ i1, __half* __restrict__ o1,
                            const float* __restrict__ i2, __half* __restrict__ o2,
                            const float* __restrict__ i3, __half* __restrict__ o3,
                            size_t n4)
{
    size_t i = (size_t)blockIdx.x*blockDim.x + threadIdx.x;
    if (i >= n4) return;
    const float* in = (blockIdx.y==0)?i0:(blockIdx.y==1)?i1:(blockIdx.y==2)?i2:i3;
    __half* out     = (blockIdx.y==0)?o0:(blockIdx.y==1)?o1:(blockIdx.y==2)?o2:o3;
    float4 v = ((const float4*)in)[i];
    ((__half2*)out)[i*2  ] = __floats2half2_rn(v.x, v.y);
    ((__half2*)out)[i*2+1] = __floats2half2_rn(v.z, v.w);
}

// ---------------------------------------------------------------------------
// 8 lora-weight transposes (f32[R][C] -> f16[C][R]) in ONE launch (blockIdx.z)
// ---------------------------------------------------------------------------
__device__ __forceinline__
void transpose_body(const float* __restrict__ in, __half* __restrict__ out, int R, int C)
{
    __shared__ float tile[32][33];
    int cb = blockIdx.x*32, rb = blockIdx.y*32;
    if (cb >= C || rb >= R) return;
    int c = cb + threadIdx.x;
    #pragma unroll
    for (int i=threadIdx.y; i<32; i+=8){
        int r = rb + i;
        if (r<R && c<C) tile[i][threadIdx.x] = in[(size_t)r*C + c];
    }
    __syncthreads();
    int r2 = rb + threadIdx.x;
    #pragma unroll
    for (int i=threadIdx.y; i<32; i+=8){
        int c2 = cb + i;
        if (r2<R && c2<C) out[(size_t)c2*R + r2] = __float2half_rn(tile[threadIdx.x][i]);
    }
}

__global__ void transpose8(const float* w1, __half* w1h, const float* w2, __half* w2h,
                           const float* a1, __half* a1h, const float* a2, __half* a2h,
                           const float* v1, __half* v1h, const float* v2, __half* v2h,
                           const float* g1, __half* g1h, const float* g2, __half* g2h)
{
    switch(blockIdx.z){
        case 0: transpose_body(w1, w1h, Cq, DW); break;
        case 1: transpose_body(w2, w2h, DW, Cq); break;
        case 2: transpose_body(a1, a1h, Cq, DA); break;
        case 3: transpose_body(a2, a2h, DA, Cq); break;
        case 4: transpose_body(v1, v1h, Cq, DV); break;
        case 5: transpose_body(v2, v2h, DV, Cq); break;
        case 6: transpose_body(g1, g1h, Cq, DG); break;
        default: transpose_body(g2, g2h, DG, Cq); break;
    }
}

// ---------------------------------------------------------------------------
// Token-shift mix -> fp16 outputs
// ---------------------------------------------------------------------------
__global__ void mix_kernel(const float* __restrict__ x,
                           const float* __restrict__ cr, const float* __restrict__ cw,
                           const float* __restrict__ ck, const float* __restrict__ cv,
                           const float* __restrict__ ca, const float* __restrict__ cg,
                           __half* __restrict__ xr, __half* __restrict__ xw,
                           __half* __restrict__ xk, __half* __restrict__ xv,
                           __half* __restrict__ xa, __half* __restrict__ xg)
{
    size_t i4 = (size_t)blockIdx.x*blockDim.x + threadIdx.x;
    size_t n4 = BTC/4;
    if (i4 >= n4) return;
    size_t flat = i4*4;
    int tok = (int)(flat / Cq);
    int t   = tok % Tq;
    const float4* x4 = (const float4*)x;
    float4 xc = x4[i4];
    float4 xp = (t==0) ? make_float4(0,0,0,0) : x4[i4 - Cq/4];
    float4 dx = make_float4(xp.x-xc.x, xp.y-xc.y, xp.z-xc.z, xp.w-xc.w);
    size_t c4 = i4 % (Cq/4);
    #define MIX1(COEF, OUT) { \
        float4 cf = ((const float4*)COEF)[c4]; \
        ((__half2*)OUT)[i4*2  ] = __floats2half2_rn(xc.x + dx.x*cf.x, xc.y + dx.y*cf.y); \
        ((__half2*)OUT)[i4*2+1] = __floats2half2_rn(xc.z + dx.z*cf.z, xc.w + dx.w*cf.w); }
    MIX1(cr, xr) MIX1(cw, xw) MIX1(ck, xk) MIX1(cv, xv) MIX1(ca, xa) MIX1(cg, xg)
    #undef MIX1
}

// ---------------------------------------------------------------------------
// Epilogue transform: 0 none, 1 tanh, 2 sigmoid, 3 w->decay, 4 a-sigm, 5 v-mix
// ---------------------------------------------------------------------------
template<int EPI>
__device__ __forceinline__ float epi_val(float val, int m, int n, int Nd,
                                         const float* __restrict__ bias,
                                         const float* __restrict__ vold,
                                         const float* __restrict__ vfirst)
{
    if (EPI==1) { val = tanhf(val); }
    else if (EPI==2) { val = sigmoidf_(val); }
    else if (EPI==3) {
        float w = bias[n] + val;
        float mneg = -w;
        float sp = fmaxf(mneg,0.f) + log1pf(expf(-fabsf(mneg)));
        float wl = -sp - 0.5f;
        val = expf(-expf(wl));
    }
    else if (EPI==4) { val = sigmoidf_(bias[n] + val); }
    else if (EPI==5) {
        float s  = sigmoidf_(bias[n] + val);
        size_t idx = (size_t)m*Nd + n;
        float vo = vold[idx];
        val = vo + (vfirst[idx] - vo)*s;
    }
    return val;
}

// ---------------------------------------------------------------------------
// fp16 tensor-core GEMM body: C[m,n] = sum_k A[m,k] * B[n,k]
// CTA 128x128, BK=32, 4-stage cp.async ring with ONE __syncthreads per slab:
//   wait_group(2) -> barrier -> issue loads for s+3 -> compute(s)
// (loads at iter s write buf (s-1)&3 whose readers finished before the barrier)
// ---------------------------------------------------------------------------
#define GSTAGES 4
#define STAGE_HB 10240           // bytes: 128 rows * 40 halves * 2B
#define STAGE_BYTES (2*STAGE_HB)

template<int EPI,int RND>
__device__ __forceinline__
void gemm_body(const __half* __restrict__ A, const __half* __restrict__ Bw,
               void* __restrict__ Cm, int Nd, int Kd,
               const float* __restrict__ bias,
               const float* __restrict__ vold, const float* __restrict__ vfirst)
{
    extern __shared__ __align__(128) char smc[];
    const int tid = threadIdx.x;
    const int lane = tid&31, warp = tid>>5;
    const int bm = blockIdx.y*128, bn = blockIdx.x*128;
    const int wm = (warp&1)*64, wn = (warp>>1)*32;
    const int g = lane>>2, tig = lane&3;
    const uint32_t sbase = (uint32_t)__cvta_generic_to_shared(smc);

    const int arow = wm + (lane&7) + ((lane>>3)&1)*8;   // + mt*16
    const int akof = (lane>>4)*8;
    const int brow = wn + (lane&7) + (lane>>4)*8;       // + p*16
    const int bkof = ((lane>>3)&1)*8;

    float acc[4][4][4];
    #pragma unroll
    for (int i=0;i<4;i++)
        #pragma unroll
        for (int j=0;j<4;j++)
            #pragma unroll
            for (int q=0;q<4;q++) acc[i][j][q]=0.f;

    const int NS = Kd >> 5;

    auto loadSlab = [&](int s, int st){
        const uint32_t sb = sbase + st*STAGE_BYTES;
        const int k0 = s*32;
        #pragma unroll
        for (int i=0;i<2;i++){
            int id  = tid + i*256;
            int row = id>>2, c16 = id&3;
            cpa16(sb + row*80 + c16*16,
                  &A[(size_t)(bm+row)*Kd + k0 + c16*8]);
            cpa16(sb + STAGE_HB + row*80 + c16*16,
                  &Bw[(size_t)(bn+row)*Kd + k0 + c16*8]);
        }
    };
    auto compute = [&](int st){
        const uint32_t sb = sbase + st*STAGE_BYTES;
        #pragma unroll
        for (int ks=0; ks<2; ks++){
            uint32_t af[4][4], bf[2][4];
            #pragma unroll
            for (int mt=0;mt<4;mt++)
                ldsm_x4(af[mt], sb + ((arow+mt*16)*40 + akof + ks*16)*2);
            #pragma unroll
            for (int p=0;p<2;p++)
                ldsm_x4(bf[p], sb + STAGE_HB + ((brow+p*16)*40 + bkof + ks*16)*2);
            #pragma unroll
            for (int mt=0;mt<4;mt++)
                #pragma unroll
                for (int nt=0;nt<4;nt++)
                    mma16(acc[mt][nt], af[mt], &bf[nt>>1][(nt&1)*2]);
        }
    };

    #pragma unroll
    for (int i=0;i<GSTAGES-1;i++){
        if (i<NS) loadSlab(i,i);
        asm volatile("cp.async.commit_group;\n");
    }
    for (int s=0;s<NS;s++){
        asm volatile("cp.async.wait_group %0;\n" :: "n"(GSTAGES-2));
        __syncthreads();
        int ld = s + GSTAGES-1;
        if (ld < NS) loadSlab(ld, ld&3);
        asm volatile("cp.async.commit_group;\n");
        compute(s&3);
    }

    #pragma unroll
    for (int mt=0;mt<4;mt++){
        int r0 = bm + wm + mt*16 + g;
        #pragma unroll
        for (int nt=0;nt<4;nt++){
            int n0 = bn + wn + nt*8 + tig*2;
            if (n0 < Nd){
                float* c = acc[mt][nt];
                float v00 = epi_val<EPI>(c[0], r0,   n0,   Nd, bias, vold, vfirst);
                float v01 = epi_val<EPI>(c[1], r0,   n0+1, Nd, bias, vold, vfirst);
                float v10 = epi_val<EPI>(c[2], r0+8, n0,   Nd, bias, vold, vfirst);
                float v11 = epi_val<EPI>(c[3], r0+8, n0+1, Nd, bias, vold, vfirst);
                if (RND){
                    __half* O = (__half*)Cm;
                    *(__half2*)&O[(size_t)r0*Nd + n0]     = __floats2half2_rn(v00, v01);
                    *(__half2*)&O[(size_t)(r0+8)*Nd + n0] = __floats2half2_rn(v10, v11);
                } else {
                    float* O = (float*)Cm;
                    *(float2*)&O[(size_t)r0*Nd + n0]     = make_float2(v00, v01);
                    *(float2*)&O[(size_t)(r0+8)*Nd + n0] = make_float2(v10, v11);
                }
            }
        }
    }
}

template<int EPI,int RND>
__global__ __launch_bounds__(256,2)
void gemm_h(const __half* __restrict__ A, const __half* __restrict__ Bw,
            void* __restrict__ Cm, int Nd, int Kd,
            const float* __restrict__ bias,
            const float* __restrict__ vold, const float* __restrict__ vfirst)
{
    gemm_body<EPI,RND>(A, Bw, Cm, Nd, Kd, bias, vold, vfirst);
}

// 4 lora up-projections in ONE launch (blockIdx.z selects; uniform per block)
__global__ __launch_bounds__(256,2)
void gemm_lora4(const __half* __restrict__ xw, const __half* __restrict__ w1h, __half* __restrict__ tw,
                const __half* __restrict__ xa, const __half* __restrict__ a1h, __half* __restrict__ ta,
                const __half* __restrict__ xv, const __half* __restrict__ v1h, __half* __restrict__ tv,
                const __half* __restrict__ xg, const __half* __restrict__ g1h, __half* __restrict__ tg)
{
    const int bn = blockIdx.x*128;
    switch(blockIdx.z){
        case 0: if (bn >= DW) return; gemm_body<1,1>(xw, w1h, (void*)tw, DW, Cq, nullptr,nullptr,nullptr); break;
        case 1: if (bn >= DA) return; gemm_body<0,1>(xa, a1h, (void*)ta, DA, Cq, nullptr,nullptr,nullptr); break;
        case 2: if (bn >= DV) return; gemm_body<0,1>(xv, v1h, (void*)tv, DV, Cq, nullptr,nullptr,nullptr); break;
        default:                      gemm_body<2,1>(xg, g1h, (void*)tg, DG, Cq, nullptr,nullptr,nullptr); break;
    }
}

// 4 lora down-projections in ONE launch (blockIdx.z selects; uniform per block)
__global__ __launch_bounds__(256,2)
void gemm_lorad4(const __half* __restrict__ twh, const __half* __restrict__ w2h, float* __restrict__ dec, const float* __restrict__ w0,
                 const __half* __restrict__ tah, const __half* __restrict__ a2h, float* __restrict__ aB,  const float* __restrict__ a0,
                 const __half* __restrict__ tvh, const __half* __restrict__ v2h, float* __restrict__ vB,  const float* __restrict__ v0,
                 const float* __restrict__ vfirst,
                 const __half* __restrict__ tgh, const __half* __restrict__ g2h, float* __restrict__ gB)
{
    switch(blockIdx.z){
        case 0: gemm_body<3,0>(twh, w2h, (void*)dec, Cq, DW, w0, nullptr, nullptr); break;
        case 1: gemm_body<4,0>(tah, a2h, (void*)aB,  Cq, DA, a0, nullptr, nullptr); break;
        case 2: gemm_body<5,0>(tvh, v2h, (void*)vB,  Cq, DV, v0, vB, vfirst);       break;
        default: gemm_body<0,0>(tgh, g2h, (void*)gB, Cq, DG, nullptr, nullptr, nullptr); break;
    }
}

// ---------------------------------------------------------------------------
// kk normalize + k transform
// ---------------------------------------------------------------------------
__global__ void kk_kernel(float* __restrict__ k, const float* __restrict__ a,
                          const float* __restrict__ k_k, const float* __restrict__ k_a,
                          float* __restrict__ kk)
{
    int gw   = blockIdx.x*8 + (threadIdx.x>>5);
    int lane = threadIdx.x & 31;
    int m = gw >> 5;
    int h = gw & 31;
    size_t base = (size_t)m*Cq + h*HSq;
    int c0 = h*HSq + lane, c1 = c0 + 32;
    float k0 = k[base+lane], k1 = k[base+lane+32];
    float kk0 = k0*k_k[c0], kk1 = k1*k_k[c1];
    float s = kk0*kk0 + kk1*kk1;
    #pragma unroll
    for (int off=16; off; off>>=1) s += __shfl_xor_sync(0xffffffffu, s, off);
    float inv = 1.0f / fmaxf(sqrtf(s), 1e-12f);
    kk[base+lane]    = kk0*inv;
    kk[base+lane+32] = kk1*inv;
    float a0 = a[base+lane], a1 = a[base+lane+32];
    k[base+lane]    = k0*(1.0f + (a0-1.0f)*k_a[c0]);
    k[base+lane+32] = k1*(1.0f + (a1-1.0f)*k_a[c1]);
}

// ---------------------------------------------------------------------------
// WKV7 scan (one block per (b,h), 64 threads, register-prefetched) — R5 exact
// ---------------------------------------------------------------------------
__global__ __launch_bounds__(64)
void wkv_kernel(const float* __restrict__ r, const float* __restrict__ wd,
                const float* __restrict__ k, const float* __restrict__ v,
                const float* __restrict__ kkp, const float* __restrict__ ap,
                float* __restrict__ y)
{
    int bh = blockIdx.x;
    int b = bh >> 5;
    int h = bh & 31;
    int i = threadIdx.x;
    __shared__ __align__(16) float sr[64], sw[64], sk[64], sa[64], sb[64];
    float st[64];
    #pragma unroll
    for (int j=0;j<64;j++) st[j]=0.f;
    size_t base = ((size_t)b*Tq)*Cq + (size_t)h*HSq;

    size_t o = base;
    float rv=r[o+i], wv=wd[o+i], kv=k[o+i], kkv=kkp[o+i], av=ap[o+i], vv=v[o+i];

    for (int t=0; t<Tq; t++) {
        sr[i]=rv; sw[i]=wv; sk[i]=kv; sa[i]=-kkv; sb[i]=kkv*av;
        float vcur = vv;
        __syncthreads();

        size_t on = o + Cq;
        if (t+1 < Tq){
            rv=r[on+i]; wv=wd[on+i]; kv=k[on+i]; kkv=kkp[on+i]; av=ap[on+i]; vv=v[on+i];
        }

        float s0=0,s1=0,s2=0,s3=0;
        const float4* A4 = (const float4*)sa;
        #pragma unroll
        for (int j=0;j<16;j++) {
            float4 a4 = A4[j];
            s0 += st[4*j+0]*a4.x; s1 += st[4*j+1]*a4.y;
            s2 += st[4*j+2]*a4.z; s3 += st[4*j+3]*a4.w;
        }
        float sav = (s0+s1)+(s2+s3);

        const float4* W4=(const float4*)sw; const float4* K4=(const float4*)sk;
        const float4* B4=(const float4*)sb; const float4* R4=(const float4*)sr;
        float o0=0,o1=0,o2=0,o3=0;
        #pragma unroll
        for (int j=0;j<16;j++) {
            float4 w4=W4[j], k4=K4[j], b4=B4[j], r4=R4[j];
            float t0 = st[4*j+0]*w4.x + vcur*k4.x + sav*b4.x;
            float t1 = st[4*j+1]*w4.y + vcur*k4.y + sav*b4.y;
            float t2 = st[4*j+2]*w4.z + vcur*k4.z + sav*b4.z;
            float t3 = st[4*j+3]*w4.w + vcur*k4.w + sav*b4.w;
            st[4*j+0]=t0; st[4*j+1]=t1; st[4*j+2]=t2; st[4*j+3]=t3;
            o0 += t0*r4.x; o1 += t1*r4.y; o2 += t2*r4.z; o3 += t3*r4.w;
        }
        y[o+i] = (o0+o1)+(o2+o3);
        o = on;
        __syncthreads();
    }
}

// ---------------------------------------------------------------------------
// GroupNorm + bonus + gate -> z (fp16 for Wo gemm)
// ---------------------------------------------------------------------------
__global__ void gn_kernel(const float* __restrict__ y, const float* __restrict__ r,
                          const float* __restrict__ k, const float* __restrict__ v,
                          const float* __restrict__ g,
                          const float* __restrict__ lnw, const float* __restrict__ lnb,
                          const float* __restrict__ r_k, __half* __restrict__ z)
{
    int gw   = blockIdx.x*8 + (threadIdx.x>>5);
    int lane = threadIdx.x & 31;
    int m = gw >> 5;
    int h = gw & 31;
    size_t base = (size_t)m*Cq + h*HSq;
    int c0 = h*HSq + lane, c1 = c0 + 32;
    float y0=y[base+lane], y1=y[base+lane+32];
    float r0=r[base+lane], r1=r[base+lane+32];
    float k0=k[base+lane], k1=k[base+lane+32];
    float sum = y0+y1;
    float sq  = y0*y0 + y1*y1;
    float dot = r0*k0*r_k[c0] + r1*k1*r_k[c1];
    #pragma unroll
    for (int off=16; off; off>>=1) {
        sum += __shfl_xor_sync(0xffffffffu, sum, off);
        sq  += __shfl_xor_sync(0xffffffffu, sq , off);
        dot += __shfl_xor_sync(0xffffffffu, dot, off);
    }
    float mean = sum * (1.0f/64.0f);
    float var  = sq * (1.0f/64.0f) - mean*mean;
    float inv  = rsqrtf(var + EPS_GN);
    float v0=v[base+lane], v1=v[base+lane+32];
    float g0=g[base+lane], g1=g[base+lane+32];
    float z0 = ((y0-mean)*inv*lnw[c0] + lnb[c0] + dot*v0) * g0;
    float z1 = ((y1-mean)*inv*lnw[c1] + lnb[c1] + dot*v1) * g1;
    z[base+lane]    = __float2half_rn(z0);
    z[base+lane+32] = __float2half_rn(z1);
}

// ---------------------------------------------------------------------------
// Host helpers
// ---------------------------------------------------------------------------
template<int EPI,int RND>
static void rg(const __half* A, const __half* Bw, void* C, int Nd, int Kd,
               const float* bias, const float* vold, const float* vfirst)
{
    cudaFuncSetAttribute(gemm_h<EPI,RND>, cudaFuncAttributeMaxDynamicSharedMemorySize,
                         GSTAGES*STAGE_BYTES);
    dim3 grid((Nd+127)/128, Mq/128);
    gemm_h<EPI,RND><<<grid, 256, GSTAGES*STAGE_BYTES>>>(A, Bw, C, Nd, Kd, bias, vold, vfirst);
}

// ---------------------------------------------------------------------------
// Launch
// ---------------------------------------------------------------------------
extern "C" void kernel_launch(void* const* d_in, const int* in_sizes, int n_in,
                              void* d_out, int out_size)
{
    const float* x       = (const float*)d_in[0];
    const float* v_first = (const float*)d_in[1];
    const float* x_r = (const float*)d_in[2];
    const float* x_w = (const float*)d_in[3];
    const float* x_k = (const float*)d_in[4];
    const float* x_v = (const float*)d_in[5];
    const float* x_a = (const float*)d_in[6];
    const float* x_g = (const float*)d_in[7];
    const float* w0  = (const float*)d_in[8];
    const float* w1  = (const float*)d_in[9];
    const float* w2  = (const float*)d_in[10];
    const float* a0  = (const float*)d_in[11];
    const float* a1  = (const float*)d_in[12];
    const float* a2  = (const float*)d_in[13];
    const float* v0  = (const float*)d_in[14];
    const float* v1  = (const float*)d_in[15];
    const float* v2  = (const float*)d_in[16];
    const float* g1  = (const float*)d_in[17];
    const float* g2  = (const float*)d_in[18];
    const float* k_k = (const float*)d_in[19];
    const float* k_a = (const float*)d_in[20];
    const float* r_k = (const float*)d_in[21];
    const float* Wr  = (const float*)d_in[22];
    const float* Wk  = (const float*)d_in[23];
    const float* Wv  = (const float*)d_in[24];
    const float* Wo  = (const float*)d_in[25];
    const float* lnw = (const float*)d_in[26];
    const float* lnb = (const float*)d_in[27];
    float* out = (float*)d_out;

    __half *xr,*xw,*xk,*xv,*xa,*xg,*zh,*Wrh,*Wkh,*Wvh,*Woh;
    __half *w1h,*w2h,*a1h,*a2h,*v1h,*v2h,*g1h,*g2h,*twh,*tah,*tvh,*tgh;
    float *rB,*kB,*vB,*dec,*aB,*gB,*kkB,*yB;
    cudaGetSymbolAddress((void**)&xr , h_xr);
    cudaGetSymbolAddress((void**)&xw , h_xw);
    cudaGetSymbolAddress((void**)&xk , h_xk);
    cudaGetSymbolAddress((void**)&xv , h_xv);
    cudaGetSymbolAddress((void**)&xa , h_xa);
    cudaGetSymbolAddress((void**)&xg , h_xg);
    cudaGetSymbolAddress((void**)&zh , h_z);
    cudaGetSymbolAddress((void**)&Wrh, h_Wr);
    cudaGetSymbolAddress((void**)&Wkh, h_Wk);
    cudaGetSymbolAddress((void**)&Wvh, h_Wv);
    cudaGetSymbolAddress((void**)&Woh, h_Wo);
    cudaGetSymbolAddress((void**)&w1h, h_w1);
    cudaGetSymbolAddress((void**)&w2h, h_w2);
    cudaGetSymbolAddress((void**)&a1h, h_a1);
    cudaGetSymbolAddress((void**)&a2h, h_a2);
    cudaGetSymbolAddress((void**)&v1h, h_v1);
    cudaGetSymbolAddress((void**)&v2h, h_v2);
    cudaGetSymbolAddress((void**)&g1h, h_g1);
    cudaGetSymbolAddress((void**)&g2h, h_g2);
    cudaGetSymbolAddress((void**)&twh, h_tw);
    cudaGetSymbolAddress((void**)&tah, h_ta);
    cudaGetSymbolAddress((void**)&tvh, h_tv);
    cudaGetSymbolAddress((void**)&tgh, h_tg);
    cudaGetSymbolAddress((void**)&rB , g_r);
    cudaGetSymbolAddress((void**)&kB , g_k);
    cudaGetSymbolAddress((void**)&vB , g_v);
    cudaGetSymbolAddress((void**)&dec, g_dec);
    cudaGetSymbolAddress((void**)&aB , g_a);
    cudaGetSymbolAddress((void**)&gB , g_g);
    cudaGetSymbolAddress((void**)&kkB, g_kk);
    cudaGetSymbolAddress((void**)&yB , g_y);

    // big weights f32->f16 (one launch)
    f2h4_kernel<<<dim3((unsigned)(((size_t)Cq*Cq/4 + 255)/256), 4), 256>>>(
        Wr, Wrh, Wk, Wkh, Wv, Wvh, Wo, Woh, (size_t)Cq*Cq/4);

    // lora weight transposes (one launch)
    transpose8<<<dim3(64, 64, 8), dim3(32,8)>>>(w1, w1h, w2, w2h, a1, a1h, a2, a2h,
                                                v1, v1h, v2, v2h, g1, g1h, g2, g2h);

    // token-shift mixes -> fp16
    mix_kernel<<<(unsigned)((BTC/4 + 255)/256), 256>>>(x, x_r,x_w,x_k,x_v,x_a,x_g,
                                                       xr,xw,xk,xv,xa,xg);

    // big projections r/k/v (separate)
    rg<0,0>(xr, Wrh, rB, Cq, Cq, nullptr,nullptr,nullptr);
    rg<0,0>(xk, Wkh, kB, Cq, Cq, nullptr,nullptr,nullptr);
    rg<0,0>(xv, Wvh, vB, Cq, Cq, nullptr,nullptr,nullptr);

    // lora up-projections (one launch)
    cudaFuncSetAttribute(gemm_lora4, cudaFuncAttributeMaxDynamicSharedMemorySize,
                         GSTAGES*STAGE_BYTES);
    gemm_lora4<<<dim3(2, Mq/128, 4), 256, GSTAGES*STAGE_BYTES>>>(
        xw, w1h, twh, xa, a1h, tah, xv, v1h, tvh, xg, g1h, tgh);

    // lora down-projections (one launch)
    cudaFuncSetAttribute(gemm_lorad4, cudaFuncAttributeMaxDynamicSharedMemorySize,
                         GSTAGES*STAGE_BYTES);
    gemm_lorad4<<<dim3(Cq/128, Mq/128, 4), 256, GSTAGES*STAGE_BYTES>>>(
        twh, w2h, dec, w0, tah, a2h, aB, a0, tvh, v2h, vB, v0, v_first, tgh, g2h, gB);

    // kk normalize + k transform
    kk_kernel<<<Mq*Hq/8, 256>>>(kB, aB, k_k, k_a, kkB);

    // WKV7 scan (64 threads/block)
    wkv_kernel<<<Bq*Hq, 64>>>(rB, dec, kB, vB, kkB, aB, yB);

    // GroupNorm + bonus + gate -> fp16 z
    gn_kernel<<<Mq*Hq/8, 256>>>(yB, rB, kB, vB, gB, lnw, lnb, r_k, zh);

    // output projection
    rg<0,0>(zh, Woh, out, Cq, Cq, nullptr,nullptr,nullptr);
}

// round 10
// speedup vs baseline: 1.3614x; 1.0264x over previous
#include <cuda_runtime.h>
#include <cuda_fp16.h>
#include <math.h>
#include <stdint.h>

// Problem constants
#define Bq 4
#define Tq 2048
#define Cq 2048
#define Hq 32
#define HSq 64
#define Mq (Bq*Tq)            // 8192 tokens
#define DW 128
#define DA 128
#define DG 224
#define DV 64
#define EPS_GN 0.00064f

// ---------------------------------------------------------------------------
// Scratch (static device globals; zero-initialized at module load)
// ---------------------------------------------------------------------------
#define BTC ((size_t)Mq*Cq)
__device__ __half h_xr[BTC];
__device__ __half h_xw[BTC];
__device__ __half h_xk[BTC];
__device__ __half h_xv[BTC];
__device__ __half h_xa[BTC];
__device__ __half h_xg[BTC];
__device__ __half h_z [BTC];
__device__ __half h_Wr[(size_t)Cq*Cq];
__device__ __half h_Wk[(size_t)Cq*Cq];
__device__ __half h_Wv[(size_t)Cq*Cq];
__device__ __half h_Wo[(size_t)Cq*Cq];
__device__ __half h_w1[(size_t)128*Cq];   // [DW pad128][C]
__device__ __half h_w2[(size_t)Cq*DW];    // [C][DW]
__device__ __half h_a1[(size_t)128*Cq];
__device__ __half h_a2[(size_t)Cq*DA];
__device__ __half h_v1[(size_t)128*Cq];   // [DV pad128][C]
__device__ __half h_v2[(size_t)Cq*DV];
__device__ __half h_g1[(size_t)256*Cq];   // [DG pad256][C]
__device__ __half h_g2[(size_t)Cq*DG];
__device__ __half h_tw[(size_t)Mq*DW];
__device__ __half h_ta[(size_t)Mq*DA];
__device__ __half h_tv[(size_t)Mq*DV];
__device__ __half h_tg[(size_t)Mq*DG];
// fp32 intermediates
__device__ float g_r [BTC];
__device__ float g_k [BTC];
__device__ float g_v [BTC];
__device__ float g_dec[BTC];
__device__ float g_a [BTC];
__device__ float g_g [BTC];
__device__ float g_kk[BTC];
__device__ float g_y [BTC];

__device__ __forceinline__ float sigmoidf_(float x){ return 1.0f/(1.0f+expf(-x)); }

__device__ __forceinline__ void cpa16(uint32_t s, const void* g){
    asm volatile("cp.async.cg.shared.global [%0], [%1], 16;\n" :: "r"(s), "l"(g));
}
__device__ __forceinline__ void ldsm_x4(uint32_t* r, uint32_t addr){
    asm volatile("ldmatrix.sync.aligned.m8n8.x4.shared.b16 {%0,%1,%2,%3}, [%4];"
        : "=r"(r[0]),"=r"(r[1]),"=r"(r[2]),"=r"(r[3]) : "r"(addr));
}
__device__ __forceinline__ void mma16(float* c, const uint32_t* a, const uint32_t* b){
    asm volatile("mma.sync.aligned.m16n8k16.row.col.f32.f16.f16.f32 "
        "{%0,%1,%2,%3},{%4,%5,%6,%7},{%8,%9},{%0,%1,%2,%3};\n"
        : "+f"(c[0]),"+f"(c[1]),"+f"(c[2]),"+f"(c[3])
        : "r"(a[0]),"r"(a[1]),"r"(a[2]),"r"(a[3]),"r"(b[0]),"r"(b[1]));
}

// ---------------------------------------------------------------------------
// Prep: 4x f32->f16 weight copies in ONE launch (blockIdx.y selects)
// ---------------------------------------------------------------------------
__global__ void f2h4_kernel(const float* __restrict__ i0, __half* __restrict__ o0,
                            const float* __restrict__ i1, __half* __restrict__ o1,
                            const float* __restrict__ i2, __half* __restrict__ o2,
                            const float* __restrict__ i3, __half* __restrict__ o3,
                            size_t n4)
{
    size_t i = (size_t)blockIdx.x*blockDim.x + threadIdx.x;
    if (i >= n4) return;
    const float* in = (blockIdx.y==0)?i0:(blockIdx.y==1)?i1:(blockIdx.y==2)?i2:i3;
    __half* out     = (blockIdx.y==0)?o0:(blockIdx.y==1)?o1:(blockIdx.y==2)?o2:o3;
    float4 v = ((const float4*)in)[i];
    ((__half2*)out)[i*2  ] = __floats2half2_rn(v.x, v.y);
    ((__half2*)out)[i*2+1] = __floats2half2_rn(v.z, v.w);
}

// ---------------------------------------------------------------------------
// 8 lora-weight transposes (f32[R][C] -> f16[C][R]) in ONE launch (blockIdx.z)
// ---------------------------------------------------------------------------
__device__ __forceinline__
void transpose_body(const float* __restrict__ in, __half* __restrict__ out, int R, int C)
{
    __shared__ float tile[32][33];
    int cb = blockIdx.x*32, rb = blockIdx.y*32;
    if (cb >= C || rb >= R) return;
    int c = cb + threadIdx.x;
    #pragma unroll
    for (int i=threadIdx.y; i<32; i+=8){
        int r = rb + i;
        if (r<R && c<C) tile[i][threadIdx.x] = in[(size_t)r*C + c];
    }
    __syncthreads();
    int r2 = rb + threadIdx.x;
    #pragma unroll
    for (int i=threadIdx.y; i<32; i+=8){
        int c2 = cb + i;
        if (r2<R && c2<C) out[(size_t)c2*R + r2] = __float2half_rn(tile[threadIdx.x][i]);
    }
}

__global__ void transpose8(const float* w1, __half* w1h, const float* w2, __half* w2h,
                           const float* a1, __half* a1h, const float* a2, __half* a2h,
                           const float* v1, __half* v1h, const float* v2, __half* v2h,
                           const float* g1, __half* g1h, const float* g2, __half* g2h)
{
    switch(blockIdx.z){
        case 0: transpose_body(w1, w1h, Cq, DW); break;
        case 1: transpose_body(w2, w2h, DW, Cq); break;
        case 2: transpose_body(a1, a1h, Cq, DA); break;
        case 3: transpose_body(a2, a2h, DA, Cq); break;
        case 4: transpose_body(v1, v1h, Cq, DV); break;
        case 5: transpose_body(v2, v2h, DV, Cq); break;
        case 6: transpose_body(g1, g1h, Cq, DG); break;
        default: transpose_body(g2, g2h, DG, Cq); break;
    }
}

// ---------------------------------------------------------------------------
// Token-shift mix -> fp16 outputs
// ---------------------------------------------------------------------------
__global__ void mix_kernel(const float* __restrict__ x,
                           const float* __restrict__ cr, const float* __restrict__ cw,
                           const float* __restrict__ ck, const float* __restrict__ cv,
                           const float* __restrict__ ca, const float* __restrict__ cg,
                           __half* __restrict__ xr, __half* __restrict__ xw,
                           __half* __restrict__ xk, __half* __restrict__ xv,
                           __half* __restrict__ xa, __half* __restrict__ xg)
{
    size_t i4 = (size_t)blockIdx.x*blockDim.x + threadIdx.x;
    size_t n4 = BTC/4;
    if (i4 >= n4) return;
    size_t flat = i4*4;
    int tok = (int)(flat / Cq);
    int t   = tok % Tq;
    const float4* x4 = (const float4*)x;
    float4 xc = x4[i4];
    float4 xp = (t==0) ? make_float4(0,0,0,0) : x4[i4 - Cq/4];
    float4 dx = make_float4(xp.x-xc.x, xp.y-xc.y, xp.z-xc.z, xp.w-xc.w);
    size_t c4 = i4 % (Cq/4);
    #define MIX1(COEF, OUT) { \
        float4 cf = ((const float4*)COEF)[c4]; \
        ((__half2*)OUT)[i4*2  ] = __floats2half2_rn(xc.x + dx.x*cf.x, xc.y + dx.y*cf.y); \
        ((__half2*)OUT)[i4*2+1] = __floats2half2_rn(xc.z + dx.z*cf.z, xc.w + dx.w*cf.w); }
    MIX1(cr, xr) MIX1(cw, xw) MIX1(ck, xk) MIX1(cv, xv) MIX1(ca, xa) MIX1(cg, xg)
    #undef MIX1
}

// ---------------------------------------------------------------------------
// Epilogue transform: 0 none, 1 tanh, 2 sigmoid, 3 w->decay, 4 a-sigm, 5 v-mix
// ---------------------------------------------------------------------------
template<int EPI>
__device__ __forceinline__ float epi_val(float val, int m, int n, int Nd,
                                         const float* __restrict__ bias,
                                         const float* __restrict__ vold,
                                         const float* __restrict__ vfirst)
{
    if (EPI==1) { val = tanhf(val); }
    else if (EPI==2) { val = sigmoidf_(val); }
    else if (EPI==3) {
        float w = bias[n] + val;
        float mneg = -w;
        float sp = fmaxf(mneg,0.f) + log1pf(expf(-fabsf(mneg)));
        float wl = -sp - 0.5f;
        val = expf(-expf(wl));
    }
    else if (EPI==4) { val = sigmoidf_(bias[n] + val); }
    else if (EPI==5) {
        float s  = sigmoidf_(bias[n] + val);
        size_t idx = (size_t)m*Nd + n;
        float vo = vold[idx];
        val = vo + (vfirst[idx] - vo)*s;
    }
    return val;
}

// ---------------------------------------------------------------------------
// fp16 tensor-core GEMM body: C[m,n] = sum_k A[m,k] * B[n,k]
// CTA 128x128, BK=32, 4-stage cp.async ring, ONE __syncthreads per slab.
// ---------------------------------------------------------------------------
#define GSTAGES 4
#define STAGE_HB 10240           // bytes: 128 rows * 40 halves * 2B
#define STAGE_BYTES (2*STAGE_HB)

template<int EPI,int RND>
__device__ __forceinline__
void gemm_body(const __half* __restrict__ A, const __half* __restrict__ Bw,
               void* __restrict__ Cm, int Nd, int Kd,
               const float* __restrict__ bias,
               const float* __restrict__ vold, const float* __restrict__ vfirst)
{
    extern __shared__ __align__(128) char smc[];
    const int tid = threadIdx.x;
    const int lane = tid&31, warp = tid>>5;
    const int bm = blockIdx.y*128, bn = blockIdx.x*128;
    const int wm = (warp&1)*64, wn = (warp>>1)*32;
    const int g = lane>>2, tig = lane&3;
    const uint32_t sbase = (uint32_t)__cvta_generic_to_shared(smc);

    const int arow = wm + (lane&7) + ((lane>>3)&1)*8;   // + mt*16
    const int akof = (lane>>4)*8;
    const int brow = wn + (lane&7) + (lane>>4)*8;       // + p*16
    const int bkof = ((lane>>3)&1)*8;

    float acc[4][4][4];
    #pragma unroll
    for (int i=0;i<4;i++)
        #pragma unroll
        for (int j=0;j<4;j++)
            #pragma unroll
            for (int q=0;q<4;q++) acc[i][j][q]=0.f;

    const int NS = Kd >> 5;

    auto loadSlab = [&](int s, int st){
        const uint32_t sb = sbase + st*STAGE_BYTES;
        const int k0 = s*32;
        #pragma unroll
        for (int i=0;i<2;i++){
            int id  = tid + i*256;
            int row = id>>2, c16 = id&3;
            cpa16(sb + row*80 + c16*16,
                  &A[(size_t)(bm+row)*Kd + k0 + c16*8]);
            cpa16(sb + STAGE_HB + row*80 + c16*16,
                  &Bw[(size_t)(bn+row)*Kd + k0 + c16*8]);
        }
    };
    auto compute = [&](int st){
        const uint32_t sb = sbase + st*STAGE_BYTES;
        #pragma unroll
        for (int ks=0; ks<2; ks++){
            uint32_t af[4][4], bf[2][4];
            #pragma unroll
            for (int mt=0;mt<4;mt++)
                ldsm_x4(af[mt], sb + ((arow+mt*16)*40 + akof + ks*16)*2);
            #pragma unroll
            for (int p=0;p<2;p++)
                ldsm_x4(bf[p], sb + STAGE_HB + ((brow+p*16)*40 + bkof + ks*16)*2);
            #pragma unroll
            for (int mt=0;mt<4;mt++)
                #pragma unroll
                for (int nt=0;nt<4;nt++)
                    mma16(acc[mt][nt], af[mt], &bf[nt>>1][(nt&1)*2]);
        }
    };

    #pragma unroll
    for (int i=0;i<GSTAGES-1;i++){
        if (i<NS) loadSlab(i,i);
        asm volatile("cp.async.commit_group;\n");
    }
    for (int s=0;s<NS;s++){
        asm volatile("cp.async.wait_group %0;\n" :: "n"(GSTAGES-2));
        __syncthreads();
        int ld = s + GSTAGES-1;
        if (ld < NS) loadSlab(ld, ld&3);
        asm volatile("cp.async.commit_group;\n");
        compute(s&3);
    }

    #pragma unroll
    for (int mt=0;mt<4;mt++){
        int r0 = bm + wm + mt*16 + g;
        #pragma unroll
        for (int nt=0;nt<4;nt++){
            int n0 = bn + wn + nt*8 + tig*2;
            if (n0 < Nd){
                float* c = acc[mt][nt];
                float v00 = epi_val<EPI>(c[0], r0,   n0,   Nd, bias, vold, vfirst);
                float v01 = epi_val<EPI>(c[1], r0,   n0+1, Nd, bias, vold, vfirst);
                float v10 = epi_val<EPI>(c[2], r0+8, n0,   Nd, bias, vold, vfirst);
                float v11 = epi_val<EPI>(c[3], r0+8, n0+1, Nd, bias, vold, vfirst);
                if (RND){
                    __half* O = (__half*)Cm;
                    *(__half2*)&O[(size_t)r0*Nd + n0]     = __floats2half2_rn(v00, v01);
                    *(__half2*)&O[(size_t)(r0+8)*Nd + n0] = __floats2half2_rn(v10, v11);
                } else {
                    float* O = (float*)Cm;
                    *(float2*)&O[(size_t)r0*Nd + n0]     = make_float2(v00, v01);
                    *(float2*)&O[(size_t)(r0+8)*Nd + n0] = make_float2(v10, v11);
                }
            }
        }
    }
}

template<int EPI,int RND>
__global__ __launch_bounds__(256,2)
void gemm_h(const __half* __restrict__ A, const __half* __restrict__ Bw,
            void* __restrict__ Cm, int Nd, int Kd,
            const float* __restrict__ bias,
            const float* __restrict__ vold, const float* __restrict__ vfirst)
{
    gemm_body<EPI,RND>(A, Bw, Cm, Nd, Kd, bias, vold, vfirst);
}

// merged r/k/v projections: blockIdx.z selects which
__global__ __launch_bounds__(256,2)
void gemm_h3(const __half* __restrict__ A0, const __half* __restrict__ B0, float* __restrict__ C0,
             const __half* __restrict__ A1, const __half* __restrict__ B1, float* __restrict__ C1,
             const __half* __restrict__ A2, const __half* __restrict__ B2, float* __restrict__ C2)
{
    const __half* A = (blockIdx.z==0) ? A0 : (blockIdx.z==1) ? A1 : A2;
    const __half* B = (blockIdx.z==0) ? B0 : (blockIdx.z==1) ? B1 : B2;
    float*        C = (blockIdx.z==0) ? C0 : (blockIdx.z==1) ? C1 : C2;
    gemm_body<0,0>(A, B, (void*)C, Cq, Cq, nullptr, nullptr, nullptr);
}

// 4 lora up-projections in ONE launch (blockIdx.z selects; uniform per block)
__global__ __launch_bounds__(256,2)
void gemm_lora4(const __half* __restrict__ xw, const __half* __restrict__ w1h, __half* __restrict__ tw,
                const __half* __restrict__ xa, const __half* __restrict__ a1h, __half* __restrict__ ta,
                const __half* __restrict__ xv, const __half* __restrict__ v1h, __half* __restrict__ tv,
                const __half* __restrict__ xg, const __half* __restrict__ g1h, __half* __restrict__ tg)
{
    const int bn = blockIdx.x*128;
    switch(blockIdx.z){
        case 0: if (bn >= DW) return; gemm_body<1,1>(xw, w1h, (void*)tw, DW, Cq, nullptr,nullptr,nullptr); break;
        case 1: if (bn >= DA) return; gemm_body<0,1>(xa, a1h, (void*)ta, DA, Cq, nullptr,nullptr,nullptr); break;
        case 2: if (bn >= DV) return; gemm_body<0,1>(xv, v1h, (void*)tv, DV, Cq, nullptr,nullptr,nullptr); break;
        default:                      gemm_body<2,1>(xg, g1h, (void*)tg, DG, Cq, nullptr,nullptr,nullptr); break;
    }
}

// 4 lora down-projections in ONE launch (blockIdx.z selects; uniform per block)
__global__ __launch_bounds__(256,2)
void gemm_lorad4(const __half* __restrict__ twh, const __half* __restrict__ w2h, float* __restrict__ dec, const float* __restrict__ w0,
                 const __half* __restrict__ tah, const __half* __restrict__ a2h, float* __restrict__ aB,  const float* __restrict__ a0,
                 const __half* __restrict__ tvh, const __half* __restrict__ v2h, float* __restrict__ vB,  const float* __restrict__ v0,
                 const float* __restrict__ vfirst,
                 const __half* __restrict__ tgh, const __half* __restrict__ g2h, float* __restrict__ gB)
{
    switch(blockIdx.z){
        case 0: gemm_body<3,0>(twh, w2h, (void*)dec, Cq, DW, w0, nullptr, nullptr); break;
        case 1: gemm_body<4,0>(tah, a2h, (void*)aB,  Cq, DA, a0, nullptr, nullptr); break;
        case 2: gemm_body<5,0>(tvh, v2h, (void*)vB,  Cq, DV, v0, vB, vfirst);       break;
        default: gemm_body<0,0>(tgh, g2h, (void*)gB, Cq, DG, nullptr, nullptr, nullptr); break;
    }
}

// ---------------------------------------------------------------------------
// kk normalize + k transform
// ---------------------------------------------------------------------------
__global__ void kk_kernel(float* __restrict__ k, const float* __restrict__ a,
                          const float* __restrict__ k_k, const float* __restrict__ k_a,
                          float* __restrict__ kk)
{
    int gw   = blockIdx.x*8 + (threadIdx.x>>5);
    int lane = threadIdx.x & 31;
    int m = gw >> 5;
    int h = gw & 31;
    size_t base = (size_t)m*Cq + h*HSq;
    int c0 = h*HSq + lane, c1 = c0 + 32;
    float k0 = k[base+lane], k1 = k[base+lane+32];
    float kk0 = k0*k_k[c0], kk1 = k1*k_k[c1];
    float s = kk0*kk0 + kk1*kk1;
    #pragma unroll
    for (int off=16; off; off>>=1) s += __shfl_xor_sync(0xffffffffu, s, off);
    float inv = 1.0f / fmaxf(sqrtf(s), 1e-12f);
    kk[base+lane]    = kk0*inv;
    kk[base+lane+32] = kk1*inv;
    float a0 = a[base+lane], a1 = a[base+lane+32];
    k[base+lane]    = k0*(1.0f + (a0-1.0f)*k_a[c0]);
    k[base+lane+32] = k1*(1.0f + (a1-1.0f)*k_a[c1]);
}

// ---------------------------------------------------------------------------
// WKV7 scan: 64 threads per (b,h); DEPTH-4 register prefetch ring so gmem
// latency (~600cyc) is fully hidden (issue->consume distance ~3.5 steps).
// ---------------------------------------------------------------------------
__global__ __launch_bounds__(64)
void wkv_kernel(const float* __restrict__ r, const float* __restrict__ wd,
                const float* __restrict__ k, const float* __restrict__ v,
                const float* __restrict__ kkp, const float* __restrict__ ap,
                float* __restrict__ y)
{
    int bh = blockIdx.x;
    int b = bh >> 5;
    int h = bh & 31;
    int i = threadIdx.x;
    __shared__ __align__(16) float sr[64], sw[64], sk[64], sa[64], sb[64];
    float st[64];
    #pragma unroll
    for (int j=0;j<64;j++) st[j]=0.f;
    size_t base = ((size_t)b*Tq)*Cq + (size_t)h*HSq;

    // depth-4 register prefetch ring
    float R[4], W[4], K[4], Q[4], A[4], V[4];
    #pragma unroll
    for (int j=0;j<4;j++){
        size_t o0 = base + (size_t)j*Cq;
        R[j]=r[o0+i]; W[j]=wd[o0+i]; K[j]=k[o0+i];
        Q[j]=kkp[o0+i]; A[j]=ap[o0+i]; V[j]=v[o0+i];
    }

    size_t o = base;
    for (int t=0; t<Tq; t+=4){
        #pragma unroll
        for (int q=0; q<4; q++){
            // publish step t+q from ring slot q
            sr[i]=R[q]; sw[i]=W[q]; sk[i]=K[q]; sa[i]=-Q[q]; sb[i]=Q[q]*A[q];
            float vcur = V[q];
            __syncthreads();

            // refill slot q with step t+q+4 (consumed ~3.5 steps later)
            int tn = t + q + 4;
            if (tn < Tq){
                size_t on = base + (size_t)tn*Cq;
                R[q]=r[on+i]; W[q]=wd[on+i]; K[q]=k[on+i];
                Q[q]=kkp[on+i]; A[q]=ap[on+i]; V[q]=v[on+i];
            }

            // ---- compute ----
            float s0=0,s1=0,s2=0,s3=0;
            const float4* A4 = (const float4*)sa;
            #pragma unroll
            for (int j=0;j<16;j++) {
                float4 a4 = A4[j];
                s0 += st[4*j+0]*a4.x; s1 += st[4*j+1]*a4.y;
                s2 += st[4*j+2]*a4.z; s3 += st[4*j+3]*a4.w;
            }
            float sav = (s0+s1)+(s2+s3);

            const float4* W4=(const float4*)sw; const float4* K4=(const float4*)sk;
            const float4* B4=(const float4*)sb; const float4* R4=(const float4*)sr;
            float o0=0,o1=0,o2=0,o3=0;
            #pragma unroll
            for (int j=0;j<16;j++) {
                float4 w4=W4[j], k4=K4[j], b4=B4[j], r4=R4[j];
                float t0 = st[4*j+0]*w4.x + vcur*k4.x + sav*b4.x;
                float t1 = st[4*j+1]*w4.y + vcur*k4.y + sav*b4.y;
                float t2 = st[4*j+2]*w4.z + vcur*k4.z + sav*b4.z;
                float t3 = st[4*j+3]*w4.w + vcur*k4.w + sav*b4.w;
                st[4*j+0]=t0; st[4*j+1]=t1; st[4*j+2]=t2; st[4*j+3]=t3;
                o0 += t0*r4.x; o1 += t1*r4.y; o2 += t2*r4.z; o3 += t3*r4.w;
            }
            y[o+i] = (o0+o1)+(o2+o3);
            o += Cq;
            __syncthreads();
        }
    }
}

// ---------------------------------------------------------------------------
// GroupNorm + bonus + gate -> z (fp16 for Wo gemm)
// ---------------------------------------------------------------------------
__global__ void gn_kernel(const float* __restrict__ y, const float* __restrict__ r,
                          const float* __restrict__ k, const float* __restrict__ v,
                          const float* __restrict__ g,
                          const float* __restrict__ lnw, const float* __restrict__ lnb,
                          const float* __restrict__ r_k, __half* __restrict__ z)
{
    int gw   = blockIdx.x*8 + (threadIdx.x>>5);
    int lane = threadIdx.x & 31;
    int m = gw >> 5;
    int h = gw & 31;
    size_t base = (size_t)m*Cq + h*HSq;
    int c0 = h*HSq + lane, c1 = c0 + 32;
    float y0=y[base+lane], y1=y[base+lane+32];
    float r0=r[base+lane], r1=r[base+lane+32];
    float k0=k[base+lane], k1=k[base+lane+32];
    float sum = y0+y1;
    float sq  = y0*y0 + y1*y1;
    float dot = r0*k0*r_k[c0] + r1*k1*r_k[c1];
    #pragma unroll
    for (int off=16; off; off>>=1) {
        sum += __shfl_xor_sync(0xffffffffu, sum, off);
        sq  += __shfl_xor_sync(0xffffffffu, sq , off);
        dot += __shfl_xor_sync(0xffffffffu, dot, off);
    }
    float mean = sum * (1.0f/64.0f);
    float var  = sq * (1.0f/64.0f) - mean*mean;
    float inv  = rsqrtf(var + EPS_GN);
    float v0=v[base+lane], v1=v[base+lane+32];
    float g0=g[base+lane], g1=g[base+lane+32];
    float z0 = ((y0-mean)*inv*lnw[c0] + lnb[c0] + dot*v0) * g0;
    float z1 = ((y1-mean)*inv*lnw[c1] + lnb[c1] + dot*v1) * g1;
    z[base+lane]    = __float2half_rn(z0);
    z[base+lane+32] = __float2half_rn(z1);
}

// ---------------------------------------------------------------------------
// Host helpers
// ---------------------------------------------------------------------------
template<int EPI,int RND>
static void rg(const __half* A, const __half* Bw, void* C, int Nd, int Kd,
               const float* bias, const float* vold, const float* vfirst)
{
    cudaFuncSetAttribute(gemm_h<EPI,RND>, cudaFuncAttributeMaxDynamicSharedMemorySize,
                         GSTAGES*STAGE_BYTES);
    dim3 grid((Nd+127)/128, Mq/128);
    gemm_h<EPI,RND><<<grid, 256, GSTAGES*STAGE_BYTES>>>(A, Bw, C, Nd, Kd, bias, vold, vfirst);
}

// ---------------------------------------------------------------------------
// Launch
// ---------------------------------------------------------------------------
extern "C" void kernel_launch(void* const* d_in, const int* in_sizes, int n_in,
                              void* d_out, int out_size)
{
    const float* x       = (const float*)d_in[0];
    const float* v_first = (const float*)d_in[1];
    const float* x_r = (const float*)d_in[2];
    const float* x_w = (const float*)d_in[3];
    const float* x_k = (const float*)d_in[4];
    const float* x_v = (const float*)d_in[5];
    const float* x_a = (const float*)d_in[6];
    const float* x_g = (const float*)d_in[7];
    const float* w0  = (const float*)d_in[8];
    const float* w1  = (const float*)d_in[9];
    const float* w2  = (const float*)d_in[10];
    const float* a0  = (const float*)d_in[11];
    const float* a1  = (const float*)d_in[12];
    const float* a2  = (const float*)d_in[13];
    const float* v0  = (const float*)d_in[14];
    const float* v1  = (const float*)d_in[15];
    const float* v2  = (const float*)d_in[16];
    const float* g1  = (const float*)d_in[17];
    const float* g2  = (const float*)d_in[18];
    const float* k_k = (const float*)d_in[19];
    const float* k_a = (const float*)d_in[20];
    const float* r_k = (const float*)d_in[21];
    const float* Wr  = (const float*)d_in[22];
    const float* Wk  = (const float*)d_in[23];
    const float* Wv  = (const float*)d_in[24];
    const float* Wo  = (const float*)d_in[25];
    const float* lnw = (const float*)d_in[26];
    const float* lnb = (const float*)d_in[27];
    float* out = (float*)d_out;

    __half *xr,*xw,*xk,*xv,*xa,*xg,*zh,*Wrh,*Wkh,*Wvh,*Woh;
    __half *w1h,*w2h,*a1h,*a2h,*v1h,*v2h,*g1h,*g2h,*twh,*tah,*tvh,*tgh;
    float *rB,*kB,*vB,*dec,*aB,*gB,*kkB,*yB;
    cudaGetSymbolAddress((void**)&xr , h_xr);
    cudaGetSymbolAddress((void**)&xw , h_xw);
    cudaGetSymbolAddress((void**)&xk , h_xk);
    cudaGetSymbolAddress((void**)&xv , h_xv);
    cudaGetSymbolAddress((void**)&xa , h_xa);
    cudaGetSymbolAddress((void**)&xg , h_xg);
    cudaGetSymbolAddress((void**)&zh , h_z);
    cudaGetSymbolAddress((void**)&Wrh, h_Wr);
    cudaGetSymbolAddress((void**)&Wkh, h_Wk);
    cudaGetSymbolAddress((void**)&Wvh, h_Wv);
    cudaGetSymbolAddress((void**)&Woh, h_Wo);
    cudaGetSymbolAddress((void**)&w1h, h_w1);
    cudaGetSymbolAddress((void**)&w2h, h_w2);
    cudaGetSymbolAddress((void**)&a1h, h_a1);
    cudaGetSymbolAddress((void**)&a2h, h_a2);
    cudaGetSymbolAddress((void**)&v1h, h_v1);
    cudaGetSymbolAddress((void**)&v2h, h_v2);
    cudaGetSymbolAddress((void**)&g1h, h_g1);
    cudaGetSymbolAddress((void**)&g2h, h_g2);
    cudaGetSymbolAddress((void**)&twh, h_tw);
    cudaGetSymbolAddress((void**)&tah, h_ta);
    cudaGetSymbolAddress((void**)&tvh, h_tv);
    cudaGetSymbolAddress((void**)&tgh, h_tg);
    cudaGetSymbolAddress((void**)&rB , g_r);
    cudaGetSymbolAddress((void**)&kB , g_k);
    cudaGetSymbolAddress((void**)&vB , g_v);
    cudaGetSymbolAddress((void**)&dec, g_dec);
    cudaGetSymbolAddress((void**)&aB , g_a);
    cudaGetSymbolAddress((void**)&gB , g_g);
    cudaGetSymbolAddress((void**)&kkB, g_kk);
    cudaGetSymbolAddress((void**)&yB , g_y);

    // big weights f32->f16 (one launch)
    f2h4_kernel<<<dim3((unsigned)(((size_t)Cq*Cq/4 + 255)/256), 4), 256>>>(
        Wr, Wrh, Wk, Wkh, Wv, Wvh, Wo, Woh, (size_t)Cq*Cq/4);

    // lora weight transposes (one launch)
    transpose8<<<dim3(64, 64, 8), dim3(32,8)>>>(w1, w1h, w2, w2h, a1, a1h, a2, a2h,
                                                v1, v1h, v2, v2h, g1, g1h, g2, g2h);

    // token-shift mixes -> fp16
    mix_kernel<<<(unsigned)((BTC/4 + 255)/256), 256>>>(x, x_r,x_w,x_k,x_v,x_a,x_g,
                                                       xr,xw,xk,xv,xa,xg);

    // merged big projections r/k/v (one launch)
    cudaFuncSetAttribute(gemm_h3, cudaFuncAttributeMaxDynamicSharedMemorySize,
                         GSTAGES*STAGE_BYTES);
    gemm_h3<<<dim3(Cq/128, Mq/128, 3), 256, GSTAGES*STAGE_BYTES>>>(
        xr, Wrh, rB, xk, Wkh, kB, xv, Wvh, vB);

    // lora up-projections (one launch)
    cudaFuncSetAttribute(gemm_lora4, cudaFuncAttributeMaxDynamicSharedMemorySize,
                         GSTAGES*STAGE_BYTES);
    gemm_lora4<<<dim3(2, Mq/128, 4), 256, GSTAGES*STAGE_BYTES>>>(
        xw, w1h, twh, xa, a1h, tah, xv, v1h, tvh, xg, g1h, tgh);

    // lora down-projections (one launch)
    cudaFuncSetAttribute(gemm_lorad4, cudaFuncAttributeMaxDynamicSharedMemorySize,
                         GSTAGES*STAGE_BYTES);
    gemm_lorad4<<<dim3(Cq/128, Mq/128, 4), 256, GSTAGES*STAGE_BYTES>>>(
        twh, w2h, dec, w0, tah, a2h, aB, a0, tvh, v2h, vB, v0, v_first, tgh, g2h, gB);

    // kk normalize + k transform
    kk_kernel<<<Mq*Hq/8, 256>>>(kB, aB, k_k, k_a, kkB);

    // WKV7 scan (64 threads/block, depth-4 prefetch)
    wkv_kernel<<<Bq*Hq, 64>>>(rB, dec, kB, vB, kkB, aB, yB);

    // GroupNorm + bonus + gate -> fp16 z
    gn_kernel<<<Mq*Hq/8, 256>>>(yB, rB, kB, vB, gB, lnw, lnb, r_k, zh);

    // output projection
    rg<0,0>(zh, Woh, out, Cq, Cq, nullptr,nullptr,nullptr);
}

// round 11
// speedup vs baseline: 1.3934x; 1.0235x over previous
#include <cuda_runtime.h>
#include <cuda_fp16.h>
#include <math.h>
#include <stdint.h>

// Problem constants
#define Bq 4
#define Tq 2048
#define Cq 2048
#define Hq 32
#define HSq 64
#define Mq (Bq*Tq)            // 8192 tokens
#define DW 128
#define DA 128
#define DG 224
#define DGp 256               // padded K for g lora (BK=64 divisibility)
#define DV 64
#define EPS_GN 0.00064f

// ---------------------------------------------------------------------------
// Scratch (static device globals; zero-initialized at module load)
// ---------------------------------------------------------------------------
#define BTC ((size_t)Mq*Cq)
__device__ __half h_xr[BTC];
__device__ __half h_xw[BTC];
__device__ __half h_xk[BTC];
__device__ __half h_xv[BTC];
__device__ __half h_xa[BTC];
__device__ __half h_xg[BTC];
__device__ __half h_z [BTC];
__device__ __half h_Wr[(size_t)Cq*Cq];
__device__ __half h_Wk[(size_t)Cq*Cq];
__device__ __half h_Wv[(size_t)Cq*Cq];
__device__ __half h_Wo[(size_t)Cq*Cq];
__device__ __half h_w1[(size_t)128*Cq];   // [DW pad128][C]
__device__ __half h_w2[(size_t)Cq*DW];    // [C][DW]
__device__ __half h_a1[(size_t)128*Cq];
__device__ __half h_a2[(size_t)Cq*DA];
__device__ __half h_v1[(size_t)128*Cq];   // [DV pad128][C]
__device__ __half h_v2[(size_t)Cq*DV];
__device__ __half h_g1[(size_t)DGp*Cq];   // [DG pad256][C], pad rows stay 0
__device__ __half h_g2[(size_t)Cq*DGp];   // [C][DG pad256], pad cols stay 0
__device__ __half h_tw[(size_t)Mq*DW];
__device__ __half h_ta[(size_t)Mq*DA];
__device__ __half h_tv[(size_t)Mq*DV];
__device__ __half h_tg[(size_t)Mq*DGp];   // stride 256
// fp32 intermediates
__device__ float g_r [BTC];
__device__ float g_k [BTC];
__device__ float g_v [BTC];
__device__ float g_dec[BTC];
__device__ float g_a [BTC];
__device__ float g_g [BTC];
__device__ float g_kk[BTC];
__device__ float g_y [BTC];

__device__ __forceinline__ float sigmoidf_(float x){ return 1.0f/(1.0f+expf(-x)); }

__device__ __forceinline__ void cpa16(uint32_t s, const void* g){
    asm volatile("cp.async.cg.shared.global [%0], [%1], 16;\n" :: "r"(s), "l"(g));
}
__device__ __forceinline__ void ldsm_x4(uint32_t* r, uint32_t addr){
    asm volatile("ldmatrix.sync.aligned.m8n8.x4.shared.b16 {%0,%1,%2,%3}, [%4];"
        : "=r"(r[0]),"=r"(r[1]),"=r"(r[2]),"=r"(r[3]) : "r"(addr));
}
__device__ __forceinline__ void mma16(float* c, const uint32_t* a, const uint32_t* b){
    asm volatile("mma.sync.aligned.m16n8k16.row.col.f32.f16.f16.f32 "
        "{%0,%1,%2,%3},{%4,%5,%6,%7},{%8,%9},{%0,%1,%2,%3};\n"
        : "+f"(c[0]),"+f"(c[1]),"+f"(c[2]),"+f"(c[3])
        : "r"(a[0]),"r"(a[1]),"r"(a[2]),"r"(a[3]),"r"(b[0]),"r"(b[1]));
}

// ---------------------------------------------------------------------------
// Prep: 4x f32->f16 weight copies in ONE launch (blockIdx.y selects)
// ---------------------------------------------------------------------------
__global__ void f2h4_kernel(const float* __restrict__ i0, __half* __restrict__ o0,
                            const float* __restrict__ i1, __half* __restrict__ o1,
                            const float* __restrict__ i2, __half* __restrict__ o2,
                            const float* __restrict__ i3, __half* __restrict__ o3,
                            size_t n4)
{
    size_t i = (size_t)blockIdx.x*blockDim.x + threadIdx.x;
    if (i >= n4) return;
    const float* in = (blockIdx.y==0)?i0:(blockIdx.y==1)?i1:(blockIdx.y==2)?i2:i3;
    __half* out     = (blockIdx.y==0)?o0:(blockIdx.y==1)?o1:(blockIdx.y==2)?o2:o3;
    float4 v = ((const float4*)in)[i];
    ((__half2*)out)[i*2  ] = __floats2half2_rn(v.x, v.y);
    ((__half2*)out)[i*2+1] = __floats2half2_rn(v.z, v.w);
}

// ---------------------------------------------------------------------------
// 8 lora-weight transposes (f32[R][C] -> f16[C][Rs], Rs = padded out stride)
// ---------------------------------------------------------------------------
__device__ __forceinline__
void transpose_body(const float* __restrict__ in, __half* __restrict__ out,
                    int R, int C, int Rs)
{
    __shared__ float tile[32][33];
    int cb = blockIdx.x*32, rb = blockIdx.y*32;
    if (cb >= C || rb >= R) return;
    int c = cb + threadIdx.x;
    #pragma unroll
    for (int i=threadIdx.y; i<32; i+=8){
        int r = rb + i;
        if (r<R && c<C) tile[i][threadIdx.x] = in[(size_t)r*C + c];
    }
    __syncthreads();
    int r2 = rb + threadIdx.x;
    #pragma unroll
    for (int i=threadIdx.y; i<32; i+=8){
        int c2 = cb + i;
        if (r2<R && c2<C) out[(size_t)c2*Rs + r2] = __float2half_rn(tile[threadIdx.x][i]);
    }
}

__global__ void transpose8(const float* w1, __half* w1h, const float* w2, __half* w2h,
                           const float* a1, __half* a1h, const float* a2, __half* a2h,
                           const float* v1, __half* v1h, const float* v2, __half* v2h,
                           const float* g1, __half* g1h, const float* g2, __half* g2h)
{
    switch(blockIdx.z){
        case 0: transpose_body(w1, w1h, Cq, DW, DW); break;
        case 1: transpose_body(w2, w2h, DW, Cq, DW == DW ? Cq : Cq); break;
        case 2: transpose_body(a1, a1h, Cq, DA, DA); break;
        case 3: transpose_body(a2, a2h, DA, Cq, Cq); break;
        case 4: transpose_body(v1, v1h, Cq, DV, DV); break;
        case 5: transpose_body(v2, v2h, DV, Cq, Cq); break;
        case 6: transpose_body(g1, g1h, Cq, DG, DG); break;
        default: transpose_body(g2, g2h, DG, Cq, Cq); break;
    }
}
// NOTE on strides above: for the "1" (up) matrices the output is [D][C]
// (Rs applies to the *first* out dim index r2 = row within C?) — careful:
// transpose_body writes out[c2*Rs + r2] where c2 indexes C (out rows) and
// r2 indexes R (out cols). So Rs is the out row stride = R (padded).
// case0: w1 in[Cq][DW] -> out[DW][Cq]: R=Cq, C=DW, Rs=Cq.  (fixed below)

__global__ void transpose8b(const float* w1, __half* w1h, const float* w2, __half* w2h,
                            const float* a1, __half* a1h, const float* a2, __half* a2h,
                            const float* v1, __half* v1h, const float* v2, __half* v2h,
                            const float* g1, __half* g1h, const float* g2, __half* g2h)
{
    switch(blockIdx.z){
        case 0: transpose_body(w1, w1h, Cq, DW, Cq);  break;  // [DW][Cq]
        case 1: transpose_body(w2, w2h, DW, Cq, DW);  break;  // [Cq][DW]
        case 2: transpose_body(a1, a1h, Cq, DA, Cq);  break;
        case 3: transpose_body(a2, a2h, DA, Cq, DA);  break;
        case 4: transpose_body(v1, v1h, Cq, DV, Cq);  break;
        case 5: transpose_body(v2, v2h, DV, Cq, DV);  break;
        case 6: transpose_body(g1, g1h, Cq, DG, Cq);  break;  // [DG..256][Cq]
        default: transpose_body(g2, g2h, DG, Cq, DGp); break; // [Cq][256], pad 0
    }
}

// ---------------------------------------------------------------------------
// Token-shift mix -> fp16 outputs
// ---------------------------------------------------------------------------
__global__ void mix_kernel(const float* __restrict__ x,
                           const float* __restrict__ cr, const float* __restrict__ cw,
                           const float* __restrict__ ck, const float* __restrict__ cv,
                           const float* __restrict__ ca, const float* __restrict__ cg,
                           __half* __restrict__ xr, __half* __restrict__ xw,
                           __half* __restrict__ xk, __half* __restrict__ xv,
                           __half* __restrict__ xa, __half* __restrict__ xg)
{
    size_t i4 = (size_t)blockIdx.x*blockDim.x + threadIdx.x;
    size_t n4 = BTC/4;
    if (i4 >= n4) return;
    size_t flat = i4*4;
    int tok = (int)(flat / Cq);
    int t   = tok % Tq;
    const float4* x4 = (const float4*)x;
    float4 xc = x4[i4];
    float4 xp = (t==0) ? make_float4(0,0,0,0) : x4[i4 - Cq/4];
    float4 dx = make_float4(xp.x-xc.x, xp.y-xc.y, xp.z-xc.z, xp.w-xc.w);
    size_t c4 = i4 % (Cq/4);
    #define MIX1(COEF, OUT) { \
        float4 cf = ((const float4*)COEF)[c4]; \
        ((__half2*)OUT)[i4*2  ] = __floats2half2_rn(xc.x + dx.x*cf.x, xc.y + dx.y*cf.y); \
        ((__half2*)OUT)[i4*2+1] = __floats2half2_rn(xc.z + dx.z*cf.z, xc.w + dx.w*cf.w); }
    MIX1(cr, xr) MIX1(cw, xw) MIX1(ck, xk) MIX1(cv, xv) MIX1(ca, xa) MIX1(cg, xg)
    #undef MIX1
}

// ---------------------------------------------------------------------------
// Epilogue transform: 0 none, 1 tanh, 2 sigmoid, 3 w->decay, 4 a-sigm, 5 v-mix
// ---------------------------------------------------------------------------
template<int EPI>
__device__ __forceinline__ float epi_val(float val, int m, int n, int Nd,
                                         const float* __restrict__ bias,
                                         const float* __restrict__ vold,
                                         const float* __restrict__ vfirst)
{
    if (EPI==1) { val = tanhf(val); }
    else if (EPI==2) { val = sigmoidf_(val); }
    else if (EPI==3) {
        float w = bias[n] + val;
        float mneg = -w;
        float sp = fmaxf(mneg,0.f) + log1pf(expf(-fabsf(mneg)));
        float wl = -sp - 0.5f;
        val = expf(-expf(wl));
    }
    else if (EPI==4) { val = sigmoidf_(bias[n] + val); }
    else if (EPI==5) {
        float s  = sigmoidf_(bias[n] + val);
        size_t idx = (size_t)m*Nd + n;
        float vo = vold[idx];
        val = vo + (vfirst[idx] - vo)*s;
    }
    return val;
}

// ---------------------------------------------------------------------------
// fp16 tensor-core GEMM body: C[m,n] = sum_k A[m,k] * B[n,k]
// CTA 128x128, BK=64, 3-stage cp.async ring, ONE __syncthreads per 64-k slab.
// smem/stage: 2 * 128rows * 72halves * 2B = 36 KB; 3 stages = 110.6 KB/CTA.
// Row stride 72 halves (144B) keeps ldmatrix conflict-free.
// ---------------------------------------------------------------------------
#define GST 3
#define ST_HB (128*72*2)            // 18432 B per matrix per stage
#define ST_BYTES (2*ST_HB)          // 36864 B per stage

template<int EPI,int RND>
__device__ __forceinline__
void gemm_body(const __half* __restrict__ A, const __half* __restrict__ Bw,
               void* __restrict__ Cm, int Nd, int Kd,
               const float* __restrict__ bias,
               const float* __restrict__ vold, const float* __restrict__ vfirst)
{
    extern __shared__ __align__(128) char smc[];
    const int tid = threadIdx.x;
    const int lane = tid&31, warp = tid>>5;
    const int bm = blockIdx.y*128, bn = blockIdx.x*128;
    const int wm = (warp&1)*64, wn = (warp>>1)*32;
    const int g = lane>>2, tig = lane&3;
    const uint32_t sbase = (uint32_t)__cvta_generic_to_shared(smc);

    const int arow = wm + (lane&7) + ((lane>>3)&1)*8;   // + mt*16
    const int akof = (lane>>4)*8;
    const int brow = wn + (lane&7) + (lane>>4)*8;       // + p*16
    const int bkof = ((lane>>3)&1)*8;

    float acc[4][4][4];
    #pragma unroll
    for (int i=0;i<4;i++)
        #pragma unroll
        for (int j=0;j<4;j++)
            #pragma unroll
            for (int q=0;q<4;q++) acc[i][j][q]=0.f;

    const int NS = Kd >> 6;          // 64-wide slabs

    auto loadSlab = [&](int s, int st){
        const uint32_t sb = sbase + st*ST_BYTES;
        const int k0 = s*64;
        #pragma unroll
        for (int i=0;i<4;i++){
            int id  = tid + i*256;          // 0..1023
            int row = id>>3, c16 = id&7;    // 8 x 16B chunks per row
            cpa16(sb + row*144 + c16*16,
                  &A[(size_t)(bm+row)*Kd + k0 + c16*8]);
            cpa16(sb + ST_HB + row*144 + c16*16,
                  &Bw[(size_t)(bn+row)*Kd + k0 + c16*8]);
        }
    };
    auto compute = [&](int st){
        const uint32_t sb = sbase + st*ST_BYTES;
        #pragma unroll
        for (int ks=0; ks<4; ks++){
            uint32_t af[4][4], bf[2][4];
            #pragma unroll
            for (int mt=0;mt<4;mt++)
                ldsm_x4(af[mt], sb + ((arow+mt*16)*72 + akof + ks*16)*2);
            #pragma unroll
            for (int p=0;p<2;p++)
                ldsm_x4(bf[p], sb + ST_HB + ((brow+p*16)*72 + bkof + ks*16)*2);
            #pragma unroll
            for (int mt=0;mt<4;mt++)
                #pragma unroll
                for (int nt=0;nt<4;nt++)
                    mma16(acc[mt][nt], af[mt], &bf[nt>>1][(nt&1)*2]);
        }
    };

    #pragma unroll
    for (int i=0;i<GST-1;i++){
        if (i<NS) loadSlab(i,i);
        asm volatile("cp.async.commit_group;\n");
    }
    int st = 0;
    for (int s=0;s<NS;s++){
        asm volatile("cp.async.wait_group %0;\n" :: "n"(GST-2));
        __syncthreads();
        int ld = s + GST-1;
        if (ld < NS){
            int lst = st + 2; if (lst >= 3) lst -= 3;
            loadSlab(ld, lst);
        }
        asm volatile("cp.async.commit_group;\n");
        compute(st);
        if (++st == 3) st = 0;
    }

    #pragma unroll
    for (int mt=0;mt<4;mt++){
        int r0 = bm + wm + mt*16 + g;
        #pragma unroll
        for (int nt=0;nt<4;nt++){
            int n0 = bn + wn + nt*8 + tig*2;
            if (n0 < Nd){
                float* c = acc[mt][nt];
                float v00 = epi_val<EPI>(c[0], r0,   n0,   Nd, bias, vold, vfirst);
                float v01 = epi_val<EPI>(c[1], r0,   n0+1, Nd, bias, vold, vfirst);
                float v10 = epi_val<EPI>(c[2], r0+8, n0,   Nd, bias, vold, vfirst);
                float v11 = epi_val<EPI>(c[3], r0+8, n0+1, Nd, bias, vold, vfirst);
                if (RND){
                    __half* O = (__half*)Cm;
                    *(__half2*)&O[(size_t)r0*Nd + n0]     = __floats2half2_rn(v00, v01);
                    *(__half2*)&O[(size_t)(r0+8)*Nd + n0] = __floats2half2_rn(v10, v11);
                } else {
                    float* O = (float*)Cm;
                    *(float2*)&O[(size_t)r0*Nd + n0]     = make_float2(v00, v01);
                    *(float2*)&O[(size_t)(r0+8)*Nd + n0] = make_float2(v10, v11);
                }
            }
        }
    }
}

template<int EPI,int RND>
__global__ __launch_bounds__(256,2)
void gemm_h(const __half* __restrict__ A, const __half* __restrict__ Bw,
            void* __restrict__ Cm, int Nd, int Kd,
            const float* __restrict__ bias,
            const float* __restrict__ vold, const float* __restrict__ vfirst)
{
    gemm_body<EPI,RND>(A, Bw, Cm, Nd, Kd, bias, vold, vfirst);
}

// merged r/k/v projections: blockIdx.z selects which
__global__ __launch_bounds__(256,2)
void gemm_h3(const __half* __restrict__ A0, const __half* __restrict__ B0, float* __restrict__ C0,
             const __half* __restrict__ A1, const __half* __restrict__ B1, float* __restrict__ C1,
             const __half* __restrict__ A2, const __half* __restrict__ B2, float* __restrict__ C2)
{
    const __half* A = (blockIdx.z==0) ? A0 : (blockIdx.z==1) ? A1 : A2;
    const __half* B = (blockIdx.z==0) ? B0 : (blockIdx.z==1) ? B1 : B2;
    float*        C = (blockIdx.z==0) ? C0 : (blockIdx.z==1) ? C1 : C2;
    gemm_body<0,0>(A, B, (void*)C, Cq, Cq, nullptr, nullptr, nullptr);
}

// 4 lora up-projections in ONE launch (blockIdx.z selects; uniform per block)
__global__ __launch_bounds__(256,2)
void gemm_lora4(const __half* __restrict__ xw, const __half* __restrict__ w1h, __half* __restrict__ tw,
                const __half* __restrict__ xa, const __half* __restrict__ a1h, __half* __restrict__ ta,
                const __half* __restrict__ xv, const __half* __restrict__ v1h, __half* __restrict__ tv,
                const __half* __restrict__ xg, const __half* __restrict__ g1h, __half* __restrict__ tg)
{
    const int bn = blockIdx.x*128;
    switch(blockIdx.z){
        case 0: if (bn >= DW) return; gemm_body<1,1>(xw, w1h, (void*)tw, DW,  Cq, nullptr,nullptr,nullptr); break;
        case 1: if (bn >= DA) return; gemm_body<0,1>(xa, a1h, (void*)ta, DA,  Cq, nullptr,nullptr,nullptr); break;
        case 2: if (bn >= DV) return; gemm_body<0,1>(xv, v1h, (void*)tv, DV,  Cq, nullptr,nullptr,nullptr); break;
        default:                      gemm_body<2,1>(xg, g1h, (void*)tg, DGp, Cq, nullptr,nullptr,nullptr); break;
    }
}

// 4 lora down-projections in ONE launch (blockIdx.z selects; uniform per block)
__global__ __launch_bounds__(256,2)
void gemm_lorad4(const __half* __restrict__ twh, const __half* __restrict__ w2h, float* __restrict__ dec, const float* __restrict__ w0,
                 const __half* __restrict__ tah, const __half* __restrict__ a2h, float* __restrict__ aB,  const float* __restrict__ a0,
                 const __half* __restrict__ tvh, const __half* __restrict__ v2h, float* __restrict__ vB,  const float* __restrict__ v0,
                 const float* __restrict__ vfirst,
                 const __half* __restrict__ tgh, const __half* __restrict__ g2h, float* __restrict__ gB)
{
    switch(blockIdx.z){
        case 0: gemm_body<3,0>(twh, w2h, (void*)dec, Cq, DW, w0, nullptr, nullptr); break;
        case 1: gemm_body<4,0>(tah, a2h, (void*)aB,  Cq, DA, a0, nullptr, nullptr); break;
        case 2: gemm_body<5,0>(tvh, v2h, (void*)vB,  Cq, DV, v0, vB, vfirst);       break;
        default: gemm_body<0,0>(tgh, g2h, (void*)gB, Cq, DGp, nullptr, nullptr, nullptr); break;
    }
}

// ---------------------------------------------------------------------------
// kk normalize + k transform
// ---------------------------------------------------------------------------
__global__ void kk_kernel(float* __restrict__ k, const float* __restrict__ a,
                          const float* __restrict__ k_k, const float* __restrict__ k_a,
                          float* __restrict__ kk)
{
    int gw   = blockIdx.x*8 + (threadIdx.x>>5);
    int lane = threadIdx.x & 31;
    int m = gw >> 5;
    int h = gw & 31;
    size_t base = (size_t)m*Cq + h*HSq;
    int c0 = h*HSq + lane, c1 = c0 + 32;
    float k0 = k[base+lane], k1 = k[base+lane+32];
    float kk0 = k0*k_k[c0], kk1 = k1*k_k[c1];
    float s = kk0*kk0 + kk1*kk1;
    #pragma unroll
    for (int off=16; off; off>>=1) s += __shfl_xor_sync(0xffffffffu, s, off);
    float inv = 1.0f / fmaxf(sqrtf(s), 1e-12f);
    kk[base+lane]    = kk0*inv;
    kk[base+lane+32] = kk1*inv;
    float a0 = a[base+lane], a1 = a[base+lane+32];
    k[base+lane]    = k0*(1.0f + (a0-1.0f)*k_a[c0]);
    k[base+lane+32] = k1*(1.0f + (a1-1.0f)*k_a[c1]);
}

// ---------------------------------------------------------------------------
// WKV7 scan: 64 threads per (b,h), depth-4 register prefetch ring
// ---------------------------------------------------------------------------
__global__ __launch_bounds__(64)
void wkv_kernel(const float* __restrict__ r, const float* __restrict__ wd,
                const float* __restrict__ k, const float* __restrict__ v,
                const float* __restrict__ kkp, const float* __restrict__ ap,
                float* __restrict__ y)
{
    int bh = blockIdx.x;
    int b = bh >> 5;
    int h = bh & 31;
    int i = threadIdx.x;
    __shared__ __align__(16) float sr[64], sw[64], sk[64], sa[64], sb[64];
    float st[64];
    #pragma unroll
    for (int j=0;j<64;j++) st[j]=0.f;
    size_t base = ((size_t)b*Tq)*Cq + (size_t)h*HSq;

    float R[4], W[4], K[4], Q[4], A[4], V[4];
    #pragma unroll
    for (int j=0;j<4;j++){
        size_t o0 = base + (size_t)j*Cq;
        R[j]=r[o0+i]; W[j]=wd[o0+i]; K[j]=k[o0+i];
        Q[j]=kkp[o0+i]; A[j]=ap[o0+i]; V[j]=v[o0+i];
    }

    size_t o = base;
    for (int t=0; t<Tq; t+=4){
        #pragma unroll
        for (int q=0; q<4; q++){
            sr[i]=R[q]; sw[i]=W[q]; sk[i]=K[q]; sa[i]=-Q[q]; sb[i]=Q[q]*A[q];
            float vcur = V[q];
            __syncthreads();

            int tn = t + q + 4;
            if (tn < Tq){
                size_t on = base + (size_t)tn*Cq;
                R[q]=r[on+i]; W[q]=wd[on+i]; K[q]=k[on+i];
                Q[q]=kkp[on+i]; A[q]=ap[on+i]; V[q]=v[on+i];
            }

            float s0=0,s1=0,s2=0,s3=0;
            const float4* A4 = (const float4*)sa;
            #pragma unroll
            for (int j=0;j<16;j++) {
                float4 a4 = A4[j];
                s0 += st[4*j+0]*a4.x; s1 += st[4*j+1]*a4.y;
                s2 += st[4*j+2]*a4.z; s3 += st[4*j+3]*a4.w;
            }
            float sav = (s0+s1)+(s2+s3);

            const float4* W4=(const float4*)sw; const float4* K4=(const float4*)sk;
            const float4* B4=(const float4*)sb; const float4* R4=(const float4*)sr;
            float o0=0,o1=0,o2=0,o3=0;
            #pragma unroll
            for (int j=0;j<16;j++) {
                float4 w4=W4[j], k4=K4[j], b4=B4[j], r4=R4[j];
                float t0 = st[4*j+0]*w4.x + vcur*k4.x + sav*b4.x;
                float t1 = st[4*j+1]*w4.y + vcur*k4.y + sav*b4.y;
                float t2 = st[4*j+2]*w4.z + vcur*k4.z + sav*b4.z;
                float t3 = st[4*j+3]*w4.w + vcur*k4.w + sav*b4.w;
                st[4*j+0]=t0; st[4*j+1]=t1; st[4*j+2]=t2; st[4*j+3]=t3;
                o0 += t0*r4.x; o1 += t1*r4.y; o2 += t2*r4.z; o3 += t3*r4.w;
            }
            y[o+i] = (o0+o1)+(o2+o3);
            o += Cq;
            __syncthreads();
        }
    }
}

// ---------------------------------------------------------------------------
// GroupNorm + bonus + gate -> z (fp16 for Wo gemm)
// ---------------------------------------------------------------------------
__global__ void gn_kernel(const float* __restrict__ y, const float* __restrict__ r,
                          const float* __restrict__ k, const float* __restrict__ v,
                          const float* __restrict__ g,
                          const float* __restrict__ lnw, const float* __restrict__ lnb,
                          const float* __restrict__ r_k, __half* __restrict__ z)
{
    int gw   = blockIdx.x*8 + (threadIdx.x>>5);
    int lane = threadIdx.x & 31;
    int m = gw >> 5;
    int h = gw & 31;
    size_t base = (size_t)m*Cq + h*HSq;
    int c0 = h*HSq + lane, c1 = c0 + 32;
    float y0=y[base+lane], y1=y[base+lane+32];
    float r0=r[base+lane], r1=r[base+lane+32];
    float k0=k[base+lane], k1=k[base+lane+32];
    float sum = y0+y1;
    float sq  = y0*y0 + y1*y1;
    float dot = r0*k0*r_k[c0] + r1*k1*r_k[c1];
    #pragma unroll
    for (int off=16; off; off>>=1) {
        sum += __shfl_xor_sync(0xffffffffu, sum, off);
        sq  += __shfl_xor_sync(0xffffffffu, sq , off);
        dot += __shfl_xor_sync(0xffffffffu, dot, off);
    }
    float mean = sum * (1.0f/64.0f);
    float var  = sq * (1.0f/64.0f) - mean*mean;
    float inv  = rsqrtf(var + EPS_GN);
    float v0=v[base+lane], v1=v[base+lane+32];
    float g0=g[base+lane], g1=g[base+lane+32];
    float z0 = ((y0-mean)*inv*lnw[c0] + lnb[c0] + dot*v0) * g0;
    float z1 = ((y1-mean)*inv*lnw[c1] + lnb[c1] + dot*v1) * g1;
    z[base+lane]    = __float2half_rn(z0);
    z[base+lane+32] = __float2half_rn(z1);
}

// ---------------------------------------------------------------------------
// Host helpers
// ---------------------------------------------------------------------------
#define SMEM_GEMM (GST*ST_BYTES)

template<int EPI,int RND>
static void rg(const __half* A, const __half* Bw, void* C, int Nd, int Kd,
               const float* bias, const float* vold, const float* vfirst)
{
    cudaFuncSetAttribute(gemm_h<EPI,RND>, cudaFuncAttributeMaxDynamicSharedMemorySize,
                         SMEM_GEMM);
    dim3 grid((Nd+127)/128, Mq/128);
    gemm_h<EPI,RND><<<grid, 256, SMEM_GEMM>>>(A, Bw, C, Nd, Kd, bias, vold, vfirst);
}

// ---------------------------------------------------------------------------
// Launch
// ---------------------------------------------------------------------------
extern "C" void kernel_launch(void* const* d_in, const int* in_sizes, int n_in,
                              void* d_out, int out_size)
{
    const float* x       = (const float*)d_in[0];
    const float* v_first = (const float*)d_in[1];
    const float* x_r = (const float*)d_in[2];
    const float* x_w = (const float*)d_in[3];
    const float* x_k = (const float*)d_in[4];
    const float* x_v = (const float*)d_in[5];
    const float* x_a = (const float*)d_in[6];
    const float* x_g = (const float*)d_in[7];
    const float* w0  = (const float*)d_in[8];
    const float* w1  = (const float*)d_in[9];
    const float* w2  = (const float*)d_in[10];
    const float* a0  = (const float*)d_in[11];
    const float* a1  = (const float*)d_in[12];
    const float* a2  = (const float*)d_in[13];
    const float* v0  = (const float*)d_in[14];
    const float* v1  = (const float*)d_in[15];
    const float* v2  = (const float*)d_in[16];
    const float* g1  = (const float*)d_in[17];
    const float* g2  = (const float*)d_in[18];
    const float* k_k = (const float*)d_in[19];
    const float* k_a = (const float*)d_in[20];
    const float* r_k = (const float*)d_in[21];
    const float* Wr  = (const float*)d_in[22];
    const float* Wk  = (const float*)d_in[23];
    const float* Wv  = (const float*)d_in[24];
    const float* Wo  = (const float*)d_in[25];
    const float* lnw = (const float*)d_in[26];
    const float* lnb = (const float*)d_in[27];
    float* out = (float*)d_out;

    __half *xr,*xw,*xk,*xv,*xa,*xg,*zh,*Wrh,*Wkh,*Wvh,*Woh;
    __half *w1h,*w2h,*a1h,*a2h,*v1h,*v2h,*g1h,*g2h,*twh,*tah,*tvh,*tgh;
    float *rB,*kB,*vB,*dec,*aB,*gB,*kkB,*yB;
    cudaGetSymbolAddress((void**)&xr , h_xr);
    cudaGetSymbolAddress((void**)&xw , h_xw);
    cudaGetSymbolAddress((void**)&xk , h_xk);
    cudaGetSymbolAddress((void**)&xv , h_xv);
    cudaGetSymbolAddress((void**)&xa , h_xa);
    cudaGetSymbolAddress((void**)&xg , h_xg);
    cudaGetSymbolAddress((void**)&zh , h_z);
    cudaGetSymbolAddress((void**)&Wrh, h_Wr);
    cudaGetSymbolAddress((void**)&Wkh, h_Wk);
    cudaGetSymbolAddress((void**)&Wvh, h_Wv);
    cudaGetSymbolAddress((void**)&Woh, h_Wo);
    cudaGetSymbolAddress((void**)&w1h, h_w1);
    cudaGetSymbolAddress((void**)&w2h, h_w2);
    cudaGetSymbolAddress((void**)&a1h, h_a1);
    cudaGetSymbolAddress((void**)&a2h, h_a2);
    cudaGetSymbolAddress((void**)&v1h, h_v1);
    cudaGetSymbolAddress((void**)&v2h, h_v2);
    cudaGetSymbolAddress((void**)&g1h, h_g1);
    cudaGetSymbolAddress((void**)&g2h, h_g2);
    cudaGetSymbolAddress((void**)&twh, h_tw);
    cudaGetSymbolAddress((void**)&tah, h_ta);
    cudaGetSymbolAddress((void**)&tvh, h_tv);
    cudaGetSymbolAddress((void**)&tgh, h_tg);
    cudaGetSymbolAddress((void**)&rB , g_r);
    cudaGetSymbolAddress((void**)&kB , g_k);
    cudaGetSymbolAddress((void**)&vB , g_v);
    cudaGetSymbolAddress((void**)&dec, g_dec);
    cudaGetSymbolAddress((void**)&aB , g_a);
    cudaGetSymbolAddress((void**)&gB , g_g);
    cudaGetSymbolAddress((void**)&kkB, g_kk);
    cudaGetSymbolAddress((void**)&yB , g_y);

    // big weights f32->f16 (one launch)
    f2h4_kernel<<<dim3((unsigned)(((size_t)Cq*Cq/4 + 255)/256), 4), 256>>>(
        Wr, Wrh, Wk, Wkh, Wv, Wvh, Wo, Woh, (size_t)Cq*Cq/4);

    // lora weight transposes (one launch; g2 padded to K-stride 256)
    transpose8b<<<dim3(64, 64, 8), dim3(32,8)>>>(w1, w1h, w2, w2h, a1, a1h, a2, a2h,
                                                 v1, v1h, v2, v2h, g1, g1h, g2, g2h);

    // token-shift mixes -> fp16
    mix_kernel<<<(unsigned)((BTC/4 + 255)/256), 256>>>(x, x_r,x_w,x_k,x_v,x_a,x_g,
                                                       xr,xw,xk,xv,xa,xg);

    // merged big projections r/k/v (one launch)
    cudaFuncSetAttribute(gemm_h3, cudaFuncAttributeMaxDynamicSharedMemorySize, SMEM_GEMM);
    gemm_h3<<<dim3(Cq/128, Mq/128, 3), 256, SMEM_GEMM>>>(
        xr, Wrh, rB, xk, Wkh, kB, xv, Wvh, vB);

    // lora up-projections (one launch)
    cudaFuncSetAttribute(gemm_lora4, cudaFuncAttributeMaxDynamicSharedMemorySize, SMEM_GEMM);
    gemm_lora4<<<dim3(2, Mq/128, 4), 256, SMEM_GEMM>>>(
        xw, w1h, twh, xa, a1h, tah, xv, v1h, tvh, xg, g1h, tgh);

    // lora down-projections (one launch; g uses padded K=256)
    cudaFuncSetAttribute(gemm_lorad4, cudaFuncAttributeMaxDynamicSharedMemorySize, SMEM_GEMM);
    gemm_lorad4<<<dim3(Cq/128, Mq/128, 4), 256, SMEM_GEMM>>>(
        twh, w2h, dec, w0, tah, a2h, aB, a0, tvh, v2h, vB, v0, v_first, tgh, g2h, gB);

    // kk normalize + k transform
    kk_kernel<<<Mq*Hq/8, 256>>>(kB, aB, k_k, k_a, kkB);

    // WKV7 scan
    wkv_kernel<<<Bq*Hq, 64>>>(rB, dec, kB, vB, kkB, aB, yB);

    // GroupNorm + bonus + gate -> fp16 z
    gn_kernel<<<Mq*Hq/8, 256>>>(yB, rB, kB, vB, gB, lnw, lnb, r_k, zh);

    // output projection
    rg<0,0>(zh, Woh, out, Cq, Cq, nullptr,nullptr,nullptr);
}

// round 12
// speedup vs baseline: 1.5391x; 1.1046x over previous
#include <cuda_runtime.h>
#include <cuda_fp16.h>
#include <math.h>
#include <stdint.h>

// Problem constants
#define Bq 4
#define Tq 2048
#define Cq 2048
#define Hq 32
#define HSq 64
#define Mq (Bq*Tq)            // 8192 tokens
#define DW 128
#define DA 128
#define DG 224
#define DGp 256               // padded K for g lora (BK=64 divisibility)
#define DV 64
#define EPS_GN 0.00064f

// ---------------------------------------------------------------------------
// Scratch (static device globals; zero-initialized at module load)
// ---------------------------------------------------------------------------
#define BTC ((size_t)Mq*Cq)
__device__ __half h_xr[BTC];
__device__ __half h_xw[BTC];
__device__ __half h_xk[BTC];
__device__ __half h_xv[BTC];
__device__ __half h_xa[BTC];
__device__ __half h_xg[BTC];
__device__ __half h_z [BTC];
__device__ __half h_Wr[(size_t)Cq*Cq];
__device__ __half h_Wk[(size_t)Cq*Cq];
__device__ __half h_Wv[(size_t)Cq*Cq];
__device__ __half h_Wo[(size_t)Cq*Cq];
__device__ __half h_w1[(size_t)128*Cq];
__device__ __half h_w2[(size_t)Cq*DW];
__device__ __half h_a1[(size_t)128*Cq];
__device__ __half h_a2[(size_t)Cq*DA];
__device__ __half h_v1[(size_t)128*Cq];
__device__ __half h_v2[(size_t)Cq*DV];
__device__ __half h_g1[(size_t)DGp*Cq];   // pad rows stay 0
__device__ __half h_g2[(size_t)Cq*DGp];   // pad cols stay 0
__device__ __half h_tw[(size_t)Mq*DW];
__device__ __half h_ta[(size_t)Mq*DA];
__device__ __half h_tv[(size_t)Mq*DV];
__device__ __half h_tg[(size_t)Mq*DGp];   // stride 256
// fp32 intermediates
__device__ float g_r [BTC];
__device__ float g_k [BTC];
__device__ float g_v [BTC];
__device__ float g_dec[BTC];
__device__ float g_a [BTC];
__device__ float g_g [BTC];
__device__ float g_kk[BTC];
__device__ float g_y [BTC];

__device__ __forceinline__ float sigmoidf_(float x){ return 1.0f/(1.0f+expf(-x)); }

__device__ __forceinline__ void cpa16(uint32_t s, const void* g){
    asm volatile("cp.async.cg.shared.global [%0], [%1], 16;\n" :: "r"(s), "l"(g));
}
__device__ __forceinline__ void ldsm_x4(uint32_t* r, uint32_t addr){
    asm volatile("ldmatrix.sync.aligned.m8n8.x4.shared.b16 {%0,%1,%2,%3}, [%4];"
        : "=r"(r[0]),"=r"(r[1]),"=r"(r[2]),"=r"(r[3]) : "r"(addr));
}
__device__ __forceinline__ void mma16(float* c, const uint32_t* a, const uint32_t* b){
    asm volatile("mma.sync.aligned.m16n8k16.row.col.f32.f16.f16.f32 "
        "{%0,%1,%2,%3},{%4,%5,%6,%7},{%8,%9},{%0,%1,%2,%3};\n"
        : "+f"(c[0]),"+f"(c[1]),"+f"(c[2]),"+f"(c[3])
        : "r"(a[0]),"r"(a[1]),"r"(a[2]),"r"(a[3]),"r"(b[0]),"r"(b[1]));
}

// ---------------------------------------------------------------------------
// Prep: 4x f32->f16 weight copies in ONE launch (blockIdx.y selects)
// ---------------------------------------------------------------------------
__global__ void f2h4_kernel(const float* __restrict__ i0, __half* __restrict__ o0,
                            const float* __restrict__ i1, __half* __restrict__ o1,
                            const float* __restrict__ i2, __half* __restrict__ o2,
                            const float* __restrict__ i3, __half* __restrict__ o3,
                            size_t n4)
{
    size_t i = (size_t)blockIdx.x*blockDim.x + threadIdx.x;
    if (i >= n4) return;
    const float* in = (blockIdx.y==0)?i0:(blockIdx.y==1)?i1:(blockIdx.y==2)?i2:i3;
    __half* out     = (blockIdx.y==0)?o0:(blockIdx.y==1)?o1:(blockIdx.y==2)?o2:o3;
    float4 v = ((const float4*)in)[i];
    ((__half2*)out)[i*2  ] = __floats2half2_rn(v.x, v.y);
    ((__half2*)out)[i*2+1] = __floats2half2_rn(v.z, v.w);
}

// ---------------------------------------------------------------------------
// 8 lora-weight transposes (f32[R][C] -> f16[C][Rs]) in ONE launch
// transpose_body writes out[c2*Rs + r2]; Rs = output row stride (padded R).
// ---------------------------------------------------------------------------
__device__ __forceinline__
void transpose_body(const float* __restrict__ in, __half* __restrict__ out,
                    int R, int C, int Rs)
{
    __shared__ float tile[32][33];
    int cb = blockIdx.x*32, rb = blockIdx.y*32;
    if (cb >= C || rb >= R) return;
    int c = cb + threadIdx.x;
    #pragma unroll
    for (int i=threadIdx.y; i<32; i+=8){
        int r = rb + i;
        if (r<R && c<C) tile[i][threadIdx.x] = in[(size_t)r*C + c];
    }
    __syncthreads();
    int r2 = rb + threadIdx.x;
    #pragma unroll
    for (int i=threadIdx.y; i<32; i+=8){
        int c2 = cb + i;
        if (r2<R && c2<C) out[(size_t)c2*Rs + r2] = __float2half_rn(tile[threadIdx.x][i]);
    }
}

__global__ void transpose8b(const float* w1, __half* w1h, const float* w2, __half* w2h,
                            const float* a1, __half* a1h, const float* a2, __half* a2h,
                            const float* v1, __half* v1h, const float* v2, __half* v2h,
                            const float* g1, __half* g1h, const float* g2, __half* g2h)
{
    switch(blockIdx.z){
        case 0: transpose_body(w1, w1h, Cq, DW, Cq);  break;  // [DW][Cq]
        case 1: transpose_body(w2, w2h, DW, Cq, DW);  break;  // [Cq][DW]
        case 2: transpose_body(a1, a1h, Cq, DA, Cq);  break;
        case 3: transpose_body(a2, a2h, DA, Cq, DA);  break;
        case 4: transpose_body(v1, v1h, Cq, DV, Cq);  break;
        case 5: transpose_body(v2, v2h, DV, Cq, DV);  break;
        case 6: transpose_body(g1, g1h, Cq, DG, Cq);  break;  // [DG..256][Cq]
        default: transpose_body(g2, g2h, DG, Cq, DGp); break; // [Cq][256], pad 0
    }
}

// ---------------------------------------------------------------------------
// Token-shift mix -> fp16 outputs
// ---------------------------------------------------------------------------
__global__ void mix_kernel(const float* __restrict__ x,
                           const float* __restrict__ cr, const float* __restrict__ cw,
                           const float* __restrict__ ck, const float* __restrict__ cv,
                           const float* __restrict__ ca, const float* __restrict__ cg,
                           __half* __restrict__ xr, __half* __restrict__ xw,
                           __half* __restrict__ xk, __half* __restrict__ xv,
                           __half* __restrict__ xa, __half* __restrict__ xg)
{
    size_t i4 = (size_t)blockIdx.x*blockDim.x + threadIdx.x;
    size_t n4 = BTC/4;
    if (i4 >= n4) return;
    size_t flat = i4*4;
    int tok = (int)(flat / Cq);
    int t   = tok % Tq;
    const float4* x4 = (const float4*)x;
    float4 xc = x4[i4];
    float4 xp = (t==0) ? make_float4(0,0,0,0) : x4[i4 - Cq/4];
    float4 dx = make_float4(xp.x-xc.x, xp.y-xc.y, xp.z-xc.z, xp.w-xc.w);
    size_t c4 = i4 % (Cq/4);
    #define MIX1(COEF, OUT) { \
        float4 cf = ((const float4*)COEF)[c4]; \
        ((__half2*)OUT)[i4*2  ] = __floats2half2_rn(xc.x + dx.x*cf.x, xc.y + dx.y*cf.y); \
        ((__half2*)OUT)[i4*2+1] = __floats2half2_rn(xc.z + dx.z*cf.z, xc.w + dx.w*cf.w); }
    MIX1(cr, xr) MIX1(cw, xw) MIX1(ck, xk) MIX1(cv, xv) MIX1(ca, xa) MIX1(cg, xg)
    #undef MIX1
}

// ---------------------------------------------------------------------------
// Epilogue transform: 0 none, 1 tanh, 2 sigmoid, 3 w->decay, 4 a-sigm, 5 v-mix
// ---------------------------------------------------------------------------
template<int EPI>
__device__ __forceinline__ float epi_val(float val, int m, int n, int Nd,
                                         const float* __restrict__ bias,
                                         const float* __restrict__ vold,
                                         const float* __restrict__ vfirst)
{
    if (EPI==1) { val = tanhf(val); }
    else if (EPI==2) { val = sigmoidf_(val); }
    else if (EPI==3) {
        float w = bias[n] + val;
        float mneg = -w;
        float sp = fmaxf(mneg,0.f) + log1pf(expf(-fabsf(mneg)));
        float wl = -sp - 0.5f;
        val = expf(-expf(wl));
    }
    else if (EPI==4) { val = sigmoidf_(bias[n] + val); }
    else if (EPI==5) {
        float s  = sigmoidf_(bias[n] + val);
        size_t idx = (size_t)m*Nd + n;
        float vo = vold[idx];
        val = vo + (vfirst[idx] - vo)*s;
    }
    return val;
}

// ---------------------------------------------------------------------------
// fp16 tensor-core GEMM body: C[m,n] = sum_k A[m,k] * B[n,k]
// CTA 128x128, BK=64, 3-stage cp.async ring, ONE __syncthreads per slab.
// ---------------------------------------------------------------------------
#define GST 3
#define ST_HB (128*72*2)            // 18432 B per matrix per stage
#define ST_BYTES (2*ST_HB)          // 36864 B per stage

template<int EPI,int RND>
__device__ __forceinline__
void gemm_body(const __half* __restrict__ A, const __half* __restrict__ Bw,
               void* __restrict__ Cm, int Nd, int Kd,
               const float* __restrict__ bias,
               const float* __restrict__ vold, const float* __restrict__ vfirst)
{
    extern __shared__ __align__(128) char smc[];
    const int tid = threadIdx.x;
    const int lane = tid&31, warp = tid>>5;
    const int bm = blockIdx.y*128, bn = blockIdx.x*128;
    const int wm = (warp&1)*64, wn = (warp>>1)*32;
    const int g = lane>>2, tig = lane&3;
    const uint32_t sbase = (uint32_t)__cvta_generic_to_shared(smc);

    const int arow = wm + (lane&7) + ((lane>>3)&1)*8;
    const int akof = (lane>>4)*8;
    const int brow = wn + (lane&7) + (lane>>4)*8;
    const int bkof = ((lane>>3)&1)*8;

    float acc[4][4][4];
    #pragma unroll
    for (int i=0;i<4;i++)
        #pragma unroll
        for (int j=0;j<4;j++)
            #pragma unroll
            for (int q=0;q<4;q++) acc[i][j][q]=0.f;

    const int NS = Kd >> 6;

    auto loadSlab = [&](int s, int st){
        const uint32_t sb = sbase + st*ST_BYTES;
        const int k0 = s*64;
        #pragma unroll
        for (int i=0;i<4;i++){
            int id  = tid + i*256;
            int row = id>>3, c16 = id&7;
            cpa16(sb + row*144 + c16*16,
                  &A[(size_t)(bm+row)*Kd + k0 + c16*8]);
            cpa16(sb + ST_HB + row*144 + c16*16,
                  &Bw[(size_t)(bn+row)*Kd + k0 + c16*8]);
        }
    };
    auto compute = [&](int st){
        const uint32_t sb = sbase + st*ST_BYTES;
        #pragma unroll
        for (int ks=0; ks<4; ks++){
            uint32_t af[4][4], bf[2][4];
            #pragma unroll
            for (int mt=0;mt<4;mt++)
                ldsm_x4(af[mt], sb + ((arow+mt*16)*72 + akof + ks*16)*2);
            #pragma unroll
            for (int p=0;p<2;p++)
                ldsm_x4(bf[p], sb + ST_HB + ((brow+p*16)*72 + bkof + ks*16)*2);
            #pragma unroll
            for (int mt=0;mt<4;mt++)
                #pragma unroll
                for (int nt=0;nt<4;nt++)
                    mma16(acc[mt][nt], af[mt], &bf[nt>>1][(nt&1)*2]);
        }
    };

    #pragma unroll
    for (int i=0;i<GST-1;i++){
        if (i<NS) loadSlab(i,i);
        asm volatile("cp.async.commit_group;\n");
    }
    int st = 0;
    for (int s=0;s<NS;s++){
        asm volatile("cp.async.wait_group %0;\n" :: "n"(GST-2));
        __syncthreads();
        int ld = s + GST-1;
        if (ld < NS){
            int lst = st + 2; if (lst >= 3) lst -= 3;
            loadSlab(ld, lst);
        }
        asm volatile("cp.async.commit_group;\n");
        compute(st);
        if (++st == 3) st = 0;
    }

    #pragma unroll
    for (int mt=0;mt<4;mt++){
        int r0 = bm + wm + mt*16 + g;
        #pragma unroll
        for (int nt=0;nt<4;nt++){
            int n0 = bn + wn + nt*8 + tig*2;
            if (n0 < Nd){
                float* c = acc[mt][nt];
                float v00 = epi_val<EPI>(c[0], r0,   n0,   Nd, bias, vold, vfirst);
                float v01 = epi_val<EPI>(c[1], r0,   n0+1, Nd, bias, vold, vfirst);
                float v10 = epi_val<EPI>(c[2], r0+8, n0,   Nd, bias, vold, vfirst);
                float v11 = epi_val<EPI>(c[3], r0+8, n0+1, Nd, bias, vold, vfirst);
                if (RND){
                    __half* O = (__half*)Cm;
                    *(__half2*)&O[(size_t)r0*Nd + n0]     = __floats2half2_rn(v00, v01);
                    *(__half2*)&O[(size_t)(r0+8)*Nd + n0] = __floats2half2_rn(v10, v11);
                } else {
                    float* O = (float*)Cm;
                    *(float2*)&O[(size_t)r0*Nd + n0]     = make_float2(v00, v01);
                    *(float2*)&O[(size_t)(r0+8)*Nd + n0] = make_float2(v10, v11);
                }
            }
        }
    }
}

template<int EPI,int RND>
__global__ __launch_bounds__(256,2)
void gemm_h(const __half* __restrict__ A, const __half* __restrict__ Bw,
            void* __restrict__ Cm, int Nd, int Kd,
            const float* __restrict__ bias,
            const float* __restrict__ vold, const float* __restrict__ vfirst)
{
    gemm_body<EPI,RND>(A, Bw, Cm, Nd, Kd, bias, vold, vfirst);
}

// merged r/k/v projections: blockIdx.z selects which
__global__ __launch_bounds__(256,2)
void gemm_h3(const __half* __restrict__ A0, const __half* __restrict__ B0, float* __restrict__ C0,
             const __half* __restrict__ A1, const __half* __restrict__ B1, float* __restrict__ C1,
             const __half* __restrict__ A2, const __half* __restrict__ B2, float* __restrict__ C2)
{
    const __half* A = (blockIdx.z==0) ? A0 : (blockIdx.z==1) ? A1 : A2;
    const __half* B = (blockIdx.z==0) ? B0 : (blockIdx.z==1) ? B1 : B2;
    float*        C = (blockIdx.z==0) ? C0 : (blockIdx.z==1) ? C1 : C2;
    gemm_body<0,0>(A, B, (void*)C, Cq, Cq, nullptr, nullptr, nullptr);
}

// 4 lora up-projections in ONE launch
__global__ __launch_bounds__(256,2)
void gemm_lora4(const __half* __restrict__ xw, const __half* __restrict__ w1h, __half* __restrict__ tw,
                const __half* __restrict__ xa, const __half* __restrict__ a1h, __half* __restrict__ ta,
                const __half* __restrict__ xv, const __half* __restrict__ v1h, __half* __restrict__ tv,
                const __half* __restrict__ xg, const __half* __restrict__ g1h, __half* __restrict__ tg)
{
    const int bn = blockIdx.x*128;
    switch(blockIdx.z){
        case 0: if (bn >= DW) return; gemm_body<1,1>(xw, w1h, (void*)tw, DW,  Cq, nullptr,nullptr,nullptr); break;
        case 1: if (bn >= DA) return; gemm_body<0,1>(xa, a1h, (void*)ta, DA,  Cq, nullptr,nullptr,nullptr); break;
        case 2: if (bn >= DV) return; gemm_body<0,1>(xv, v1h, (void*)tv, DV,  Cq, nullptr,nullptr,nullptr); break;
        default:                      gemm_body<2,1>(xg, g1h, (void*)tg, DGp, Cq, nullptr,nullptr,nullptr); break;
    }
}

// 4 lora down-projections in ONE launch
__global__ __launch_bounds__(256,2)
void gemm_lorad4(const __half* __restrict__ twh, const __half* __restrict__ w2h, float* __restrict__ dec, const float* __restrict__ w0,
                 const __half* __restrict__ tah, const __half* __restrict__ a2h, float* __restrict__ aB,  const float* __restrict__ a0,
                 const __half* __restrict__ tvh, const __half* __restrict__ v2h, float* __restrict__ vB,  const float* __restrict__ v0,
                 const float* __restrict__ vfirst,
                 const __half* __restrict__ tgh, const __half* __restrict__ g2h, float* __restrict__ gB)
{
    switch(blockIdx.z){
        case 0: gemm_body<3,0>(twh, w2h, (void*)dec, Cq, DW, w0, nullptr, nullptr); break;
        case 1: gemm_body<4,0>(tah, a2h, (void*)aB,  Cq, DA, a0, nullptr, nullptr); break;
        case 2: gemm_body<5,0>(tvh, v2h, (void*)vB,  Cq, DV, v0, vB, vfirst);       break;
        default: gemm_body<0,0>(tgh, g2h, (void*)gB, Cq, DGp, nullptr, nullptr, nullptr); break;
    }
}

// ---------------------------------------------------------------------------
// kk normalize + k transform
// ---------------------------------------------------------------------------
__global__ void kk_kernel(float* __restrict__ k, const float* __restrict__ a,
                          const float* __restrict__ k_k, const float* __restrict__ k_a,
                          float* __restrict__ kk)
{
    int gw   = blockIdx.x*8 + (threadIdx.x>>5);
    int lane = threadIdx.x & 31;
    int m = gw >> 5;
    int h = gw & 31;
    size_t base = (size_t)m*Cq + h*HSq;
    int c0 = h*HSq + lane, c1 = c0 + 32;
    float k0 = k[base+lane], k1 = k[base+lane+32];
    float kk0 = k0*k_k[c0], kk1 = k1*k_k[c1];
    float s = kk0*kk0 + kk1*kk1;
    #pragma unroll
    for (int off=16; off; off>>=1) s += __shfl_xor_sync(0xffffffffu, s, off);
    float inv = 1.0f / fmaxf(sqrtf(s), 1e-12f);
    kk[base+lane]    = kk0*inv;
    kk[base+lane+32] = kk1*inv;
    float a0 = a[base+lane], a1 = a[base+lane+32];
    k[base+lane]    = k0*(1.0f + (a0-1.0f)*k_a[c0]);
    k[base+lane+32] = k1*(1.0f + (a1-1.0f)*k_a[c1]);
}

// ---------------------------------------------------------------------------
// WKV7 scan: 128 threads per (b,h). Thread (i,p) owns state row i (0..63),
// half p (32 cols). All 4 SMSPs busy; ONE shfl per reduction; double-buffered
// smem + register-staged loads; ONE __syncthreads per step.
// ---------------------------------------------------------------------------
__global__ __launch_bounds__(128)
void wkv_kernel(const float* __restrict__ r, const float* __restrict__ wd,
                const float* __restrict__ k, const float* __restrict__ v,
                const float* __restrict__ kkp, const float* __restrict__ ap,
                float* __restrict__ y)
{
    const int bh = blockIdx.x;
    const int b = bh >> 5, h = bh & 31;
    const int tid = threadIdx.x;
    const int i = tid >> 1;      // state row
    const int p = tid & 1;       // half (cols p*32 .. p*32+31)
    const int role = tid >> 6;   // loader role 0/1
    const int lc   = tid & 63;   // loader column

    // [buf][array][64]; arrays: 0=r 1=w 2=k 3=a(-kk) 4=b(kk*a) 5=v
    __shared__ __align__(16) float sbuf[2][6][64];

    float st[32];
    #pragma unroll
    for (int j=0;j<32;j++) st[j]=0.f;

    const size_t base = ((size_t)b*Tq)*Cq + (size_t)h*HSq;

    // register-stage step 0 (each loader thread owns 3 streams for column lc)
    float l0, l1, l2;
    if (role==0){ l0 = r[base+lc];  l1 = v[base+lc];   l2 = wd[base+lc]; }
    else        { l0 = k[base+lc];  l1 = kkp[base+lc]; l2 = ap[base+lc]; }

    size_t o = base;
    for (int t=0; t<Tq; t++){
        const int cur = t&1;

        // publish step t from registers
        if (role==0){ sbuf[cur][0][lc]=l0; sbuf[cur][5][lc]=l1; sbuf[cur][1][lc]=l2; }
        else        { sbuf[cur][2][lc]=l0; sbuf[cur][3][lc]=-l1; sbuf[cur][4][lc]=l1*l2; }
        __syncthreads();

        // issue prefetch of step t+1 (latency overlaps compute below)
        if (t+1 < Tq){
            size_t on = o + Cq;
            if (role==0){ l0 = r[on+lc];  l1 = v[on+lc];   l2 = wd[on+lc]; }
            else        { l0 = k[on+lc];  l1 = kkp[on+lc]; l2 = ap[on+lc]; }
        }

        // ---- compute on cur ----
        const float4* A4 = (const float4*)&sbuf[cur][3][p*32];
        float s0=0,s1=0,s2=0,s3=0;
        #pragma unroll
        for (int j=0;j<8;j++){
            float4 a4 = A4[j];
            s0 += st[4*j+0]*a4.x; s1 += st[4*j+1]*a4.y;
            s2 += st[4*j+2]*a4.z; s3 += st[4*j+3]*a4.w;
        }
        float sav = (s0+s1)+(s2+s3);
        sav += __shfl_xor_sync(0xffffffffu, sav, 1);

        const float vv = sbuf[cur][5][i];
        const float4* W4=(const float4*)&sbuf[cur][1][p*32];
        const float4* K4=(const float4*)&sbuf[cur][2][p*32];
        const float4* B4=(const float4*)&sbuf[cur][4][p*32];
        const float4* R4=(const float4*)&sbuf[cur][0][p*32];
        float o0=0,o1=0,o2=0,o3=0;
        #pragma unroll
        for (int j=0;j<8;j++){
            float4 w4=W4[j], k4=K4[j], b4=B4[j], r4=R4[j];
            float t0 = st[4*j+0]*w4.x + vv*k4.x + sav*b4.x;
            float t1 = st[4*j+1]*w4.y + vv*k4.y + sav*b4.y;
            float t2 = st[4*j+2]*w4.z + vv*k4.z + sav*b4.z;
            float t3 = st[4*j+3]*w4.w + vv*k4.w + sav*b4.w;
            st[4*j+0]=t0; st[4*j+1]=t1; st[4*j+2]=t2; st[4*j+3]=t3;
            o0 += t0*r4.x; o1 += t1*r4.y; o2 += t2*r4.z; o3 += t3*r4.w;
        }
        float op = (o0+o1)+(o2+o3);
        op += __shfl_xor_sync(0xffffffffu, op, 1);
        if (p==0) y[o+i] = op;

        o += Cq;
        // no trailing barrier: next iter writes the OTHER buffer; writes to
        // this buffer at t+2 are ordered behind t's reads by t+1's barrier.
    }
}

// ---------------------------------------------------------------------------
// GroupNorm + bonus + gate -> z (fp16 for Wo gemm)
// ---------------------------------------------------------------------------
__global__ void gn_kernel(const float* __restrict__ y, const float* __restrict__ r,
                          const float* __restrict__ k, const float* __restrict__ v,
                          const float* __restrict__ g,
                          const float* __restrict__ lnw, const float* __restrict__ lnb,
                          const float* __restrict__ r_k, __half* __restrict__ z)
{
    int gw   = blockIdx.x*8 + (threadIdx.x>>5);
    int lane = threadIdx.x & 31;
    int m = gw >> 5;
    int h = gw & 31;
    size_t base = (size_t)m*Cq + h*HSq;
    int c0 = h*HSq + lane, c1 = c0 + 32;
    float y0=y[base+lane], y1=y[base+lane+32];
    float r0=r[base+lane], r1=r[base+lane+32];
    float k0=k[base+lane], k1=k[base+lane+32];
    float sum = y0+y1;
    float sq  = y0*y0 + y1*y1;
    float dot = r0*k0*r_k[c0] + r1*k1*r_k[c1];
    #pragma unroll
    for (int off=16; off; off>>=1) {
        sum += __shfl_xor_sync(0xffffffffu, sum, off);
        sq  += __shfl_xor_sync(0xffffffffu, sq , off);
        dot += __shfl_xor_sync(0xffffffffu, dot, off);
    }
    float mean = sum * (1.0f/64.0f);
    float var  = sq * (1.0f/64.0f) - mean*mean;
    float inv  = rsqrtf(var + EPS_GN);
    float v0=v[base+lane], v1=v[base+lane+32];
    float g0=g[base+lane], g1=g[base+lane+32];
    float z0 = ((y0-mean)*inv*lnw[c0] + lnb[c0] + dot*v0) * g0;
    float z1 = ((y1-mean)*inv*lnw[c1] + lnb[c1] + dot*v1) * g1;
    z[base+lane]    = __float2half_rn(z0);
    z[base+lane+32] = __float2half_rn(z1);
}

// ---------------------------------------------------------------------------
// Host helpers
// ---------------------------------------------------------------------------
#define SMEM_GEMM (GST*ST_BYTES)

template<int EPI,int RND>
static void rg(const __half* A, const __half* Bw, void* C, int Nd, int Kd,
               const float* bias, const float* vold, const float* vfirst)
{
    cudaFuncSetAttribute(gemm_h<EPI,RND>, cudaFuncAttributeMaxDynamicSharedMemorySize,
                         SMEM_GEMM);
    dim3 grid((Nd+127)/128, Mq/128);
    gemm_h<EPI,RND><<<grid, 256, SMEM_GEMM>>>(A, Bw, C, Nd, Kd, bias, vold, vfirst);
}

// ---------------------------------------------------------------------------
// Launch
// ---------------------------------------------------------------------------
extern "C" void kernel_launch(void* const* d_in, const int* in_sizes, int n_in,
                              void* d_out, int out_size)
{
    const float* x       = (const float*)d_in[0];
    const float* v_first = (const float*)d_in[1];
    const float* x_r = (const float*)d_in[2];
    const float* x_w = (const float*)d_in[3];
    const float* x_k = (const float*)d_in[4];
    const float* x_v = (const float*)d_in[5];
    const float* x_a = (const float*)d_in[6];
    const float* x_g = (const float*)d_in[7];
    const float* w0  = (const float*)d_in[8];
    const float* w1  = (const float*)d_in[9];
    const float* w2  = (const float*)d_in[10];
    const float* a0  = (const float*)d_in[11];
    const float* a1  = (const float*)d_in[12];
    const float* a2  = (const float*)d_in[13];
    const float* v0  = (const float*)d_in[14];
    const float* v1  = (const float*)d_in[15];
    const float* v2  = (const float*)d_in[16];
    const float* g1  = (const float*)d_in[17];
    const float* g2  = (const float*)d_in[18];
    const float* k_k = (const float*)d_in[19];
    const float* k_a = (const float*)d_in[20];
    const float* r_k = (const float*)d_in[21];
    const float* Wr  = (const float*)d_in[22];
    const float* Wk  = (const float*)d_in[23];
    const float* Wv  = (const float*)d_in[24];
    const float* Wo  = (const float*)d_in[25];
    const float* lnw = (const float*)d_in[26];
    const float* lnb = (const float*)d_in[27];
    float* out = (float*)d_out;

    __half *xr,*xw,*xk,*xv,*xa,*xg,*zh,*Wrh,*Wkh,*Wvh,*Woh;
    __half *w1h,*w2h,*a1h,*a2h,*v1h,*v2h,*g1h,*g2h,*twh,*tah,*tvh,*tgh;
    float *rB,*kB,*vB,*dec,*aB,*gB,*kkB,*yB;
    cudaGetSymbolAddress((void**)&xr , h_xr);
    cudaGetSymbolAddress((void**)&xw , h_xw);
    cudaGetSymbolAddress((void**)&xk , h_xk);
    cudaGetSymbolAddress((void**)&xv , h_xv);
    cudaGetSymbolAddress((void**)&xa , h_xa);
    cudaGetSymbolAddress((void**)&xg , h_xg);
    cudaGetSymbolAddress((void**)&zh , h_z);
    cudaGetSymbolAddress((void**)&Wrh, h_Wr);
    cudaGetSymbolAddress((void**)&Wkh, h_Wk);
    cudaGetSymbolAddress((void**)&Wvh, h_Wv);
    cudaGetSymbolAddress((void**)&Woh, h_Wo);
    cudaGetSymbolAddress((void**)&w1h, h_w1);
    cudaGetSymbolAddress((void**)&w2h, h_w2);
    cudaGetSymbolAddress((void**)&a1h, h_a1);
    cudaGetSymbolAddress((void**)&a2h, h_a2);
    cudaGetSymbolAddress((void**)&v1h, h_v1);
    cudaGetSymbolAddress((void**)&v2h, h_v2);
    cudaGetSymbolAddress((void**)&g1h, h_g1);
    cudaGetSymbolAddress((void**)&g2h, h_g2);
    cudaGetSymbolAddress((void**)&twh, h_tw);
    cudaGetSymbolAddress((void**)&tah, h_ta);
    cudaGetSymbolAddress((void**)&tvh, h_tv);
    cudaGetSymbolAddress((void**)&tgh, h_tg);
    cudaGetSymbolAddress((void**)&rB , g_r);
    cudaGetSymbolAddress((void**)&kB , g_k);
    cudaGetSymbolAddress((void**)&vB , g_v);
    cudaGetSymbolAddress((void**)&dec, g_dec);
    cudaGetSymbolAddress((void**)&aB , g_a);
    cudaGetSymbolAddress((void**)&gB , g_g);
    cudaGetSymbolAddress((void**)&kkB, g_kk);
    cudaGetSymbolAddress((void**)&yB , g_y);

    // big weights f32->f16 (one launch)
    f2h4_kernel<<<dim3((unsigned)(((size_t)Cq*Cq/4 + 255)/256), 4), 256>>>(
        Wr, Wrh, Wk, Wkh, Wv, Wvh, Wo, Woh, (size_t)Cq*Cq/4);

    // lora weight transposes (one launch; g2 padded to K-stride 256)
    transpose8b<<<dim3(64, 64, 8), dim3(32,8)>>>(w1, w1h, w2, w2h, a1, a1h, a2, a2h,
                                                 v1, v1h, v2, v2h, g1, g1h, g2, g2h);

    // token-shift mixes -> fp16
    mix_kernel<<<(unsigned)((BTC/4 + 255)/256), 256>>>(x, x_r,x_w,x_k,x_v,x_a,x_g,
                                                       xr,xw,xk,xv,xa,xg);

    // merged big projections r/k/v (one launch)
    cudaFuncSetAttribute(gemm_h3, cudaFuncAttributeMaxDynamicSharedMemorySize, SMEM_GEMM);
    gemm_h3<<<dim3(Cq/128, Mq/128, 3), 256, SMEM_GEMM>>>(
        xr, Wrh, rB, xk, Wkh, kB, xv, Wvh, vB);

    // lora up-projections (one launch)
    cudaFuncSetAttribute(gemm_lora4, cudaFuncAttributeMaxDynamicSharedMemorySize, SMEM_GEMM);
    gemm_lora4<<<dim3(2, Mq/128, 4), 256, SMEM_GEMM>>>(
        xw, w1h, twh, xa, a1h, tah, xv, v1h, tvh, xg, g1h, tgh);

    // lora down-projections (one launch; g uses padded K=256)
    cudaFuncSetAttribute(gemm_lorad4, cudaFuncAttributeMaxDynamicSharedMemorySize, SMEM_GEMM);
    gemm_lorad4<<<dim3(Cq/128, Mq/128, 4), 256, SMEM_GEMM>>>(
        twh, w2h, dec, w0, tah, a2h, aB, a0, tvh, v2h, vB, v0, v_first, tgh, g2h, gB);

    // kk normalize + k transform
    kk_kernel<<<Mq*Hq/8, 256>>>(kB, aB, k_k, k_a, kkB);

    // WKV7 scan (128 threads/block, 2-way column split)
    wkv_kernel<<<Bq*Hq, 128>>>(rB, dec, kB, vB, kkB, aB, yB);

    // GroupNorm + bonus + gate -> fp16 z
    gn_kernel<<<Mq*Hq/8, 256>>>(yB, rB, kB, vB, gB, lnw, lnb, r_k, zh);

    // output projection
    rg<0,0>(zh, Woh, out, Cq, Cq, nullptr,nullptr,nullptr);
}